// round 2
// baseline (speedup 1.0000x reference)
#include <cuda_runtime.h>
#include <cuda_bf16.h>
#include <math.h>

#define NHEAD  16
#define DMODEL 1024
#define DHEAD  64
#define BATCH  2
#define SEQ    2048
#define MROWS  (BATCH*SEQ)   // 4096
#define MASKN  ((size_t)BATCH*SEQ*SEQ)   // 8388608

// Scratch (device globals; no allocation in kernel_launch)
__device__ float g_qh [MROWS*DMODEL];
__device__ float g_kh [MROWS*DMODEL];
__device__ float g_vh [MROWS*DMODEL];
__device__ float g_ctx[MROWS*DMODEL];
__device__ float g_y  [MROWS*DMODEL];
__device__ unsigned char g_mask8[MASKN];
__device__ int g_fmt;

// ---------------------------------------------------------------------------
// Mask dtype probe: the reference mask is jax bool; the harness delivers it as
// an unknown dtype (uint8 / int32 / float32). Classify by word patterns over
// the first 1M words (4MB — within the smallest possible buffer of 8.4MB).
//   int32 0/1   -> every word in {0, 1}
//   float 0/1.0 -> every word in {0, 0x3F800000}
//   uint8 0/1   -> random 4-byte combos of 0x00/0x01 (fails both tests)
// ---------------------------------------------------------------------------
__global__ void probe_mask(const unsigned int* __restrict__ m) {
    __shared__ int s_i32, s_f32;
    if (threadIdx.x == 0) { s_i32 = 1; s_f32 = 1; }
    __syncthreads();
    int bad_i = 0, bad_f = 0;
    for (int i = threadIdx.x; i < (1 << 20); i += blockDim.x) {
        unsigned int w = m[i];
        if (w != 0u && w != 1u) bad_i = 1;
        if (w != 0u && w != 0x3F800000u) bad_f = 1;
    }
    if (bad_i) atomicAnd(&s_i32, 0);
    if (bad_f) atomicAnd(&s_f32, 0);
    __syncthreads();
    if (threadIdx.x == 0) g_fmt = s_i32 ? 1 : (s_f32 ? 2 : 0);
}

__global__ void convert_mask(const void* __restrict__ src) {
    size_t i = (size_t)blockIdx.x * blockDim.x + threadIdx.x;
    if (i >= MASKN) return;
    int fmt = g_fmt;
    unsigned char v;
    if (fmt == 1)      v = (unsigned char)(((const int*)src)[i] != 0);
    else if (fmt == 2) v = (unsigned char)(((const float*)src)[i] != 0.f);
    else               v = ((const unsigned char*)src)[i];
    g_mask8[i] = v;
}

// ---------------------------------------------------------------------------
// GEMM: C[M,N] = A[M,K] @ B(+bias+residual). BM=128, BN=64, BK=16, 256 thr.
// HEADED: B is w[h, d, e] (h = n/64, ldb=64). else B is [K,N] row-major.
// ---------------------------------------------------------------------------
template<bool HEADED, bool EPILOGUE>
__global__ void __launch_bounds__(256) gemm128x64(
    const float* __restrict__ A, const float* __restrict__ B,
    float* __restrict__ C, int M, int N, int K,
    const float* __restrict__ bias, const float* __restrict__ residual)
{
    const int BK = 16;
    __shared__ float As[BK][128 + 4];
    __shared__ float Bs[BK][64 + 4];

    const int tid = threadIdx.x;
    const int m0  = blockIdx.y * 128;
    const int n0  = blockIdx.x * 64;
    const int ty  = tid >> 4;   // 0..15 -> 8 rows each
    const int tx  = tid & 15;   // 0..15 -> 4 cols each

    float acc[8][4];
#pragma unroll
    for (int i = 0; i < 8; i++)
#pragma unroll
        for (int j = 0; j < 4; j++) acc[i][j] = 0.f;

    const float* Bbase = HEADED ? (B + (size_t)(n0 >> 6) * DMODEL * DHEAD) : (B + n0);
    const int ldb = HEADED ? DHEAD : N;

    for (int k0 = 0; k0 < K; k0 += BK) {
        // A tile 128x16 (transposed into SMEM)
#pragma unroll
        for (int it = 0; it < 2; it++) {
            int idx = tid + it * 256;        // 0..511
            int row = idx >> 2;              // 0..127
            int c4  = (idx & 3) * 4;
            float4 v = *(const float4*)(A + (size_t)(m0 + row) * K + k0 + c4);
            As[c4 + 0][row] = v.x; As[c4 + 1][row] = v.y;
            As[c4 + 2][row] = v.z; As[c4 + 3][row] = v.w;
        }
        // B tile 16x64
        {
            int row = tid >> 4;              // 0..15 (k)
            int c4  = (tid & 15) * 4;
            float4 v = *(const float4*)(Bbase + (size_t)(k0 + row) * ldb + c4);
            Bs[row][c4 + 0] = v.x; Bs[row][c4 + 1] = v.y;
            Bs[row][c4 + 2] = v.z; Bs[row][c4 + 3] = v.w;
        }
        __syncthreads();

#pragma unroll
        for (int k = 0; k < BK; k++) {
            float a[8], b[4];
#pragma unroll
            for (int i = 0; i < 8; i++) a[i] = As[k][ty * 8 + i];
#pragma unroll
            for (int j = 0; j < 4; j++) b[j] = Bs[k][tx * 4 + j];
#pragma unroll
            for (int i = 0; i < 8; i++)
#pragma unroll
                for (int j = 0; j < 4; j++) acc[i][j] = fmaf(a[i], b[j], acc[i][j]);
        }
        __syncthreads();
    }

#pragma unroll
    for (int i = 0; i < 8; i++) {
        int m = m0 + ty * 8 + i;
        float4 outv;
        float* o = (float*)&outv;
#pragma unroll
        for (int j = 0; j < 4; j++) {
            int n = n0 + tx * 4 + j;
            float c = acc[i][j];
            if (EPILOGUE) c += bias[n] + residual[(size_t)m * N + n];
            o[j] = c;
        }
        *(float4*)(C + (size_t)m * N + n0 + tx * 4) = outv;
    }
}

// ---------------------------------------------------------------------------
// Streaming attention, fp32, 64 q-rows x 64 k-cols tiles, online softmax.
// mask[b,q,k] != 0  => score = -inf (masked out)
// Layouts: qh/kh/vh/ctx are [b*SEQ, 1024] with column = h*64 + e.
// ---------------------------------------------------------------------------
__global__ void __launch_bounds__(256) attn_kernel(
    const float* __restrict__ qh, const float* __restrict__ kh,
    const float* __restrict__ vh, const unsigned char* __restrict__ mask,
    float* __restrict__ ctx)
{
    extern __shared__ float sm[];
    const int PAD = 68;
    float* Qs = sm;
    float* Ks = Qs + 64 * PAD;
    float* Vs = Ks + 64 * PAD;
    float* Ps = Vs + 64 * PAD;

    const int tid = threadIdx.x;
    const int ty = tid >> 4;          // 0..15, 4 rows each
    const int tx = tid & 15;          // 0..15, 4 cols each
    const int qt = blockIdx.x;        // 0..31  (q tile)
    const int hb = blockIdx.y;        // 0..31
    const int h  = hb >> 1;
    const int b  = hb & 1;
    const int q0 = qt * 64;
    const size_t rowbase = (size_t)b * SEQ;
    const int coloff = h * DHEAD;

    // Q tile
#pragma unroll
    for (int it = 0; it < 4; it++) {
        int idx = tid + it * 256;      // 0..1023
        int r = idx >> 4;
        int c4 = (idx & 15) * 4;
        float4 v = *(const float4*)(qh + (rowbase + q0 + r) * DMODEL + coloff + c4);
        *(float4*)(Qs + r * PAD + c4) = v;
    }

    float m_run[4], l_run[4], acc[4][4];
#pragma unroll
    for (int i = 0; i < 4; i++) {
        m_run[i] = -1e30f; l_run[i] = 0.f;
#pragma unroll
        for (int j = 0; j < 4; j++) acc[i][j] = 0.f;
    }

    const float scale = 0.125f;   // 1/sqrt(64)

    for (int kt = 0; kt < SEQ / 64; kt++) {
        const int k0 = kt * 64;
        __syncthreads();   // Ks/Vs consumed by previous iteration (also fences Qs on kt=0)
#pragma unroll
        for (int it = 0; it < 4; it++) {
            int idx = tid + it * 256;
            int r = idx >> 4;
            int c4 = (idx & 15) * 4;
            float4 kv = *(const float4*)(kh + (rowbase + k0 + r) * DMODEL + coloff + c4);
            *(float4*)(Ks + r * PAD + c4) = kv;
            float4 vv = *(const float4*)(vh + (rowbase + k0 + r) * DMODEL + coloff + c4);
            *(float4*)(Vs + r * PAD + c4) = vv;
        }
        __syncthreads();

        // S = Q @ K^T (4x4 per thread)
        float s[4][4];
#pragma unroll
        for (int i = 0; i < 4; i++)
#pragma unroll
            for (int j = 0; j < 4; j++) s[i][j] = 0.f;
#pragma unroll
        for (int e = 0; e < 64; e++) {
            float qv[4], kv[4];
#pragma unroll
            for (int i = 0; i < 4; i++) qv[i] = Qs[(ty * 4 + i) * PAD + e];
#pragma unroll
            for (int j = 0; j < 4; j++) kv[j] = Ks[(tx * 4 + j) * PAD + e];
#pragma unroll
            for (int i = 0; i < 4; i++)
#pragma unroll
                for (int j = 0; j < 4; j++) s[i][j] = fmaf(qv[i], kv[j], s[i][j]);
        }

        // scale + mask (mask!=0 -> -inf)
#pragma unroll
        for (int i = 0; i < 4; i++) {
            int qg = q0 + ty * 4 + i;
            uchar4 mk = *(const uchar4*)(mask + ((size_t)b * SEQ + qg) * SEQ + k0 + tx * 4);
            s[i][0] = mk.x ? -1e30f : s[i][0] * scale;
            s[i][1] = mk.y ? -1e30f : s[i][1] * scale;
            s[i][2] = mk.z ? -1e30f : s[i][2] * scale;
            s[i][3] = mk.w ? -1e30f : s[i][3] * scale;
        }

        // online softmax: row max/sum reduced across the 16 tx lanes
#pragma unroll
        for (int i = 0; i < 4; i++) {
            float mt = fmaxf(fmaxf(s[i][0], s[i][1]), fmaxf(s[i][2], s[i][3]));
#pragma unroll
            for (int o = 1; o < 16; o <<= 1)
                mt = fmaxf(mt, __shfl_xor_sync(0xffffffffu, mt, o));
            float m_new = fmaxf(m_run[i], mt);
            float f = __expf(m_run[i] - m_new);
            l_run[i] *= f;
#pragma unroll
            for (int j = 0; j < 4; j++) acc[i][j] *= f;
            float rs = 0.f;
#pragma unroll
            for (int j = 0; j < 4; j++) {
                float p = __expf(s[i][j] - m_new);
                Ps[(ty * 4 + i) * PAD + tx * 4 + j] = p;
                rs += p;
            }
#pragma unroll
            for (int o = 1; o < 16; o <<= 1)
                rs += __shfl_xor_sync(0xffffffffu, rs, o);
            l_run[i] += rs;
            m_run[i] = m_new;
        }
        __syncthreads();

        // acc += P @ V
#pragma unroll
        for (int kk = 0; kk < 64; kk++) {
            float pv[4], vv[4];
#pragma unroll
            for (int i = 0; i < 4; i++) pv[i] = Ps[(ty * 4 + i) * PAD + kk];
#pragma unroll
            for (int j = 0; j < 4; j++) vv[j] = Vs[kk * PAD + tx * 4 + j];
#pragma unroll
            for (int i = 0; i < 4; i++)
#pragma unroll
                for (int j = 0; j < 4; j++) acc[i][j] = fmaf(pv[i], vv[j], acc[i][j]);
        }
    }

    // normalize and write context
#pragma unroll
    for (int i = 0; i < 4; i++) {
        float inv = 1.f / l_run[i];
        float4 outv;
        outv.x = acc[i][0] * inv; outv.y = acc[i][1] * inv;
        outv.z = acc[i][2] * inv; outv.w = acc[i][3] * inv;
        *(float4*)(ctx + (rowbase + q0 + ty * 4 + i) * DMODEL + coloff + tx * 4) = outv;
    }
}

// ---------------------------------------------------------------------------
// LayerNorm: torch semantics — unbiased std (ddof=1), eps added to STD.
// ---------------------------------------------------------------------------
__global__ void __launch_bounds__(256) ln_kernel(
    const float* __restrict__ y, const float* __restrict__ gamma,
    const float* __restrict__ beta, float* __restrict__ out)
{
    __shared__ float sh_s[8], sh_ss[8];
    const int row = blockIdx.x;
    const float* x = y + (size_t)row * DMODEL;

    float s = 0.f, ss = 0.f;
    for (int i = threadIdx.x; i < DMODEL; i += 256) {
        float v = x[i]; s += v; ss += v * v;
    }
#pragma unroll
    for (int o = 16; o > 0; o >>= 1) {
        s  += __shfl_xor_sync(0xffffffffu, s,  o);
        ss += __shfl_xor_sync(0xffffffffu, ss, o);
    }
    int warp = threadIdx.x >> 5, lane = threadIdx.x & 31;
    if (lane == 0) { sh_s[warp] = s; sh_ss[warp] = ss; }
    __syncthreads();
    if (threadIdx.x < 32) {
        s  = (lane < 8) ? sh_s[lane]  : 0.f;
        ss = (lane < 8) ? sh_ss[lane] : 0.f;
#pragma unroll
        for (int o = 4; o > 0; o >>= 1) {
            s  += __shfl_xor_sync(0xffffffffu, s,  o);
            ss += __shfl_xor_sync(0xffffffffu, ss, o);
        }
        if (lane == 0) { sh_s[0] = s; sh_ss[0] = ss; }
    }
    __syncthreads();
    float mean = sh_s[0] * (1.f / DMODEL);
    float var  = (sh_ss[0] - (float)DMODEL * mean * mean) * (1.f / (DMODEL - 1));
    var = fmaxf(var, 0.f);
    float inv = 1.f / (sqrtf(var) + 1e-3f);
    for (int i = threadIdx.x; i < DMODEL; i += 256)
        out[(size_t)row * DMODEL + i] = (x[i] - mean) * inv * gamma[i] + beta[i];
}

// ---------------------------------------------------------------------------
extern "C" void kernel_launch(void* const* d_in, const int* in_sizes, int n_in,
                              void* d_out, int out_size)
{
    const float*         v     = (const float*)d_in[0];
    const float*         k     = (const float*)d_in[1];
    const float*         q     = (const float*)d_in[2];
    const void*          mask  = (const void*)d_in[3];
    const float*         w_q   = (const float*)d_in[4];
    const float*         w_k   = (const float*)d_in[5];
    const float*         w_v   = (const float*)d_in[6];
    const float*         w_o   = (const float*)d_in[7];
    const float*         b_o   = (const float*)d_in[8];
    const float*         gamma = (const float*)d_in[9];
    const float*         beta  = (const float*)d_in[10];
    float*               out   = (float*)d_out;

    float *qh, *kh, *vh, *ctx, *y;
    unsigned char* mask8;
    cudaGetSymbolAddress((void**)&qh,    g_qh);
    cudaGetSymbolAddress((void**)&kh,    g_kh);
    cudaGetSymbolAddress((void**)&vh,    g_vh);
    cudaGetSymbolAddress((void**)&ctx,   g_ctx);
    cudaGetSymbolAddress((void**)&y,     g_y);
    cudaGetSymbolAddress((void**)&mask8, g_mask8);

    const int SMEM_ATTN = 4 * 64 * 68 * sizeof(float);  // 69632
    cudaFuncSetAttribute(attn_kernel, cudaFuncAttributeMaxDynamicSharedMemorySize, SMEM_ATTN);

    // Mask dtype probe + normalize to uint8
    probe_mask<<<1, 1024>>>((const unsigned int*)mask);
    convert_mask<<<(int)((MASKN + 255) / 256), 256>>>(mask);

    dim3 gemm_grid(DMODEL / 64, MROWS / 128);   // (16, 32)

    // Projections: [4096,1024] @ headed [1024, (h,e)]
    gemm128x64<true,  false><<<gemm_grid, 256>>>(q, w_q, qh, MROWS, DMODEL, DMODEL, nullptr, nullptr);
    gemm128x64<true,  false><<<gemm_grid, 256>>>(k, w_k, kh, MROWS, DMODEL, DMODEL, nullptr, nullptr);
    gemm128x64<true,  false><<<gemm_grid, 256>>>(v, w_v, vh, MROWS, DMODEL, DMODEL, nullptr, nullptr);

    // Attention: grid (q tiles, h*b)
    dim3 attn_grid(SEQ / 64, NHEAD * BATCH);
    attn_kernel<<<attn_grid, 256, SMEM_ATTN>>>(qh, kh, vh, mask8, ctx);

    // Output projection + bias + residual(k)
    gemm128x64<false, true ><<<gemm_grid, 256>>>(ctx, w_o, y, MROWS, DMODEL, DMODEL, b_o, k);

    // LayerNorm
    ln_kernel<<<MROWS, 256>>>(y, gamma, beta, out);
}

// round 4
// speedup vs baseline: 1.1880x; 1.1880x over previous
#include <cuda_runtime.h>
#include <cuda_bf16.h>
#include <math.h>
#include <cstdint>

#define NHEAD  16
#define DMODEL 1024
#define DHEAD  64
#define BATCH  2
#define SEQ    2048
#define MROWS  (BATCH*SEQ)   // 4096
#define MASKN  ((size_t)BATCH*SEQ*SEQ)
#define KCAT   3072          // [hi | lo | hi] concat along K

// Scratch (device globals; no allocation in kernel_launch)
__device__ float g_qh [MROWS*DMODEL];
__device__ float g_kh [MROWS*DMODEL];
__device__ float g_vh [MROWS*DMODEL];
__device__ float g_ctx[MROWS*DMODEL];
__device__ float g_y  [MROWS*DMODEL];
__device__ unsigned char g_mask8[MASKN];
__device__ int g_fmt;
__device__ __nv_bfloat16 g_acat[(size_t)MROWS*KCAT];   // 25.2MB
__device__ __nv_bfloat16 g_wcat[(size_t)DMODEL*KCAT];  // 6.3MB

// ======================= mma.sync + cp.async helpers =======================
__device__ __forceinline__ void mma16816(float* c, const uint32_t* a, const uint32_t* b) {
    asm volatile("mma.sync.aligned.m16n8k16.row.col.f32.bf16.bf16.f32 "
        "{%0,%1,%2,%3}, {%4,%5,%6,%7}, {%8,%9}, {%0,%1,%2,%3};"
        : "+f"(c[0]), "+f"(c[1]), "+f"(c[2]), "+f"(c[3])
        : "r"(a[0]), "r"(a[1]), "r"(a[2]), "r"(a[3]), "r"(b[0]), "r"(b[1]));
}
__device__ __forceinline__ uint32_t smem_u32(const void* p) {
    uint32_t a;
    asm("{ .reg .u64 t; cvta.to.shared.u64 t, %1; cvt.u32.u64 %0, t; }" : "=r"(a) : "l"(p));
    return a;
}
__device__ __forceinline__ void cp16(uint32_t dst, const void* src) {
    asm volatile("cp.async.cg.shared.global [%0], [%1], 16;" :: "r"(dst), "l"(src));
}
#define CP_COMMIT() asm volatile("cp.async.commit_group;" ::: "memory")
#define CP_WAIT1()  asm volatile("cp.async.wait_group 1;" ::: "memory")
#define CP_WAIT0()  asm volatile("cp.async.wait_group 0;" ::: "memory")

// ======================= mask dtype probe + convert ========================
__global__ void probe_mask(const unsigned int* __restrict__ m) {
    __shared__ int s_i32, s_f32;
    if (threadIdx.x == 0) { s_i32 = 1; s_f32 = 1; }
    __syncthreads();
    int bad_i = 0, bad_f = 0;
    for (int i = threadIdx.x; i < (1 << 20); i += blockDim.x) {
        unsigned int w = m[i];
        if (w != 0u && w != 1u) bad_i = 1;
        if (w != 0u && w != 0x3F800000u) bad_f = 1;
    }
    if (bad_i) atomicAnd(&s_i32, 0);
    if (bad_f) atomicAnd(&s_f32, 0);
    __syncthreads();
    if (threadIdx.x == 0) g_fmt = s_i32 ? 1 : (s_f32 ? 2 : 0);
}
__global__ void convert_mask(const void* __restrict__ src) {
    size_t i = (size_t)blockIdx.x * blockDim.x + threadIdx.x;
    if (i >= MASKN) return;
    int fmt = g_fmt;
    unsigned char v;
    if (fmt == 1)      v = (unsigned char)(((const int*)src)[i] != 0);
    else if (fmt == 2) v = (unsigned char)(((const float*)src)[i] != 0.f);
    else               v = ((const unsigned char*)src)[i];
    g_mask8[i] = v;
}

// ======================= bf16 hi/lo split conversions ======================
// A_cat[r, 0:1024)=hi, [1024:2048)=lo, [2048:3072)=hi
__global__ void split_act(const float* __restrict__ in, __nv_bfloat16* __restrict__ out) {
    size_t i = (size_t)blockIdx.x * blockDim.x + threadIdx.x;
    if (i >= (size_t)MROWS * DMODEL) return;
    size_t r = i / DMODEL, d = i % DMODEL;
    float v = in[i];
    __nv_bfloat16 hi = __float2bfloat16(v);
    __nv_bfloat16 lo = __float2bfloat16(v - __bfloat162float(hi));
    __nv_bfloat16* o = out + r * KCAT;
    o[d] = hi; o[1024 + d] = lo; o[2048 + d] = hi;
}
// W_cat[n, 0:1024)=hi, [1024:2048)=hi, [2048:3072)=lo
__global__ void split_w_headed(const float* __restrict__ w, __nv_bfloat16* __restrict__ out) {
    size_t i = (size_t)blockIdx.x * blockDim.x + threadIdx.x;
    if (i >= (size_t)NHEAD * DMODEL * DHEAD) return;
    int h = (int)(i / (DMODEL * DHEAD));
    int rem = (int)(i % (DMODEL * DHEAD));
    int d = rem / DHEAD, e = rem % DHEAD;
    int n = h * DHEAD + e;
    float v = w[i];
    __nv_bfloat16 hi = __float2bfloat16(v);
    __nv_bfloat16 lo = __float2bfloat16(v - __bfloat162float(hi));
    __nv_bfloat16* o = out + (size_t)n * KCAT;
    o[d] = hi; o[1024 + d] = hi; o[2048 + d] = lo;
}
__global__ void split_w_flat(const float* __restrict__ w, __nv_bfloat16* __restrict__ out) {
    size_t i = (size_t)blockIdx.x * blockDim.x + threadIdx.x;
    if (i >= (size_t)DMODEL * DMODEL) return;
    int d = (int)(i / DMODEL), n = (int)(i % DMODEL);
    float v = w[i];
    __nv_bfloat16 hi = __float2bfloat16(v);
    __nv_bfloat16 lo = __float2bfloat16(v - __bfloat162float(hi));
    __nv_bfloat16* o = out + (size_t)n * KCAT;
    o[d] = hi; o[1024 + d] = hi; o[2048 + d] = lo;
}

// ======================= mma.sync GEMM: 128M x 128N, BK=64 ================
// A [MROWS, KCAT] bf16 row-major; Bt [DMODEL(n), KCAT] bf16 K-major.
// C [MROWS, DMODEL] fp32 (+bias+residual when EPI).
// SMEM: padded rows of 72 bf16 (36 words) -> conflict-free fragment LDS.
#define GBK     64
#define GNITER  (KCAT / GBK)                 // 48
#define TILE_B  (128 * 72 * 2)               // 18432 bytes per A or B tile
#define BUF_B   (2 * TILE_B)                 // 36864 per buffer (A+B)
#define GEMM_SMEM (2 * BUF_B)                // 73728

template<bool EPI>
__global__ void __launch_bounds__(256) gemm_mma(
    const __nv_bfloat16* __restrict__ A, const __nv_bfloat16* __restrict__ Bt,
    float* __restrict__ C, const float* __restrict__ bias,
    const float* __restrict__ residual)
{
    extern __shared__ char smc[];
    const uint32_t smb = smem_u32(smc);
    const int tid = threadIdx.x;
    const int wid = tid >> 5, lid = tid & 31;
    const int wm = wid >> 2, wn = wid & 3;        // warp grid 2m x 4n
    const int g = lid >> 2, tg = lid & 3;
    const int m0 = blockIdx.y * 128, n0 = blockIdx.x * 128;

    const __nv_bfloat16* Ag0 = A  + (size_t)m0 * KCAT;
    const __nv_bfloat16* Bg0 = Bt + (size_t)n0 * KCAT;

    // chunk map: 4 chunks each for A and B per thread
    const int crow = tid >> 3;          // over 2 iters covers rows (tid + i*256)>>3
    const int cch  = tid & 7;

    float acc[4][4][4];
#pragma unroll
    for (int mt = 0; mt < 4; mt++)
#pragma unroll
        for (int nt = 0; nt < 4; nt++)
#pragma unroll
            for (int r = 0; r < 4; r++) acc[mt][nt][r] = 0.f;

    // ---- prologue: load chunk 0 into buf 0
    {
        const __nv_bfloat16* Ag = Ag0;
        const __nv_bfloat16* Bg = Bg0;
#pragma unroll
        for (int i = 0; i < 4; i++) {
            int idx = tid + i * 256;
            int r = idx >> 3, ch = idx & 7;
            cp16(smb + r * 144 + ch * 16,          Ag + (size_t)r * KCAT + ch * 8);
            cp16(smb + TILE_B + r * 144 + ch * 16, Bg + (size_t)r * KCAT + ch * 8);
        }
        CP_COMMIT();
    }

    int buf = 0;
    for (int it = 0; it < GNITER; it++) {
        if (it + 1 < GNITER) {
            const __nv_bfloat16* Ag = Ag0 + (it + 1) * GBK;
            const __nv_bfloat16* Bg = Bg0 + (it + 1) * GBK;
            const uint32_t nb = smb + (buf ^ 1) * BUF_B;
#pragma unroll
            for (int i = 0; i < 4; i++) {
                int idx = tid + i * 256;
                int r = idx >> 3, ch = idx & 7;
                cp16(nb + r * 144 + ch * 16,          Ag + (size_t)r * KCAT + ch * 8);
                cp16(nb + TILE_B + r * 144 + ch * 16, Bg + (size_t)r * KCAT + ch * 8);
            }
            CP_COMMIT();
            CP_WAIT1();
        } else {
            CP_WAIT0();
        }
        __syncthreads();

        const uint32_t* As32 = (const uint32_t*)(smc + buf * BUF_B);
        const uint32_t* Bs32 = (const uint32_t*)(smc + buf * BUF_B + TILE_B);

#pragma unroll
        for (int ks = 0; ks < 4; ks++) {
            uint32_t a[4][4], b[4][2];
#pragma unroll
            for (int mt = 0; mt < 4; mt++) {
                int rb = wm * 64 + mt * 16;
                a[mt][0] = As32[(rb + g)     * 36 + ks * 8 + tg];
                a[mt][1] = As32[(rb + g + 8) * 36 + ks * 8 + tg];
                a[mt][2] = As32[(rb + g)     * 36 + ks * 8 + 4 + tg];
                a[mt][3] = As32[(rb + g + 8) * 36 + ks * 8 + 4 + tg];
            }
#pragma unroll
            for (int nt = 0; nt < 4; nt++) {
                int nb = wn * 32 + nt * 8;
                b[nt][0] = Bs32[(nb + g) * 36 + ks * 8 + tg];
                b[nt][1] = Bs32[(nb + g) * 36 + ks * 8 + 4 + tg];
            }
#pragma unroll
            for (int mt = 0; mt < 4; mt++)
#pragma unroll
                for (int nt = 0; nt < 4; nt++)
                    mma16816(acc[mt][nt], a[mt], b[nt]);
        }
        __syncthreads();
        buf ^= 1;
    }

    // ---- epilogue
#pragma unroll
    for (int mt = 0; mt < 4; mt++) {
        int m = m0 + wm * 64 + mt * 16 + g;
#pragma unroll
        for (int nt = 0; nt < 4; nt++) {
            int n = n0 + wn * 32 + nt * 8 + 2 * tg;
            float2 v0 = make_float2(acc[mt][nt][0], acc[mt][nt][1]);
            float2 v1 = make_float2(acc[mt][nt][2], acc[mt][nt][3]);
            if (EPI) {
                float2 bv = *(const float2*)(bias + n);
                float2 r0 = *(const float2*)(residual + (size_t)m * DMODEL + n);
                float2 r1 = *(const float2*)(residual + (size_t)(m + 8) * DMODEL + n);
                v0.x += bv.x + r0.x; v0.y += bv.y + r0.y;
                v1.x += bv.x + r1.x; v1.y += bv.y + r1.y;
            }
            *(float2*)(C + (size_t)m * DMODEL + n)       = v0;
            *(float2*)(C + (size_t)(m + 8) * DMODEL + n) = v1;
        }
    }
}

// ======================= attention (fp32, unchanged) =======================
__global__ void __launch_bounds__(256) attn_kernel(
    const float* __restrict__ qh, const float* __restrict__ kh,
    const float* __restrict__ vh, const unsigned char* __restrict__ mask,
    float* __restrict__ ctx)
{
    extern __shared__ float smf[];
    const int PAD = 68;
    float* Qs = smf;
    float* Ks = Qs + 64 * PAD;
    float* Vs = Ks + 64 * PAD;
    float* Ps = Vs + 64 * PAD;

    const int tid = threadIdx.x;
    const int ty = tid >> 4;
    const int tx = tid & 15;
    const int qt = blockIdx.x;
    const int hb = blockIdx.y;
    const int h  = hb >> 1;
    const int b  = hb & 1;
    const int q0 = qt * 64;
    const size_t rowbase = (size_t)b * SEQ;
    const int coloff = h * DHEAD;

#pragma unroll
    for (int it = 0; it < 4; it++) {
        int idx = tid + it * 256;
        int r = idx >> 4;
        int c4 = (idx & 15) * 4;
        float4 v = *(const float4*)(qh + (rowbase + q0 + r) * DMODEL + coloff + c4);
        *(float4*)(Qs + r * PAD + c4) = v;
    }

    float m_run[4], l_run[4], acc[4][4];
#pragma unroll
    for (int i = 0; i < 4; i++) {
        m_run[i] = -1e30f; l_run[i] = 0.f;
#pragma unroll
        for (int j = 0; j < 4; j++) acc[i][j] = 0.f;
    }
    const float scale = 0.125f;

    for (int kt = 0; kt < SEQ / 64; kt++) {
        const int k0 = kt * 64;
        __syncthreads();
#pragma unroll
        for (int it = 0; it < 4; it++) {
            int idx = tid + it * 256;
            int r = idx >> 4;
            int c4 = (idx & 15) * 4;
            float4 kv = *(const float4*)(kh + (rowbase + k0 + r) * DMODEL + coloff + c4);
            *(float4*)(Ks + r * PAD + c4) = kv;
            float4 vv = *(const float4*)(vh + (rowbase + k0 + r) * DMODEL + coloff + c4);
            *(float4*)(Vs + r * PAD + c4) = vv;
        }
        __syncthreads();

        float s[4][4];
#pragma unroll
        for (int i = 0; i < 4; i++)
#pragma unroll
            for (int j = 0; j < 4; j++) s[i][j] = 0.f;
#pragma unroll
        for (int e = 0; e < 64; e++) {
            float qv[4], kv[4];
#pragma unroll
            for (int i = 0; i < 4; i++) qv[i] = Qs[(ty * 4 + i) * PAD + e];
#pragma unroll
            for (int j = 0; j < 4; j++) kv[j] = Ks[(tx * 4 + j) * PAD + e];
#pragma unroll
            for (int i = 0; i < 4; i++)
#pragma unroll
                for (int j = 0; j < 4; j++) s[i][j] = fmaf(qv[i], kv[j], s[i][j]);
        }

#pragma unroll
        for (int i = 0; i < 4; i++) {
            int qg = q0 + ty * 4 + i;
            uchar4 mk = *(const uchar4*)(mask + ((size_t)b * SEQ + qg) * SEQ + k0 + tx * 4);
            s[i][0] = mk.x ? -1e30f : s[i][0] * scale;
            s[i][1] = mk.y ? -1e30f : s[i][1] * scale;
            s[i][2] = mk.z ? -1e30f : s[i][2] * scale;
            s[i][3] = mk.w ? -1e30f : s[i][3] * scale;
        }

#pragma unroll
        for (int i = 0; i < 4; i++) {
            float mt = fmaxf(fmaxf(s[i][0], s[i][1]), fmaxf(s[i][2], s[i][3]));
#pragma unroll
            for (int o = 1; o < 16; o <<= 1)
                mt = fmaxf(mt, __shfl_xor_sync(0xffffffffu, mt, o));
            float m_new = fmaxf(m_run[i], mt);
            float f = __expf(m_run[i] - m_new);
            l_run[i] *= f;
#pragma unroll
            for (int j = 0; j < 4; j++) acc[i][j] *= f;
            float rs = 0.f;
#pragma unroll
            for (int j = 0; j < 4; j++) {
                float p = __expf(s[i][j] - m_new);
                Ps[(ty * 4 + i) * PAD + tx * 4 + j] = p;
                rs += p;
            }
#pragma unroll
            for (int o = 1; o < 16; o <<= 1)
                rs += __shfl_xor_sync(0xffffffffu, rs, o);
            l_run[i] += rs;
            m_run[i] = m_new;
        }
        __syncthreads();

#pragma unroll
        for (int kk = 0; kk < 64; kk++) {
            float pv[4], vv[4];
#pragma unroll
            for (int i = 0; i < 4; i++) pv[i] = Ps[(ty * 4 + i) * PAD + kk];
#pragma unroll
            for (int j = 0; j < 4; j++) vv[j] = Vs[kk * PAD + tx * 4 + j];
#pragma unroll
            for (int i = 0; i < 4; i++)
#pragma unroll
                for (int j = 0; j < 4; j++) acc[i][j] = fmaf(pv[i], vv[j], acc[i][j]);
        }
    }

#pragma unroll
    for (int i = 0; i < 4; i++) {
        float inv = 1.f / l_run[i];
        float4 outv;
        outv.x = acc[i][0] * inv; outv.y = acc[i][1] * inv;
        outv.z = acc[i][2] * inv; outv.w = acc[i][3] * inv;
        *(float4*)(ctx + (rowbase + q0 + ty * 4 + i) * DMODEL + coloff + tx * 4) = outv;
    }
}

// ======================= LayerNorm (torch semantics) =======================
__global__ void __launch_bounds__(256) ln_kernel(
    const float* __restrict__ y, const float* __restrict__ gamma,
    const float* __restrict__ beta, float* __restrict__ out)
{
    __shared__ float sh_s[8], sh_ss[8];
    const int row = blockIdx.x;
    const float* x = y + (size_t)row * DMODEL;

    float s = 0.f, ss = 0.f;
    for (int i = threadIdx.x; i < DMODEL; i += 256) {
        float v = x[i]; s += v; ss += v * v;
    }
#pragma unroll
    for (int o = 16; o > 0; o >>= 1) {
        s  += __shfl_xor_sync(0xffffffffu, s,  o);
        ss += __shfl_xor_sync(0xffffffffu, ss, o);
    }
    int warp = threadIdx.x >> 5, lane = threadIdx.x & 31;
    if (lane == 0) { sh_s[warp] = s; sh_ss[warp] = ss; }
    __syncthreads();
    if (threadIdx.x < 32) {
        s  = (lane < 8) ? sh_s[lane]  : 0.f;
        ss = (lane < 8) ? sh_ss[lane] : 0.f;
#pragma unroll
        for (int o = 4; o > 0; o >>= 1) {
            s  += __shfl_xor_sync(0xffffffffu, s,  o);
            ss += __shfl_xor_sync(0xffffffffu, ss, o);
        }
        if (lane == 0) { sh_s[0] = s; sh_ss[0] = ss; }
    }
    __syncthreads();
    float mean = sh_s[0] * (1.f / DMODEL);
    float var  = (sh_ss[0] - (float)DMODEL * mean * mean) * (1.f / (DMODEL - 1));
    var = fmaxf(var, 0.f);
    float inv = 1.f / (sqrtf(var) + 1e-3f);
    for (int i = threadIdx.x; i < DMODEL; i += 256)
        out[(size_t)row * DMODEL + i] = (x[i] - mean) * inv * gamma[i] + beta[i];
}

// ===========================================================================
extern "C" void kernel_launch(void* const* d_in, const int* in_sizes, int n_in,
                              void* d_out, int out_size)
{
    const float* v     = (const float*)d_in[0];
    const float* k     = (const float*)d_in[1];
    const float* q     = (const float*)d_in[2];
    const void*  mask  = (const void*)d_in[3];
    const float* w_q   = (const float*)d_in[4];
    const float* w_k   = (const float*)d_in[5];
    const float* w_v   = (const float*)d_in[6];
    const float* w_o   = (const float*)d_in[7];
    const float* b_o   = (const float*)d_in[8];
    const float* gamma = (const float*)d_in[9];
    const float* beta  = (const float*)d_in[10];
    float*       out   = (float*)d_out;

    float *qh, *kh, *vh, *ctx, *y;
    unsigned char* mask8;
    __nv_bfloat16 *acat, *wcat;
    cudaGetSymbolAddress((void**)&qh,    g_qh);
    cudaGetSymbolAddress((void**)&kh,    g_kh);
    cudaGetSymbolAddress((void**)&vh,    g_vh);
    cudaGetSymbolAddress((void**)&ctx,   g_ctx);
    cudaGetSymbolAddress((void**)&y,     g_y);
    cudaGetSymbolAddress((void**)&mask8, g_mask8);
    cudaGetSymbolAddress((void**)&acat,  g_acat);
    cudaGetSymbolAddress((void**)&wcat,  g_wcat);

    const int SMEM_ATTN = 4 * 64 * 68 * sizeof(float);
    cudaFuncSetAttribute(attn_kernel, cudaFuncAttributeMaxDynamicSharedMemorySize, SMEM_ATTN);
    cudaFuncSetAttribute(gemm_mma<false>, cudaFuncAttributeMaxDynamicSharedMemorySize, GEMM_SMEM);
    cudaFuncSetAttribute(gemm_mma<true>,  cudaFuncAttributeMaxDynamicSharedMemorySize, GEMM_SMEM);

    // Mask -> uint8
    probe_mask<<<1, 1024>>>((const unsigned int*)mask);
    convert_mask<<<(int)((MASKN + 255) / 256), 256>>>(mask);

    const int ACT_N = MROWS * DMODEL;
    const int WH_N  = NHEAD * DMODEL * DHEAD;
    const int WF_N  = DMODEL * DMODEL;
    dim3 ggrid(DMODEL / 128, MROWS / 128);       // (8, 32)

    // Q projection
    split_w_headed<<<(WH_N + 255) / 256, 256>>>(w_q, wcat);
    split_act<<<(ACT_N + 255) / 256, 256>>>(q, acat);
    gemm_mma<false><<<ggrid, 256, GEMM_SMEM>>>(acat, wcat, qh, nullptr, nullptr);
    // K projection
    split_w_headed<<<(WH_N + 255) / 256, 256>>>(w_k, wcat);
    split_act<<<(ACT_N + 255) / 256, 256>>>(k, acat);
    gemm_mma<false><<<ggrid, 256, GEMM_SMEM>>>(acat, wcat, kh, nullptr, nullptr);
    // V projection
    split_w_headed<<<(WH_N + 255) / 256, 256>>>(w_v, wcat);
    split_act<<<(ACT_N + 255) / 256, 256>>>(v, acat);
    gemm_mma<false><<<ggrid, 256, GEMM_SMEM>>>(acat, wcat, vh, nullptr, nullptr);

    // Attention (fp32)
    dim3 attn_grid(SEQ / 64, NHEAD * BATCH);
    attn_kernel<<<attn_grid, 256, SMEM_ATTN>>>(qh, kh, vh, mask8, ctx);

    // Output projection + bias + residual(k)
    split_w_flat<<<(WF_N + 255) / 256, 256>>>(w_o, wcat);
    split_act<<<(ACT_N + 255) / 256, 256>>>(ctx, acat);
    gemm_mma<true><<<ggrid, 256, GEMM_SMEM>>>(acat, wcat, y, b_o, k);

    // LayerNorm
    ln_kernel<<<MROWS, 256>>>(y, gamma, beta, out);
}

// round 5
// speedup vs baseline: 2.2334x; 1.8799x over previous
#include <cuda_runtime.h>
#include <cuda_bf16.h>
#include <math.h>
#include <cstdint>

#define NHEAD  16
#define DMODEL 1024
#define DHEAD  64
#define BATCH  2
#define SEQ    2048
#define MROWS  (BATCH*SEQ)   // 4096
#define MASKN  ((size_t)BATCH*SEQ*SEQ)
#define KCAT   3072          // [hi | lo | hi] concat along K (projection GEMMs)

// Scratch (device globals; no allocation in kernel_launch)
__device__ float g_qh [MROWS*DMODEL];
__device__ float g_kh [MROWS*DMODEL];
__device__ float g_vh [MROWS*DMODEL];
__device__ float g_y  [MROWS*DMODEL];
__device__ unsigned char g_mask8[MASKN];
__device__ int g_fmt;
__device__ __nv_bfloat16 g_acat[(size_t)MROWS*KCAT];   // 25.2MB
__device__ __nv_bfloat16 g_wcat[(size_t)DMODEL*KCAT];  // 6.3MB
// attention operands: per-head [hi|lo] layouts
__device__ __nv_bfloat16 g_qc[(size_t)32*SEQ*128];     // [hb][q][hi64|lo64]
__device__ __nv_bfloat16 g_kc[(size_t)32*SEQ*128];     // [hb][k][hi64|lo64]
__device__ __nv_bfloat16 g_vt[(size_t)32*64*32*128];   // [hb][e][kt][hi64|lo64]

// ======================= mma.sync + cp.async helpers =======================
__device__ __forceinline__ void mma16816(float* c, const uint32_t* a, const uint32_t* b) {
    asm volatile("mma.sync.aligned.m16n8k16.row.col.f32.bf16.bf16.f32 "
        "{%0,%1,%2,%3}, {%4,%5,%6,%7}, {%8,%9}, {%0,%1,%2,%3};"
        : "+f"(c[0]), "+f"(c[1]), "+f"(c[2]), "+f"(c[3])
        : "r"(a[0]), "r"(a[1]), "r"(a[2]), "r"(a[3]), "r"(b[0]), "r"(b[1]));
}
__device__ __forceinline__ uint32_t smem_u32(const void* p) {
    uint32_t a;
    asm("{ .reg .u64 t; cvta.to.shared.u64 t, %1; cvt.u32.u64 %0, t; }" : "=r"(a) : "l"(p));
    return a;
}
__device__ __forceinline__ void cp16(uint32_t dst, const void* src) {
    asm volatile("cp.async.cg.shared.global [%0], [%1], 16;" :: "r"(dst), "l"(src));
}
#define CP_COMMIT() asm volatile("cp.async.commit_group;" ::: "memory")
#define CP_WAIT1()  asm volatile("cp.async.wait_group 1;" ::: "memory")
#define CP_WAIT0()  asm volatile("cp.async.wait_group 0;" ::: "memory")

__device__ __forceinline__ void pack_hilo(float x, float y, uint32_t& hi, uint32_t& lo) {
    __nv_bfloat16 hx = __float2bfloat16(x), hy = __float2bfloat16(y);
    __nv_bfloat16 lx = __float2bfloat16(x - __bfloat162float(hx));
    __nv_bfloat16 ly = __float2bfloat16(y - __bfloat162float(hy));
    __nv_bfloat162 hp = __halves2bfloat162(hx, hy);
    __nv_bfloat162 lp = __halves2bfloat162(lx, ly);
    hi = *(uint32_t*)&hp; lo = *(uint32_t*)&lp;
}

// ======================= mask dtype probe + convert ========================
__global__ void probe_mask(const unsigned int* __restrict__ m) {
    __shared__ int s_i32, s_f32;
    if (threadIdx.x == 0) { s_i32 = 1; s_f32 = 1; }
    __syncthreads();
    int bad_i = 0, bad_f = 0;
    for (int i = threadIdx.x; i < (1 << 20); i += blockDim.x) {
        unsigned int w = m[i];
        if (w != 0u && w != 1u) bad_i = 1;
        if (w != 0u && w != 0x3F800000u) bad_f = 1;
    }
    if (bad_i) atomicAnd(&s_i32, 0);
    if (bad_f) atomicAnd(&s_f32, 0);
    __syncthreads();
    if (threadIdx.x == 0) g_fmt = s_i32 ? 1 : (s_f32 ? 2 : 0);
}
__global__ void convert_mask(const void* __restrict__ src) {
    size_t i = (size_t)blockIdx.x * blockDim.x + threadIdx.x;
    if (i >= MASKN) return;
    int fmt = g_fmt;
    unsigned char v;
    if (fmt == 1)      v = (unsigned char)(((const int*)src)[i] != 0);
    else if (fmt == 2) v = (unsigned char)(((const float*)src)[i] != 0.f);
    else               v = ((const unsigned char*)src)[i];
    g_mask8[i] = v;
}

// ======================= bf16 hi/lo split conversions ======================
__global__ void split_act(const float* __restrict__ in, __nv_bfloat16* __restrict__ out) {
    size_t i = (size_t)blockIdx.x * blockDim.x + threadIdx.x;
    if (i >= (size_t)MROWS * DMODEL) return;
    size_t r = i / DMODEL, d = i % DMODEL;
    float v = in[i];
    __nv_bfloat16 hi = __float2bfloat16(v);
    __nv_bfloat16 lo = __float2bfloat16(v - __bfloat162float(hi));
    __nv_bfloat16* o = out + r * KCAT;
    o[d] = hi; o[1024 + d] = lo; o[2048 + d] = hi;
}
__global__ void split_w_headed(const float* __restrict__ w, __nv_bfloat16* __restrict__ out) {
    size_t i = (size_t)blockIdx.x * blockDim.x + threadIdx.x;
    if (i >= (size_t)NHEAD * DMODEL * DHEAD) return;
    int h = (int)(i / (DMODEL * DHEAD));
    int rem = (int)(i % (DMODEL * DHEAD));
    int d = rem / DHEAD, e = rem % DHEAD;
    int n = h * DHEAD + e;
    float v = w[i];
    __nv_bfloat16 hi = __float2bfloat16(v);
    __nv_bfloat16 lo = __float2bfloat16(v - __bfloat162float(hi));
    __nv_bfloat16* o = out + (size_t)n * KCAT;
    o[d] = hi; o[1024 + d] = hi; o[2048 + d] = lo;
}
__global__ void split_w_flat(const float* __restrict__ w, __nv_bfloat16* __restrict__ out) {
    size_t i = (size_t)blockIdx.x * blockDim.x + threadIdx.x;
    if (i >= (size_t)DMODEL * DMODEL) return;
    int d = (int)(i / DMODEL), n = (int)(i % DMODEL);
    float v = w[i];
    __nv_bfloat16 hi = __float2bfloat16(v);
    __nv_bfloat16 lo = __float2bfloat16(v - __bfloat162float(hi));
    __nv_bfloat16* o = out + (size_t)n * KCAT;
    o[d] = hi; o[1024 + d] = hi; o[2048 + d] = lo;
}

// qh/kh fp32 [4096][1024] -> [hb][row][hi64|lo64]
__global__ void conv_qk(const float* __restrict__ in, __nv_bfloat16* __restrict__ out) {
    size_t i = (size_t)blockIdx.x * blockDim.x + threadIdx.x;
    if (i >= (size_t)MROWS * DMODEL) return;
    int r = (int)(i >> 10), c = (int)(i & 1023);
    int b = r >> 11, q = r & 2047;
    int h = c >> 6, e = c & 63;
    int hb = (h << 1) + b;
    float v = in[i];
    __nv_bfloat16 hi = __float2bfloat16(v);
    __nv_bfloat16 lo = __float2bfloat16(v - __bfloat162float(hi));
    __nv_bfloat16* o = out + ((size_t)hb * SEQ + q) * 128;
    o[e] = hi; o[64 + e] = lo;
}
// vh fp32 -> transposed [hb][e][kt][hi64|lo64]
__global__ void conv_v(const float* __restrict__ vh, __nv_bfloat16* __restrict__ vt) {
    __shared__ float t[64][65];
    const int kt = blockIdx.x, hb = blockIdx.y;
    const int h = hb >> 1, b = hb & 1;
    const int tid = threadIdx.x;
#pragma unroll
    for (int i = 0; i < 16; i++) {
        int idx = tid + i * 256;
        int kr = idx >> 6, e = idx & 63;
        t[kr][e] = vh[((size_t)b * SEQ + kt * 64 + kr) * DMODEL + h * 64 + e];
    }
    __syncthreads();
#pragma unroll
    for (int i = 0; i < 16; i++) {
        int idx = tid + i * 256;
        int e = idx >> 6, kr = idx & 63;
        float v = t[kr][e];
        __nv_bfloat16 hi = __float2bfloat16(v);
        __nv_bfloat16 lo = __float2bfloat16(v - __bfloat162float(hi));
        __nv_bfloat16* o = vt + (((size_t)hb * 64 + e) * 32 + kt) * 128;
        o[kr] = hi; o[64 + kr] = lo;
    }
}

// ======================= mma.sync GEMM: 128M x 128N, BK=64 ================
#define GBK     64
#define GNITER  (KCAT / GBK)                 // 48
#define TILE_B  (128 * 72 * 2)               // 18432 bytes per A or B tile
#define BUF_B   (2 * TILE_B)                 // per buffer (A+B)
#define GEMM_SMEM (2 * BUF_B)                // 73728

template<bool EPI>
__global__ void __launch_bounds__(256) gemm_mma(
    const __nv_bfloat16* __restrict__ A, const __nv_bfloat16* __restrict__ Bt,
    float* __restrict__ C, const float* __restrict__ bias,
    const float* __restrict__ residual)
{
    extern __shared__ char smc[];
    const uint32_t smb = smem_u32(smc);
    const int tid = threadIdx.x;
    const int wid = tid >> 5, lid = tid & 31;
    const int wm = wid >> 2, wn = wid & 3;
    const int g = lid >> 2, tg = lid & 3;
    const int m0 = blockIdx.y * 128, n0 = blockIdx.x * 128;

    const __nv_bfloat16* Ag0 = A  + (size_t)m0 * KCAT;
    const __nv_bfloat16* Bg0 = Bt + (size_t)n0 * KCAT;

    float acc[4][4][4];
#pragma unroll
    for (int mt = 0; mt < 4; mt++)
#pragma unroll
        for (int nt = 0; nt < 4; nt++)
#pragma unroll
            for (int r = 0; r < 4; r++) acc[mt][nt][r] = 0.f;

    {
#pragma unroll
        for (int i = 0; i < 4; i++) {
            int idx = tid + i * 256;
            int r = idx >> 3, ch = idx & 7;
            cp16(smb + r * 144 + ch * 16,          Ag0 + (size_t)r * KCAT + ch * 8);
            cp16(smb + TILE_B + r * 144 + ch * 16, Bg0 + (size_t)r * KCAT + ch * 8);
        }
        CP_COMMIT();
    }

    int buf = 0;
    for (int it = 0; it < GNITER; it++) {
        if (it + 1 < GNITER) {
            const __nv_bfloat16* Ag = Ag0 + (it + 1) * GBK;
            const __nv_bfloat16* Bg = Bg0 + (it + 1) * GBK;
            const uint32_t nb = smb + (buf ^ 1) * BUF_B;
#pragma unroll
            for (int i = 0; i < 4; i++) {
                int idx = tid + i * 256;
                int r = idx >> 3, ch = idx & 7;
                cp16(nb + r * 144 + ch * 16,          Ag + (size_t)r * KCAT + ch * 8);
                cp16(nb + TILE_B + r * 144 + ch * 16, Bg + (size_t)r * KCAT + ch * 8);
            }
            CP_COMMIT();
            CP_WAIT1();
        } else {
            CP_WAIT0();
        }
        __syncthreads();

        const uint32_t* As32 = (const uint32_t*)(smc + buf * BUF_B);
        const uint32_t* Bs32 = (const uint32_t*)(smc + buf * BUF_B + TILE_B);

#pragma unroll
        for (int ks = 0; ks < 4; ks++) {
            uint32_t a[4][4], b[4][2];
#pragma unroll
            for (int mt = 0; mt < 4; mt++) {
                int rb = wm * 64 + mt * 16;
                a[mt][0] = As32[(rb + g)     * 36 + ks * 8 + tg];
                a[mt][1] = As32[(rb + g + 8) * 36 + ks * 8 + tg];
                a[mt][2] = As32[(rb + g)     * 36 + ks * 8 + 4 + tg];
                a[mt][3] = As32[(rb + g + 8) * 36 + ks * 8 + 4 + tg];
            }
#pragma unroll
            for (int nt = 0; nt < 4; nt++) {
                int nb = wn * 32 + nt * 8;
                b[nt][0] = Bs32[(nb + g) * 36 + ks * 8 + tg];
                b[nt][1] = Bs32[(nb + g) * 36 + ks * 8 + 4 + tg];
            }
#pragma unroll
            for (int mt = 0; mt < 4; mt++)
#pragma unroll
                for (int nt = 0; nt < 4; nt++)
                    mma16816(acc[mt][nt], a[mt], b[nt]);
        }
        __syncthreads();
        buf ^= 1;
    }

#pragma unroll
    for (int mt = 0; mt < 4; mt++) {
        int m = m0 + wm * 64 + mt * 16 + g;
#pragma unroll
        for (int nt = 0; nt < 4; nt++) {
            int n = n0 + wn * 32 + nt * 8 + 2 * tg;
            float2 v0 = make_float2(acc[mt][nt][0], acc[mt][nt][1]);
            float2 v1 = make_float2(acc[mt][nt][2], acc[mt][nt][3]);
            if (EPI) {
                float2 bv = *(const float2*)(bias + n);
                float2 r0 = *(const float2*)(residual + (size_t)m * DMODEL + n);
                float2 r1 = *(const float2*)(residual + (size_t)(m + 8) * DMODEL + n);
                v0.x += bv.x + r0.x; v0.y += bv.y + r0.y;
                v1.x += bv.x + r1.x; v1.y += bv.y + r1.y;
            }
            *(float2*)(C + (size_t)m * DMODEL + n)       = v0;
            *(float2*)(C + (size_t)(m + 8) * DMODEL + n) = v1;
        }
    }
}

// ======================= flash attention via mma.sync ======================
// Block: 128 q rows x one (h,b). 8 warps, each warp owns 16 q rows x 64 keys.
// K-tiles of 64 keys, double-buffered cp.async. 3-term hi/lo for QK and PV.
// Output written directly into acat ([hi|lo|hi], 3072 per row).
// SMEM: Q tile 128x272B; K,V tiles 64x272B x2 buffers.
#define AQ_OFF  0
#define AK_OFF  34816
#define AV_OFF  (34816 + 2*17408)
#define ATT_SMEM (34816 + 4*17408)   // 104448

__global__ void __launch_bounds__(256) attn_mma(
    const __nv_bfloat16* __restrict__ Qc, const __nv_bfloat16* __restrict__ Kc,
    const __nv_bfloat16* __restrict__ Vt, const unsigned char* __restrict__ mask,
    __nv_bfloat16* __restrict__ acat)
{
    extern __shared__ char smc[];
    const uint32_t smb = smem_u32(smc);
    const int tid = threadIdx.x;
    const int wid = tid >> 5, lid = tid & 31;
    const int g = lid >> 2, tg = lid & 3;
    const int qb = blockIdx.x, hb = blockIdx.y;
    const int h = hb >> 1, b = hb & 1;
    const int q0 = qb * 128;

    // ---- load Q tile (persistent) + first K/V tile
    {
        const __nv_bfloat16* Qg = Qc + ((size_t)hb * SEQ + q0) * 128;
#pragma unroll
        for (int i = 0; i < 8; i++) {
            int idx = tid + i * 256;
            int r = idx >> 4, ch = idx & 15;
            cp16(smb + AQ_OFF + r * 272 + ch * 16, Qg + (size_t)r * 128 + ch * 8);
        }
        const __nv_bfloat16* Kg = Kc + ((size_t)hb * SEQ) * 128;
        const __nv_bfloat16* Vg = Vt + ((size_t)hb * 64 * 32) * 128;
#pragma unroll
        for (int i = 0; i < 4; i++) {
            int idx = tid + i * 256;
            int r = idx >> 4, ch = idx & 15;
            cp16(smb + AK_OFF + r * 272 + ch * 16, Kg + (size_t)r * 128 + ch * 8);
            cp16(smb + AV_OFF + r * 272 + ch * 16, Vg + (size_t)r * 32 * 128 + ch * 8);
        }
        CP_COMMIT();
    }

    float o_acc[8][4];
#pragma unroll
    for (int nt = 0; nt < 8; nt++)
#pragma unroll
        for (int r = 0; r < 4; r++) o_acc[nt][r] = 0.f;
    float m0 = -1e30f, m1 = -1e30f, l0 = 0.f, l1 = 0.f;

    const int qrow = wid * 16;
    int buf = 0;

    for (int kt = 0; kt < SEQ / 64; kt++) {
        if (kt + 1 < SEQ / 64) {
            const __nv_bfloat16* Kg = Kc + ((size_t)hb * SEQ + (kt + 1) * 64) * 128;
            const __nv_bfloat16* Vg = Vt + ((size_t)hb * 64 * 32 + (kt + 1)) * 128;
            const uint32_t kb_ = smb + AK_OFF + (buf ^ 1) * 17408;
            const uint32_t vb_ = smb + AV_OFF + (buf ^ 1) * 17408;
#pragma unroll
            for (int i = 0; i < 4; i++) {
                int idx = tid + i * 256;
                int r = idx >> 4, ch = idx & 15;
                cp16(kb_ + r * 272 + ch * 16, Kg + (size_t)r * 128 + ch * 8);
                cp16(vb_ + r * 272 + ch * 16, Vg + (size_t)r * 32 * 128 + ch * 8);
            }
            CP_COMMIT();
            CP_WAIT1();
        } else {
            CP_WAIT0();
        }
        __syncthreads();

        const uint32_t* Qs = (const uint32_t*)(smc + AQ_OFF);
        const uint32_t* Ks = (const uint32_t*)(smc + AK_OFF + buf * 17408);
        const uint32_t* Vs = (const uint32_t*)(smc + AV_OFF + buf * 17408);

        // ---- S = Q K^T  (3-term: Qhi.Khi + Qlo.Khi + Qhi.Klo), K-chain = 12
        float s[8][4];
#pragma unroll
        for (int nt = 0; nt < 8; nt++)
#pragma unroll
            for (int r = 0; r < 4; r++) s[nt][r] = 0.f;

        const int AKS[12] = {0,1,2,3, 4,5,6,7, 0,1,2,3};
        const int BKS[12] = {0,1,2,3, 0,1,2,3, 4,5,6,7};
#pragma unroll
        for (int ks = 0; ks < 12; ks++) {
            const int ka = AKS[ks], kb = BKS[ks];
            uint32_t a[4];
            a[0] = Qs[(qrow + g)     * 68 + ka * 8 + tg];
            a[1] = Qs[(qrow + g + 8) * 68 + ka * 8 + tg];
            a[2] = Qs[(qrow + g)     * 68 + ka * 8 + 4 + tg];
            a[3] = Qs[(qrow + g + 8) * 68 + ka * 8 + 4 + tg];
#pragma unroll
            for (int nt = 0; nt < 8; nt++) {
                uint32_t bb[2];
                bb[0] = Ks[(nt * 8 + g) * 68 + kb * 8 + tg];
                bb[1] = Ks[(nt * 8 + g) * 68 + kb * 8 + 4 + tg];
                mma16816(s[nt], a, bb);
            }
        }

        // ---- scale + mask
        const size_t mrow0 = ((size_t)b * SEQ + q0 + qrow + g) * SEQ + kt * 64;
        const size_t mrow1 = mrow0 + 8 * SEQ;
#pragma unroll
        for (int nt = 0; nt < 8; nt++) {
            uchar2 mk0 = *(const uchar2*)(mask + mrow0 + nt * 8 + 2 * tg);
            uchar2 mk1 = *(const uchar2*)(mask + mrow1 + nt * 8 + 2 * tg);
            s[nt][0] = mk0.x ? -1e30f : s[nt][0] * 0.125f;
            s[nt][1] = mk0.y ? -1e30f : s[nt][1] * 0.125f;
            s[nt][2] = mk1.x ? -1e30f : s[nt][2] * 0.125f;
            s[nt][3] = mk1.y ? -1e30f : s[nt][3] * 0.125f;
        }

        // ---- online softmax (rows g and g+8; stats shared across tg quad)
        float mt0 = -1e30f, mt1 = -1e30f;
#pragma unroll
        for (int nt = 0; nt < 8; nt++) {
            mt0 = fmaxf(mt0, fmaxf(s[nt][0], s[nt][1]));
            mt1 = fmaxf(mt1, fmaxf(s[nt][2], s[nt][3]));
        }
        mt0 = fmaxf(mt0, __shfl_xor_sync(0xffffffffu, mt0, 1));
        mt0 = fmaxf(mt0, __shfl_xor_sync(0xffffffffu, mt0, 2));
        mt1 = fmaxf(mt1, __shfl_xor_sync(0xffffffffu, mt1, 1));
        mt1 = fmaxf(mt1, __shfl_xor_sync(0xffffffffu, mt1, 2));
        const float mn0 = fmaxf(m0, mt0), mn1 = fmaxf(m1, mt1);
        const float f0 = __expf(m0 - mn0), f1 = __expf(m1 - mn1);

        float ls0 = 0.f, ls1 = 0.f;
#pragma unroll
        for (int nt = 0; nt < 8; nt++) {
            s[nt][0] = __expf(s[nt][0] - mn0);
            s[nt][1] = __expf(s[nt][1] - mn0);
            s[nt][2] = __expf(s[nt][2] - mn1);
            s[nt][3] = __expf(s[nt][3] - mn1);
            ls0 += s[nt][0] + s[nt][1];
            ls1 += s[nt][2] + s[nt][3];
        }
        ls0 += __shfl_xor_sync(0xffffffffu, ls0, 1);
        ls0 += __shfl_xor_sync(0xffffffffu, ls0, 2);
        ls1 += __shfl_xor_sync(0xffffffffu, ls1, 1);
        ls1 += __shfl_xor_sync(0xffffffffu, ls1, 2);
        l0 = l0 * f0 + ls0; l1 = l1 * f1 + ls1;
        m0 = mn0; m1 = mn1;

#pragma unroll
        for (int nt = 0; nt < 8; nt++) {
            o_acc[nt][0] *= f0; o_acc[nt][1] *= f0;
            o_acc[nt][2] *= f1; o_acc[nt][3] *= f1;
        }

        // ---- P hi/lo fragments (in registers; S frag layout == A frag layout)
        uint32_t phi[4][4], plo[4][4];
#pragma unroll
        for (int ks = 0; ks < 4; ks++) {
            pack_hilo(s[2*ks][0],   s[2*ks][1],   phi[ks][0], plo[ks][0]);
            pack_hilo(s[2*ks][2],   s[2*ks][3],   phi[ks][1], plo[ks][1]);
            pack_hilo(s[2*ks+1][0], s[2*ks+1][1], phi[ks][2], plo[ks][2]);
            pack_hilo(s[2*ks+1][2], s[2*ks+1][3], phi[ks][3], plo[ks][3]);
        }

        // ---- O += P V  (Phi.Vhi + Plo.Vhi + Phi.Vlo), chain = 12
#pragma unroll
        for (int st = 0; st < 12; st++) {
            const uint32_t* af = (st < 4) ? phi[st] : (st < 8 ? plo[st - 4] : phi[st - 8]);
            const int kb = (st < 4) ? st : (st < 8 ? st - 4 : st - 4);
#pragma unroll
            for (int nt = 0; nt < 8; nt++) {
                uint32_t bb[2];
                bb[0] = Vs[(nt * 8 + g) * 68 + kb * 8 + tg];
                bb[1] = Vs[(nt * 8 + g) * 68 + kb * 8 + 4 + tg];
                mma16816(o_acc[nt], af, bb);
            }
        }
        __syncthreads();
        buf ^= 1;
    }

    // ---- epilogue: normalize, split hi/lo, write into acat [hi|lo|hi]
    const float inv0 = 1.f / l0, inv1 = 1.f / l1;
    const int row0 = b * SEQ + q0 + qrow + g;
    const int row1 = row0 + 8;
    __nv_bfloat16* p0 = acat + (size_t)row0 * KCAT;
    __nv_bfloat16* p1 = acat + (size_t)row1 * KCAT;
#pragma unroll
    for (int nt = 0; nt < 8; nt++) {
        const int d = h * 64 + nt * 8 + 2 * tg;
        uint32_t h0, lo0, h1, lo1;
        pack_hilo(o_acc[nt][0] * inv0, o_acc[nt][1] * inv0, h0, lo0);
        pack_hilo(o_acc[nt][2] * inv1, o_acc[nt][3] * inv1, h1, lo1);
        *(uint32_t*)(p0 + d)        = h0;
        *(uint32_t*)(p0 + 1024 + d) = lo0;
        *(uint32_t*)(p0 + 2048 + d) = h0;
        *(uint32_t*)(p1 + d)        = h1;
        *(uint32_t*)(p1 + 1024 + d) = lo1;
        *(uint32_t*)(p1 + 2048 + d) = h1;
    }
}

// ======================= LayerNorm (torch semantics) =======================
__global__ void __launch_bounds__(256) ln_kernel(
    const float* __restrict__ y, const float* __restrict__ gamma,
    const float* __restrict__ beta, float* __restrict__ out)
{
    __shared__ float sh_s[8], sh_ss[8];
    const int row = blockIdx.x;
    const float* x = y + (size_t)row * DMODEL;

    float s = 0.f, ss = 0.f;
    for (int i = threadIdx.x; i < DMODEL; i += 256) {
        float v = x[i]; s += v; ss += v * v;
    }
#pragma unroll
    for (int o = 16; o > 0; o >>= 1) {
        s  += __shfl_xor_sync(0xffffffffu, s,  o);
        ss += __shfl_xor_sync(0xffffffffu, ss, o);
    }
    int warp = threadIdx.x >> 5, lane = threadIdx.x & 31;
    if (lane == 0) { sh_s[warp] = s; sh_ss[warp] = ss; }
    __syncthreads();
    if (threadIdx.x < 32) {
        s  = (lane < 8) ? sh_s[lane]  : 0.f;
        ss = (lane < 8) ? sh_ss[lane] : 0.f;
#pragma unroll
        for (int o = 4; o > 0; o >>= 1) {
            s  += __shfl_xor_sync(0xffffffffu, s,  o);
            ss += __shfl_xor_sync(0xffffffffu, ss, o);
        }
        if (lane == 0) { sh_s[0] = s; sh_ss[0] = ss; }
    }
    __syncthreads();
    float mean = sh_s[0] * (1.f / DMODEL);
    float var  = (sh_ss[0] - (float)DMODEL * mean * mean) * (1.f / (DMODEL - 1));
    var = fmaxf(var, 0.f);
    float inv = 1.f / (sqrtf(var) + 1e-3f);
    for (int i = threadIdx.x; i < DMODEL; i += 256)
        out[(size_t)row * DMODEL + i] = (x[i] - mean) * inv * gamma[i] + beta[i];
}

// ===========================================================================
extern "C" void kernel_launch(void* const* d_in, const int* in_sizes, int n_in,
                              void* d_out, int out_size)
{
    const float* v     = (const float*)d_in[0];
    const float* k     = (const float*)d_in[1];
    const float* q     = (const float*)d_in[2];
    const void*  mask  = (const void*)d_in[3];
    const float* w_q   = (const float*)d_in[4];
    const float* w_k   = (const float*)d_in[5];
    const float* w_v   = (const float*)d_in[6];
    const float* w_o   = (const float*)d_in[7];
    const float* b_o   = (const float*)d_in[8];
    const float* gamma = (const float*)d_in[9];
    const float* beta  = (const float*)d_in[10];
    float*       out   = (float*)d_out;

    float *qh, *kh, *vh, *y;
    unsigned char* mask8;
    __nv_bfloat16 *acat, *wcat, *qc, *kc, *vt;
    cudaGetSymbolAddress((void**)&qh,    g_qh);
    cudaGetSymbolAddress((void**)&kh,    g_kh);
    cudaGetSymbolAddress((void**)&vh,    g_vh);
    cudaGetSymbolAddress((void**)&y,     g_y);
    cudaGetSymbolAddress((void**)&mask8, g_mask8);
    cudaGetSymbolAddress((void**)&acat,  g_acat);
    cudaGetSymbolAddress((void**)&wcat,  g_wcat);
    cudaGetSymbolAddress((void**)&qc,    g_qc);
    cudaGetSymbolAddress((void**)&kc,    g_kc);
    cudaGetSymbolAddress((void**)&vt,    g_vt);

    cudaFuncSetAttribute(gemm_mma<false>, cudaFuncAttributeMaxDynamicSharedMemorySize, GEMM_SMEM);
    cudaFuncSetAttribute(gemm_mma<true>,  cudaFuncAttributeMaxDynamicSharedMemorySize, GEMM_SMEM);
    cudaFuncSetAttribute(attn_mma,        cudaFuncAttributeMaxDynamicSharedMemorySize, ATT_SMEM);

    // Mask -> uint8
    probe_mask<<<1, 1024>>>((const unsigned int*)mask);
    convert_mask<<<(int)((MASKN + 255) / 256), 256>>>(mask);

    const int ACT_N = MROWS * DMODEL;
    const int WH_N  = NHEAD * DMODEL * DHEAD;
    const int WF_N  = DMODEL * DMODEL;
    dim3 ggrid(DMODEL / 128, MROWS / 128);       // (8, 32)

    // Projections
    split_w_headed<<<(WH_N + 255) / 256, 256>>>(w_q, wcat);
    split_act<<<(ACT_N + 255) / 256, 256>>>(q, acat);
    gemm_mma<false><<<ggrid, 256, GEMM_SMEM>>>(acat, wcat, qh, nullptr, nullptr);

    split_w_headed<<<(WH_N + 255) / 256, 256>>>(w_k, wcat);
    split_act<<<(ACT_N + 255) / 256, 256>>>(k, acat);
    gemm_mma<false><<<ggrid, 256, GEMM_SMEM>>>(acat, wcat, kh, nullptr, nullptr);

    split_w_headed<<<(WH_N + 255) / 256, 256>>>(w_v, wcat);
    split_act<<<(ACT_N + 255) / 256, 256>>>(v, acat);
    gemm_mma<false><<<ggrid, 256, GEMM_SMEM>>>(acat, wcat, vh, nullptr, nullptr);

    // Pack attention operands
    conv_qk<<<(ACT_N + 255) / 256, 256>>>(qh, qc);
    conv_qk<<<(ACT_N + 255) / 256, 256>>>(kh, kc);
    dim3 vgrid(SEQ / 64, NHEAD * BATCH);
    conv_v<<<vgrid, 256>>>(vh, vt);

    // Flash attention (writes acat directly)
    dim3 agrid(SEQ / 128, NHEAD * BATCH);
    attn_mma<<<agrid, 256, ATT_SMEM>>>(qc, kc, vt, mask8, acat);

    // Output projection + bias + residual(k)
    split_w_flat<<<(WF_N + 255) / 256, 256>>>(w_o, wcat);
    gemm_mma<true><<<ggrid, 256, GEMM_SMEM>>>(acat, wcat, y, b_o, k);

    // LayerNorm
    ln_kernel<<<MROWS, 256>>>(y, gamma, beta, out);
}

// round 7
// speedup vs baseline: 2.6104x; 1.1688x over previous
#include <cuda_runtime.h>
#include <cuda_bf16.h>
#include <math.h>
#include <cstdint>

#define NHEAD  16
#define DMODEL 1024
#define DHEAD  64
#define BATCH  2
#define SEQ    2048
#define MROWS  (BATCH*SEQ)   // 4096
#define MASKN  ((size_t)BATCH*SEQ*SEQ)
#define KCAT   3072          // [hi | lo | hi] concat along K (projection GEMMs)

// Scratch (device globals; no allocation in kernel_launch)
__device__ float g_vh [MROWS*DMODEL];
__device__ float g_y  [MROWS*DMODEL];
__device__ unsigned char g_mask8[MASKN];
__device__ int g_fmt;
__device__ __nv_bfloat16 g_acat[(size_t)MROWS*KCAT];   // 25.2MB
__device__ __nv_bfloat16 g_wcat[(size_t)DMODEL*KCAT];  // 6.3MB
// attention operands: per-head [hi|lo] layouts
__device__ __nv_bfloat16 g_qc[(size_t)32*SEQ*128];     // [hb][q][hi64|lo64]
__device__ __nv_bfloat16 g_kc[(size_t)32*SEQ*128];     // [hb][k][hi64|lo64]
__device__ __nv_bfloat16 g_vt[(size_t)32*64*32*128];   // [hb][e][kt][hi64|lo64]

// ======================= mma.sync + cp.async helpers =======================
__device__ __forceinline__ void mma16816(float* c, const uint32_t* a, const uint32_t* b) {
    asm volatile("mma.sync.aligned.m16n8k16.row.col.f32.bf16.bf16.f32 "
        "{%0,%1,%2,%3}, {%4,%5,%6,%7}, {%8,%9}, {%0,%1,%2,%3};"
        : "+f"(c[0]), "+f"(c[1]), "+f"(c[2]), "+f"(c[3])
        : "r"(a[0]), "r"(a[1]), "r"(a[2]), "r"(a[3]), "r"(b[0]), "r"(b[1]));
}
__device__ __forceinline__ void ldsm4(uint32_t* r, uint32_t addr) {
    asm volatile("ldmatrix.sync.aligned.m8n8.x4.shared.b16 {%0,%1,%2,%3}, [%4];"
        : "=r"(r[0]), "=r"(r[1]), "=r"(r[2]), "=r"(r[3]) : "r"(addr));
}
__device__ __forceinline__ uint32_t smem_u32(const void* p) {
    uint32_t a;
    asm("{ .reg .u64 t; cvta.to.shared.u64 t, %1; cvt.u32.u64 %0, t; }" : "=r"(a) : "l"(p));
    return a;
}
__device__ __forceinline__ void cp16(uint32_t dst, const void* src) {
    asm volatile("cp.async.cg.shared.global [%0], [%1], 16;" :: "r"(dst), "l"(src));
}
#define CP_COMMIT() asm volatile("cp.async.commit_group;" ::: "memory")
#define CP_WAIT1()  asm volatile("cp.async.wait_group 1;" ::: "memory")
#define CP_WAIT0()  asm volatile("cp.async.wait_group 0;" ::: "memory")

__device__ __forceinline__ void pack_hilo(float x, float y, uint32_t& hi, uint32_t& lo) {
    __nv_bfloat16 hx = __float2bfloat16(x), hy = __float2bfloat16(y);
    __nv_bfloat16 lx = __float2bfloat16(x - __bfloat162float(hx));
    __nv_bfloat16 ly = __float2bfloat16(y - __bfloat162float(hy));
    __nv_bfloat162 hp = __halves2bfloat162(hx, hy);
    __nv_bfloat162 lp = __halves2bfloat162(lx, ly);
    hi = *(uint32_t*)&hp; lo = *(uint32_t*)&lp;
}

// ======================= mask dtype probe + convert ========================
__global__ void probe_mask(const unsigned int* __restrict__ m) {
    __shared__ int s_i32, s_f32;
    if (threadIdx.x == 0) { s_i32 = 1; s_f32 = 1; }
    __syncthreads();
    int bad_i = 0, bad_f = 0;
    for (int i = threadIdx.x; i < (1 << 20); i += blockDim.x) {
        unsigned int w = m[i];
        if (w != 0u && w != 1u) bad_i = 1;
        if (w != 0u && w != 0x3F800000u) bad_f = 1;
    }
    if (bad_i) atomicAnd(&s_i32, 0);
    if (bad_f) atomicAnd(&s_f32, 0);
    __syncthreads();
    if (threadIdx.x == 0) g_fmt = s_i32 ? 1 : (s_f32 ? 2 : 0);
}
__global__ void convert_mask(const void* __restrict__ src) {
    size_t i = (size_t)blockIdx.x * blockDim.x + threadIdx.x;
    if (i >= MASKN) return;
    int fmt = g_fmt;
    unsigned char v;
    if (fmt == 1)      v = (unsigned char)(((const int*)src)[i] != 0);
    else if (fmt == 2) v = (unsigned char)(((const float*)src)[i] != 0.f);
    else               v = ((const unsigned char*)src)[i];
    g_mask8[i] = v;
}

// ======================= bf16 hi/lo split conversions ======================
__global__ void split_act(const float* __restrict__ in, __nv_bfloat16* __restrict__ out) {
    size_t i = (size_t)blockIdx.x * blockDim.x + threadIdx.x;
    if (i >= (size_t)MROWS * DMODEL) return;
    size_t r = i / DMODEL, d = i % DMODEL;
    float v = in[i];
    __nv_bfloat16 hi = __float2bfloat16(v);
    __nv_bfloat16 lo = __float2bfloat16(v - __bfloat162float(hi));
    __nv_bfloat16* o = out + r * KCAT;
    o[d] = hi; o[1024 + d] = lo; o[2048 + d] = hi;
}
__global__ void split_w_headed(const float* __restrict__ w, __nv_bfloat16* __restrict__ out) {
    size_t i = (size_t)blockIdx.x * blockDim.x + threadIdx.x;
    if (i >= (size_t)NHEAD * DMODEL * DHEAD) return;
    int h = (int)(i / (DMODEL * DHEAD));
    int rem = (int)(i % (DMODEL * DHEAD));
    int d = rem / DHEAD, e = rem % DHEAD;
    int n = h * DHEAD + e;
    float v = w[i];
    __nv_bfloat16 hi = __float2bfloat16(v);
    __nv_bfloat16 lo = __float2bfloat16(v - __bfloat162float(hi));
    __nv_bfloat16* o = out + (size_t)n * KCAT;
    o[d] = hi; o[1024 + d] = hi; o[2048 + d] = lo;
}
__global__ void split_w_flat(const float* __restrict__ w, __nv_bfloat16* __restrict__ out) {
    size_t i = (size_t)blockIdx.x * blockDim.x + threadIdx.x;
    if (i >= (size_t)DMODEL * DMODEL) return;
    int d = (int)(i / DMODEL), n = (int)(i % DMODEL);
    float v = w[i];
    __nv_bfloat16 hi = __float2bfloat16(v);
    __nv_bfloat16 lo = __float2bfloat16(v - __bfloat162float(hi));
    __nv_bfloat16* o = out + (size_t)n * KCAT;
    o[d] = hi; o[1024 + d] = hi; o[2048 + d] = lo;
}

// vh fp32 -> transposed [hb][e][kt][hi64|lo64]
__global__ void conv_v(const float* __restrict__ vh, __nv_bfloat16* __restrict__ vt) {
    __shared__ float t[64][65];
    const int kt = blockIdx.x, hb = blockIdx.y;
    const int h = hb >> 1, b = hb & 1;
    const int tid = threadIdx.x;
#pragma unroll
    for (int i = 0; i < 16; i++) {
        int idx = tid + i * 256;
        int kr = idx >> 6, e = idx & 63;
        t[kr][e] = vh[((size_t)b * SEQ + kt * 64 + kr) * DMODEL + h * 64 + e];
    }
    __syncthreads();
#pragma unroll
    for (int i = 0; i < 16; i++) {
        int idx = tid + i * 256;
        int e = idx >> 6, kr = idx & 63;
        float v = t[kr][e];
        __nv_bfloat16 hi = __float2bfloat16(v);
        __nv_bfloat16 lo = __float2bfloat16(v - __bfloat162float(hi));
        __nv_bfloat16* o = vt + (((size_t)hb * 64 + e) * 32 + kt) * 128;
        o[kr] = hi; o[64 + kr] = lo;
    }
}

// ======================= mma.sync GEMM: 128M x 128N, BK=64 ================
// MODE 0: fp32 C. MODE 1: fp32 C + bias + residual. MODE 2: packed qc/kc out.
#define GBK     64
#define GNITER  (KCAT / GBK)                 // 48
#define TILE_B  (128 * 72 * 2)               // 18432 bytes per A or B tile
#define BUF_B   (2 * TILE_B)
#define GEMM_SMEM (2 * BUF_B)                // 73728

template<int MODE>
__global__ void __launch_bounds__(256) gemm_mma(
    const __nv_bfloat16* __restrict__ A, const __nv_bfloat16* __restrict__ Bt,
    float* __restrict__ Cf, __nv_bfloat16* __restrict__ Cp,
    const float* __restrict__ bias, const float* __restrict__ residual)
{
    extern __shared__ char smc[];
    const uint32_t smb = smem_u32(smc);
    const int tid = threadIdx.x;
    const int wid = tid >> 5, lid = tid & 31;
    const int wm = wid >> 2, wn = wid & 3;
    const int g = lid >> 2, tg = lid & 3;
    const int m0 = blockIdx.y * 128, n0 = blockIdx.x * 128;

    const __nv_bfloat16* Ag0 = A  + (size_t)m0 * KCAT;
    const __nv_bfloat16* Bg0 = Bt + (size_t)n0 * KCAT;

    // ldmatrix lane-relative byte offsets (row stride 144B)
    const int lrow = lid & 7, quad = lid >> 3;
    const uint32_t aoff = (uint32_t)(((quad & 1) * 8 + lrow) * 144 + (quad >> 1) * 16)
                        + (uint32_t)(wm * 64) * 144;
    const uint32_t boff = (uint32_t)(((quad >> 1) * 8 + lrow) * 144 + (quad & 1) * 16)
                        + (uint32_t)(wn * 32) * 144 + TILE_B;

    float acc[4][4][4];
#pragma unroll
    for (int mt = 0; mt < 4; mt++)
#pragma unroll
        for (int nt = 0; nt < 4; nt++)
#pragma unroll
            for (int r = 0; r < 4; r++) acc[mt][nt][r] = 0.f;

    {
#pragma unroll
        for (int i = 0; i < 4; i++) {
            int idx = tid + i * 256;
            int r = idx >> 3, ch = idx & 7;
            cp16(smb + r * 144 + ch * 16,          Ag0 + (size_t)r * KCAT + ch * 8);
            cp16(smb + TILE_B + r * 144 + ch * 16, Bg0 + (size_t)r * KCAT + ch * 8);
        }
        CP_COMMIT();
    }

    int buf = 0;
    for (int it = 0; it < GNITER; it++) {
        if (it + 1 < GNITER) {
            const __nv_bfloat16* Ag = Ag0 + (it + 1) * GBK;
            const __nv_bfloat16* Bg = Bg0 + (it + 1) * GBK;
            const uint32_t nb = smb + (buf ^ 1) * BUF_B;
#pragma unroll
            for (int i = 0; i < 4; i++) {
                int idx = tid + i * 256;
                int r = idx >> 3, ch = idx & 7;
                cp16(nb + r * 144 + ch * 16,          Ag + (size_t)r * KCAT + ch * 8);
                cp16(nb + TILE_B + r * 144 + ch * 16, Bg + (size_t)r * KCAT + ch * 8);
            }
            CP_COMMIT();
            CP_WAIT1();
        } else {
            CP_WAIT0();
        }
        __syncthreads();

        const uint32_t bb = smb + buf * BUF_B;
#pragma unroll
        for (int ks = 0; ks < 4; ks++) {
            uint32_t a[4][4], bq[2][4];
#pragma unroll
            for (int mt = 0; mt < 4; mt++)
                ldsm4(a[mt], bb + aoff + (uint32_t)(mt * 16) * 144 + ks * 32);
#pragma unroll
            for (int p = 0; p < 2; p++)
                ldsm4(bq[p], bb + boff + (uint32_t)(p * 16) * 144 + ks * 32);
#pragma unroll
            for (int mt = 0; mt < 4; mt++)
#pragma unroll
                for (int p = 0; p < 2; p++) {
                    mma16816(acc[mt][2 * p],     a[mt], &bq[p][0]);
                    mma16816(acc[mt][2 * p + 1], a[mt], &bq[p][2]);
                }
        }
        __syncthreads();
        buf ^= 1;
    }

#pragma unroll
    for (int mt = 0; mt < 4; mt++) {
        int m = m0 + wm * 64 + mt * 16 + g;
#pragma unroll
        for (int nt = 0; nt < 4; nt++) {
            int n = n0 + wn * 32 + nt * 8 + 2 * tg;
            if (MODE == 2) {
                // packed [hb][row][hi64|lo64] output (qc / kc)
                int h = n >> 6, e = n & 63;
#pragma unroll
                for (int half = 0; half < 2; half++) {
                    int mm = m + half * 8;
                    int b = mm >> 11, qq = mm & 2047;
                    int hb = (h << 1) + b;
                    uint32_t hi, lo;
                    pack_hilo(acc[mt][nt][2 * half], acc[mt][nt][2 * half + 1], hi, lo);
                    __nv_bfloat16* o = Cp + ((size_t)hb * SEQ + qq) * 128;
                    *(uint32_t*)(o + e)      = hi;
                    *(uint32_t*)(o + 64 + e) = lo;
                }
            } else {
                float2 v0 = make_float2(acc[mt][nt][0], acc[mt][nt][1]);
                float2 v1 = make_float2(acc[mt][nt][2], acc[mt][nt][3]);
                if (MODE == 1) {
                    float2 bv = *(const float2*)(bias + n);
                    float2 r0 = *(const float2*)(residual + (size_t)m * DMODEL + n);
                    float2 r1 = *(const float2*)(residual + (size_t)(m + 8) * DMODEL + n);
                    v0.x += bv.x + r0.x; v0.y += bv.y + r0.y;
                    v1.x += bv.x + r1.x; v1.y += bv.y + r1.y;
                }
                *(float2*)(Cf + (size_t)m * DMODEL + n)       = v0;
                *(float2*)(Cf + (size_t)(m + 8) * DMODEL + n) = v1;
            }
        }
    }
}

// ======================= flash attention via mma.sync ======================
#define AQ_OFF  0
#define AK_OFF  34816
#define AV_OFF  (34816 + 2*17408)
#define ATT_SMEM (34816 + 4*17408)   // 104448

__global__ void __launch_bounds__(256) attn_mma(
    const __nv_bfloat16* __restrict__ Qc, const __nv_bfloat16* __restrict__ Kc,
    const __nv_bfloat16* __restrict__ Vt, const unsigned char* __restrict__ mask,
    __nv_bfloat16* __restrict__ acat)
{
    extern __shared__ char smc[];
    const uint32_t smb = smem_u32(smc);
    const int tid = threadIdx.x;
    const int wid = tid >> 5, lid = tid & 31;
    const int g = lid >> 2, tg = lid & 3;
    const int qb = blockIdx.x, hb = blockIdx.y;
    const int h = hb >> 1, b = hb & 1;
    const int q0 = qb * 128;
    const int qrow = wid * 16;

    // ldmatrix lane-relative byte offsets (row stride 272B)
    const int lrow = lid & 7, quad = lid >> 3;
    const uint32_t aoff = (uint32_t)(((quad & 1) * 8 + lrow) * 272 + (quad >> 1) * 16)
                        + (uint32_t)qrow * 272;
    const uint32_t boff = (uint32_t)(((quad >> 1) * 8 + lrow) * 272 + (quad & 1) * 16);

    // ---- load Q tile (persistent) + first K/V tile
    {
        const __nv_bfloat16* Qg = Qc + ((size_t)hb * SEQ + q0) * 128;
#pragma unroll
        for (int i = 0; i < 8; i++) {
            int idx = tid + i * 256;
            int r = idx >> 4, ch = idx & 15;
            cp16(smb + AQ_OFF + r * 272 + ch * 16, Qg + (size_t)r * 128 + ch * 8);
        }
        const __nv_bfloat16* Kg = Kc + ((size_t)hb * SEQ) * 128;
        const __nv_bfloat16* Vg = Vt + ((size_t)hb * 64 * 32) * 128;
#pragma unroll
        for (int i = 0; i < 4; i++) {
            int idx = tid + i * 256;
            int r = idx >> 4, ch = idx & 15;
            cp16(smb + AK_OFF + r * 272 + ch * 16, Kg + (size_t)r * 128 + ch * 8);
            cp16(smb + AV_OFF + r * 272 + ch * 16, Vg + (size_t)r * 32 * 128 + ch * 8);
        }
        CP_COMMIT();
    }

    float o_acc[8][4];
#pragma unroll
    for (int nt = 0; nt < 8; nt++)
#pragma unroll
        for (int r = 0; r < 4; r++) o_acc[nt][r] = 0.f;
    float m0 = -1e30f, m1 = -1e30f, l0 = 0.f, l1 = 0.f;

    int buf = 0;

    for (int kt = 0; kt < SEQ / 64; kt++) {
        if (kt + 1 < SEQ / 64) {
            const __nv_bfloat16* Kg = Kc + ((size_t)hb * SEQ + (kt + 1) * 64) * 128;
            const __nv_bfloat16* Vg = Vt + ((size_t)hb * 64 * 32 + (kt + 1)) * 128;
            const uint32_t kb_ = smb + AK_OFF + (buf ^ 1) * 17408;
            const uint32_t vb_ = smb + AV_OFF + (buf ^ 1) * 17408;
#pragma unroll
            for (int i = 0; i < 4; i++) {
                int idx = tid + i * 256;
                int r = idx >> 4, ch = idx & 15;
                cp16(kb_ + r * 272 + ch * 16, Kg + (size_t)r * 128 + ch * 8);
                cp16(vb_ + r * 272 + ch * 16, Vg + (size_t)r * 32 * 128 + ch * 8);
            }
            CP_COMMIT();
            CP_WAIT1();
        } else {
            CP_WAIT0();
        }
        __syncthreads();

        const uint32_t Qb = smb + AQ_OFF;
        const uint32_t Kb = smb + AK_OFF + buf * 17408;
        const uint32_t Vb = smb + AV_OFF + buf * 17408;

        // ---- S = Q K^T: Qhi.Khi + Qlo.Khi (kb 0..3), Qhi.Klo (kb 4..7)
        float s[8][4];
#pragma unroll
        for (int nt = 0; nt < 8; nt++)
#pragma unroll
            for (int r = 0; r < 4; r++) s[nt][r] = 0.f;

#pragma unroll
        for (int kb = 0; kb < 4; kb++) {
            uint32_t bq[4][4];
#pragma unroll
            for (int p = 0; p < 4; p++)
                ldsm4(bq[p], Kb + boff + (uint32_t)(p * 16) * 272 + kb * 32);
            uint32_t a[4];
            ldsm4(a, Qb + aoff + kb * 32);          // Qhi
#pragma unroll
            for (int p = 0; p < 4; p++) {
                mma16816(s[2 * p],     a, &bq[p][0]);
                mma16816(s[2 * p + 1], a, &bq[p][2]);
            }
            ldsm4(a, Qb + aoff + (kb + 4) * 32);    // Qlo
#pragma unroll
            for (int p = 0; p < 4; p++) {
                mma16816(s[2 * p],     a, &bq[p][0]);
                mma16816(s[2 * p + 1], a, &bq[p][2]);
            }
        }
#pragma unroll
        for (int kb = 4; kb < 8; kb++) {
            uint32_t bq[4][4];
#pragma unroll
            for (int p = 0; p < 4; p++)
                ldsm4(bq[p], Kb + boff + (uint32_t)(p * 16) * 272 + kb * 32);
            uint32_t a[4];
            ldsm4(a, Qb + aoff + (kb - 4) * 32);    // Qhi
#pragma unroll
            for (int p = 0; p < 4; p++) {
                mma16816(s[2 * p],     a, &bq[p][0]);
                mma16816(s[2 * p + 1], a, &bq[p][2]);
            }
        }

        // ---- scale + mask
        const size_t mrow0 = ((size_t)b * SEQ + q0 + qrow + g) * SEQ + kt * 64;
        const size_t mrow1 = mrow0 + 8 * SEQ;
#pragma unroll
        for (int nt = 0; nt < 8; nt++) {
            uchar2 mk0 = *(const uchar2*)(mask + mrow0 + nt * 8 + 2 * tg);
            uchar2 mk1 = *(const uchar2*)(mask + mrow1 + nt * 8 + 2 * tg);
            s[nt][0] = mk0.x ? -1e30f : s[nt][0] * 0.125f;
            s[nt][1] = mk0.y ? -1e30f : s[nt][1] * 0.125f;
            s[nt][2] = mk1.x ? -1e30f : s[nt][2] * 0.125f;
            s[nt][3] = mk1.y ? -1e30f : s[nt][3] * 0.125f;
        }

        // ---- online softmax
        float mt0 = -1e30f, mt1 = -1e30f;
#pragma unroll
        for (int nt = 0; nt < 8; nt++) {
            mt0 = fmaxf(mt0, fmaxf(s[nt][0], s[nt][1]));
            mt1 = fmaxf(mt1, fmaxf(s[nt][2], s[nt][3]));
        }
        mt0 = fmaxf(mt0, __shfl_xor_sync(0xffffffffu, mt0, 1));
        mt0 = fmaxf(mt0, __shfl_xor_sync(0xffffffffu, mt0, 2));
        mt1 = fmaxf(mt1, __shfl_xor_sync(0xffffffffu, mt1, 1));
        mt1 = fmaxf(mt1, __shfl_xor_sync(0xffffffffu, mt1, 2));
        const float mn0 = fmaxf(m0, mt0), mn1 = fmaxf(m1, mt1);
        const float f0 = __expf(m0 - mn0), f1 = __expf(m1 - mn1);

        float ls0 = 0.f, ls1 = 0.f;
#pragma unroll
        for (int nt = 0; nt < 8; nt++) {
            s[nt][0] = __expf(s[nt][0] - mn0);
            s[nt][1] = __expf(s[nt][1] - mn0);
            s[nt][2] = __expf(s[nt][2] - mn1);
            s[nt][3] = __expf(s[nt][3] - mn1);
            ls0 += s[nt][0] + s[nt][1];
            ls1 += s[nt][2] + s[nt][3];
        }
        ls0 += __shfl_xor_sync(0xffffffffu, ls0, 1);
        ls0 += __shfl_xor_sync(0xffffffffu, ls0, 2);
        ls1 += __shfl_xor_sync(0xffffffffu, ls1, 1);
        ls1 += __shfl_xor_sync(0xffffffffu, ls1, 2);
        l0 = l0 * f0 + ls0; l1 = l1 * f1 + ls1;
        m0 = mn0; m1 = mn1;

#pragma unroll
        for (int nt = 0; nt < 8; nt++) {
            o_acc[nt][0] *= f0; o_acc[nt][1] *= f0;
            o_acc[nt][2] *= f1; o_acc[nt][3] *= f1;
        }

        // ---- P hi/lo fragments
        uint32_t phi[4][4], plo[4][4];
#pragma unroll
        for (int ks = 0; ks < 4; ks++) {
            pack_hilo(s[2*ks][0],   s[2*ks][1],   phi[ks][0], plo[ks][0]);
            pack_hilo(s[2*ks][2],   s[2*ks][3],   phi[ks][1], plo[ks][1]);
            pack_hilo(s[2*ks+1][0], s[2*ks+1][1], phi[ks][2], plo[ks][2]);
            pack_hilo(s[2*ks+1][2], s[2*ks+1][3], phi[ks][3], plo[ks][3]);
        }

        // ---- O += P V: Phi.Vhi + Plo.Vhi (kb 0..3), Phi.Vlo (kb 4..7)
#pragma unroll
        for (int kb = 0; kb < 4; kb++) {
            uint32_t bq[4][4];
#pragma unroll
            for (int p = 0; p < 4; p++)
                ldsm4(bq[p], Vb + boff + (uint32_t)(p * 16) * 272 + kb * 32);
#pragma unroll
            for (int p = 0; p < 4; p++) {
                mma16816(o_acc[2 * p],     phi[kb], &bq[p][0]);
                mma16816(o_acc[2 * p + 1], phi[kb], &bq[p][2]);
                mma16816(o_acc[2 * p],     plo[kb], &bq[p][0]);
                mma16816(o_acc[2 * p + 1], plo[kb], &bq[p][2]);
            }
        }
#pragma unroll
        for (int kb = 4; kb < 8; kb++) {
            uint32_t bq[4][4];
#pragma unroll
            for (int p = 0; p < 4; p++)
                ldsm4(bq[p], Vb + boff + (uint32_t)(p * 16) * 272 + kb * 32);
#pragma unroll
            for (int p = 0; p < 4; p++) {
                mma16816(o_acc[2 * p],     phi[kb - 4], &bq[p][0]);
                mma16816(o_acc[2 * p + 1], phi[kb - 4], &bq[p][2]);
            }
        }
        __syncthreads();
        buf ^= 1;
    }

    // ---- epilogue: normalize, split hi/lo, write into acat [hi|lo|hi]
    const float inv0 = 1.f / l0, inv1 = 1.f / l1;
    const int row0 = b * SEQ + q0 + qrow + g;
    const int row1 = row0 + 8;
    __nv_bfloat16* p0 = acat + (size_t)row0 * KCAT;
    __nv_bfloat16* p1 = acat + (size_t)row1 * KCAT;
#pragma unroll
    for (int nt = 0; nt < 8; nt++) {
        const int d = h * 64 + nt * 8 + 2 * tg;
        uint32_t h0, lo0, h1, lo1;
        pack_hilo(o_acc[nt][0] * inv0, o_acc[nt][1] * inv0, h0, lo0);
        pack_hilo(o_acc[nt][2] * inv1, o_acc[nt][3] * inv1, h1, lo1);
        *(uint32_t*)(p0 + d)        = h0;
        *(uint32_t*)(p0 + 1024 + d) = lo0;
        *(uint32_t*)(p0 + 2048 + d) = h0;
        *(uint32_t*)(p1 + d)        = h1;
        *(uint32_t*)(p1 + 1024 + d) = lo1;
        *(uint32_t*)(p1 + 2048 + d) = h1;
    }
}

// ======================= LayerNorm (torch semantics) =======================
__global__ void __launch_bounds__(256) ln_kernel(
    const float* __restrict__ y, const float* __restrict__ gamma,
    const float* __restrict__ beta, float* __restrict__ out)
{
    __shared__ float sh_s[8], sh_ss[8];
    const int row = blockIdx.x;
    const float* x = y + (size_t)row * DMODEL;

    float s = 0.f, ss = 0.f;
    for (int i = threadIdx.x; i < DMODEL; i += 256) {
        float v = x[i]; s += v; ss += v * v;
    }
#pragma unroll
    for (int o = 16; o > 0; o >>= 1) {
        s  += __shfl_xor_sync(0xffffffffu, s,  o);
        ss += __shfl_xor_sync(0xffffffffu, ss, o);
    }
    int warp = threadIdx.x >> 5, lane = threadIdx.x & 31;
    if (lane == 0) { sh_s[warp] = s; sh_ss[warp] = ss; }
    __syncthreads();
    if (threadIdx.x < 32) {
        s  = (lane < 8) ? sh_s[lane]  : 0.f;
        ss = (lane < 8) ? sh_ss[lane] : 0.f;
#pragma unroll
        for (int o = 4; o > 0; o >>= 1) {
            s  += __shfl_xor_sync(0xffffffffu, s,  o);
            ss += __shfl_xor_sync(0xffffffffu, ss, o);
        }
        if (lane == 0) { sh_s[0] = s; sh_ss[0] = ss; }
    }
    __syncthreads();
    float mean = sh_s[0] * (1.f / DMODEL);
    float var  = (sh_ss[0] - (float)DMODEL * mean * mean) * (1.f / (DMODEL - 1));
    var = fmaxf(var, 0.f);
    float inv = 1.f / (sqrtf(var) + 1e-3f);
    for (int i = threadIdx.x; i < DMODEL; i += 256)
        out[(size_t)row * DMODEL + i] = (x[i] - mean) * inv * gamma[i] + beta[i];
}

// ===========================================================================
extern "C" void kernel_launch(void* const* d_in, const int* in_sizes, int n_in,
                              void* d_out, int out_size)
{
    const float* v     = (const float*)d_in[0];
    const float* k     = (const float*)d_in[1];
    const float* q     = (const float*)d_in[2];
    const void*  mask  = (const void*)d_in[3];
    const float* w_q   = (const float*)d_in[4];
    const float* w_k   = (const float*)d_in[5];
    const float* w_v   = (const float*)d_in[6];
    const float* w_o   = (const float*)d_in[7];
    const float* b_o   = (const float*)d_in[8];
    const float* gamma = (const float*)d_in[9];
    const float* beta  = (const float*)d_in[10];
    float*       out   = (float*)d_out;

    float *vh, *y;
    unsigned char* mask8;
    __nv_bfloat16 *acat, *wcat, *qc, *kc, *vt;
    cudaGetSymbolAddress((void**)&vh,    g_vh);
    cudaGetSymbolAddress((void**)&y,     g_y);
    cudaGetSymbolAddress((void**)&mask8, g_mask8);
    cudaGetSymbolAddress((void**)&acat,  g_acat);
    cudaGetSymbolAddress((void**)&wcat,  g_wcat);
    cudaGetSymbolAddress((void**)&qc,    g_qc);
    cudaGetSymbolAddress((void**)&kc,    g_kc);
    cudaGetSymbolAddress((void**)&vt,    g_vt);

    cudaFuncSetAttribute(gemm_mma<0>, cudaFuncAttributeMaxDynamicSharedMemorySize, GEMM_SMEM);
    cudaFuncSetAttribute(gemm_mma<1>, cudaFuncAttributeMaxDynamicSharedMemorySize, GEMM_SMEM);
    cudaFuncSetAttribute(gemm_mma<2>, cudaFuncAttributeMaxDynamicSharedMemorySize, GEMM_SMEM);
    cudaFuncSetAttribute(attn_mma,    cudaFuncAttributeMaxDynamicSharedMemorySize, ATT_SMEM);

    // Mask -> uint8
    probe_mask<<<1, 1024>>>((const unsigned int*)mask);
    convert_mask<<<(int)((MASKN + 255) / 256), 256>>>(mask);

    const int ACT_N = MROWS * DMODEL;
    const int WH_N  = NHEAD * DMODEL * DHEAD;
    const int WF_N  = DMODEL * DMODEL;
    dim3 ggrid(DMODEL / 128, MROWS / 128);       // (8, 32)

    // Q projection -> packed qc
    split_w_headed<<<(WH_N + 255) / 256, 256>>>(w_q, wcat);
    split_act<<<(ACT_N + 255) / 256, 256>>>(q, acat);
    gemm_mma<2><<<ggrid, 256, GEMM_SMEM>>>(acat, wcat, nullptr, qc, nullptr, nullptr);

    // K projection -> packed kc
    split_w_headed<<<(WH_N + 255) / 256, 256>>>(w_k, wcat);
    split_act<<<(ACT_N + 255) / 256, 256>>>(k, acat);
    gemm_mma<2><<<ggrid, 256, GEMM_SMEM>>>(acat, wcat, nullptr, kc, nullptr, nullptr);

    // V projection -> fp32 vh, then transpose-pack
    split_w_headed<<<(WH_N + 255) / 256, 256>>>(w_v, wcat);
    split_act<<<(ACT_N + 255) / 256, 256>>>(v, acat);
    gemm_mma<0><<<ggrid, 256, GEMM_SMEM>>>(acat, wcat, vh, nullptr, nullptr, nullptr);
    dim3 vgrid(SEQ / 64, NHEAD * BATCH);
    conv_v<<<vgrid, 256>>>(vh, vt);

    // Flash attention (writes acat directly)
    dim3 agrid(SEQ / 128, NHEAD * BATCH);
    attn_mma<<<agrid, 256, ATT_SMEM>>>(qc, kc, vt, mask8, acat);

    // Output projection + bias + residual(k)
    split_w_flat<<<(WF_N + 255) / 256, 256>>>(w_o, wcat);
    gemm_mma<1><<<ggrid, 256, GEMM_SMEM>>>(acat, wcat, y, nullptr, b_o, k);

    // LayerNorm
    ln_kernel<<<MROWS, 256>>>(y, gamma, beta, out);
}

// round 8
// speedup vs baseline: 2.6861x; 1.0290x over previous
#include <cuda_runtime.h>
#include <cuda_bf16.h>
#include <math.h>
#include <cstdint>

#define NHEAD  16
#define DMODEL 1024
#define DHEAD  64
#define BATCH  2
#define SEQ    2048
#define MROWS  (BATCH*SEQ)   // 4096
#define MASKN  ((size_t)BATCH*SEQ*SEQ)
#define KCAT   3072          // [hi | lo | hi] concat along K (projection GEMMs)
#define ACTN   ((size_t)MROWS*DMODEL)
#define PACKN  ((size_t)32*SEQ*128)

// Scratch (device globals; no allocation in kernel_launch)
__device__ float g_y  [MROWS*DMODEL];
__device__ unsigned char g_mask8[MASKN];
__device__ int g_fmt;
__device__ __nv_bfloat16 g_acat3[(size_t)3*MROWS*KCAT];  // 75.5MB
__device__ __nv_bfloat16 g_wcat3[(size_t)3*DMODEL*KCAT]; // 18.9MB
__device__ __nv_bfloat16 g_wcat [(size_t)DMODEL*KCAT];   // 6.3MB (w_o)
__device__ __nv_bfloat16 g_acat [(size_t)MROWS*KCAT];    // 25.2MB (attn out)
__device__ __nv_bfloat16 g_qkvc[(size_t)3*PACKN];        // qc|kc|vc, 48MB

// ======================= mma.sync + cp.async helpers =======================
__device__ __forceinline__ void mma16816(float* c, const uint32_t* a, const uint32_t* b) {
    asm volatile("mma.sync.aligned.m16n8k16.row.col.f32.bf16.bf16.f32 "
        "{%0,%1,%2,%3}, {%4,%5,%6,%7}, {%8,%9}, {%0,%1,%2,%3};"
        : "+f"(c[0]), "+f"(c[1]), "+f"(c[2]), "+f"(c[3])
        : "r"(a[0]), "r"(a[1]), "r"(a[2]), "r"(a[3]), "r"(b[0]), "r"(b[1]));
}
__device__ __forceinline__ void ldsm4(uint32_t* r, uint32_t addr) {
    asm volatile("ldmatrix.sync.aligned.m8n8.x4.shared.b16 {%0,%1,%2,%3}, [%4];"
        : "=r"(r[0]), "=r"(r[1]), "=r"(r[2]), "=r"(r[3]) : "r"(addr));
}
__device__ __forceinline__ void ldsm4t(uint32_t* r, uint32_t addr) {
    asm volatile("ldmatrix.sync.aligned.m8n8.x4.trans.shared.b16 {%0,%1,%2,%3}, [%4];"
        : "=r"(r[0]), "=r"(r[1]), "=r"(r[2]), "=r"(r[3]) : "r"(addr));
}
__device__ __forceinline__ uint32_t smem_u32(const void* p) {
    uint32_t a;
    asm("{ .reg .u64 t; cvta.to.shared.u64 t, %1; cvt.u32.u64 %0, t; }" : "=r"(a) : "l"(p));
    return a;
}
__device__ __forceinline__ void cp16(uint32_t dst, const void* src) {
    asm volatile("cp.async.cg.shared.global [%0], [%1], 16;" :: "r"(dst), "l"(src));
}
#define CP_COMMIT() asm volatile("cp.async.commit_group;" ::: "memory")
#define CP_WAIT1()  asm volatile("cp.async.wait_group 1;" ::: "memory")
#define CP_WAIT0()  asm volatile("cp.async.wait_group 0;" ::: "memory")

__device__ __forceinline__ void pack_hilo(float x, float y, uint32_t& hi, uint32_t& lo) {
    __nv_bfloat16 hx = __float2bfloat16(x), hy = __float2bfloat16(y);
    __nv_bfloat16 lx = __float2bfloat16(x - __bfloat162float(hx));
    __nv_bfloat16 ly = __float2bfloat16(y - __bfloat162float(hy));
    __nv_bfloat162 hp = __halves2bfloat162(hx, hy);
    __nv_bfloat162 lp = __halves2bfloat162(lx, ly);
    hi = *(uint32_t*)&hp; lo = *(uint32_t*)&lp;
}

// ======================= mask dtype probe + convert ========================
__global__ void probe_mask(const unsigned int* __restrict__ m) {
    __shared__ int s_i32, s_f32;
    if (threadIdx.x == 0) { s_i32 = 1; s_f32 = 1; }
    __syncthreads();
    int bad_i = 0, bad_f = 0;
    for (int i = threadIdx.x; i < (1 << 20); i += blockDim.x) {
        unsigned int w = m[i];
        if (w != 0u && w != 1u) bad_i = 1;
        if (w != 0u && w != 0x3F800000u) bad_f = 1;
    }
    if (bad_i) atomicAnd(&s_i32, 0);
    if (bad_f) atomicAnd(&s_f32, 0);
    __syncthreads();
    if (threadIdx.x == 0) g_fmt = s_i32 ? 1 : (s_f32 ? 2 : 0);
}
__global__ void convert_mask(const void* __restrict__ src) {
    size_t i = (size_t)blockIdx.x * blockDim.x + threadIdx.x;
    if (i >= MASKN) return;
    int fmt = g_fmt;
    unsigned char v;
    if (fmt == 1)      v = (unsigned char)(((const int*)src)[i] != 0);
    else if (fmt == 2) v = (unsigned char)(((const float*)src)[i] != 0.f);
    else               v = ((const unsigned char*)src)[i];
    g_mask8[i] = v;
}

// ======================= bf16 hi/lo split conversions ======================
// q,k,v -> acat3[z][r][hi|lo|hi]
__global__ void split_act3(const float* __restrict__ q, const float* __restrict__ k,
                           const float* __restrict__ v, __nv_bfloat16* __restrict__ out) {
    size_t i = (size_t)blockIdx.x * blockDim.x + threadIdx.x;
    if (i >= 3 * ACTN) return;
    int z = (int)(i / ACTN);
    size_t j = i % ACTN;
    size_t r = j / DMODEL, d = j % DMODEL;
    const float* src = (z == 0) ? q : (z == 1) ? k : v;
    float val = src[j];
    __nv_bfloat16 hi = __float2bfloat16(val);
    __nv_bfloat16 lo = __float2bfloat16(val - __bfloat162float(hi));
    __nv_bfloat16* o = out + (size_t)z * MROWS * KCAT + r * KCAT;
    o[d] = hi; o[1024 + d] = lo; o[2048 + d] = hi;
}
// w_q,w_k,w_v [h,d,e] -> wcat3[z][n][hi|hi|lo]
__global__ void split_w3(const float* __restrict__ wq, const float* __restrict__ wk,
                         const float* __restrict__ wv, __nv_bfloat16* __restrict__ out) {
    const size_t WN = (size_t)NHEAD * DMODEL * DHEAD;
    size_t i = (size_t)blockIdx.x * blockDim.x + threadIdx.x;
    if (i >= 3 * WN) return;
    int z = (int)(i / WN);
    size_t j = i % WN;
    int h = (int)(j / (DMODEL * DHEAD));
    int rem = (int)(j % (DMODEL * DHEAD));
    int d = rem / DHEAD, e = rem % DHEAD;
    int n = h * DHEAD + e;
    const float* src = (z == 0) ? wq : (z == 1) ? wk : wv;
    float val = src[j];
    __nv_bfloat16 hi = __float2bfloat16(val);
    __nv_bfloat16 lo = __float2bfloat16(val - __bfloat162float(hi));
    __nv_bfloat16* o = out + (size_t)z * DMODEL * KCAT + (size_t)n * KCAT;
    o[d] = hi; o[1024 + d] = hi; o[2048 + d] = lo;
}
__global__ void split_w_flat(const float* __restrict__ w, __nv_bfloat16* __restrict__ out) {
    size_t i = (size_t)blockIdx.x * blockDim.x + threadIdx.x;
    if (i >= (size_t)DMODEL * DMODEL) return;
    int d = (int)(i / DMODEL), n = (int)(i % DMODEL);
    float v = w[i];
    __nv_bfloat16 hi = __float2bfloat16(v);
    __nv_bfloat16 lo = __float2bfloat16(v - __bfloat162float(hi));
    __nv_bfloat16* o = out + (size_t)n * KCAT;
    o[d] = hi; o[1024 + d] = hi; o[2048 + d] = lo;
}

// ======================= mma.sync GEMM machinery ===========================
#define GBK     64
#define GNITER  (KCAT / GBK)                 // 48
#define TILE_B  (128 * 72 * 2)               // 18432 bytes per A or B tile
#define BUF_B   (2 * TILE_B)
#define GEMM_SMEM (2 * BUF_B)                // 73728

// Shared mainloop: accumulates C(128x128) for A[m0..], Bt[n0..] over KCAT.
__device__ __forceinline__ void gemm_mainloop(
    const __nv_bfloat16* Ag0, const __nv_bfloat16* Bg0,
    uint32_t smb, const char* smc, int tid, float acc[4][4][4])
{
    const int wid = tid >> 5, lid = tid & 31;
    const int wm = wid >> 2, wn = wid & 3;
    const int lrow = lid & 7, quad = lid >> 3;
    const uint32_t aoff = (uint32_t)(((quad & 1) * 8 + lrow) * 144 + (quad >> 1) * 16)
                        + (uint32_t)(wm * 64) * 144;
    const uint32_t boff = (uint32_t)(((quad >> 1) * 8 + lrow) * 144 + (quad & 1) * 16)
                        + (uint32_t)(wn * 32) * 144 + TILE_B;

    {
#pragma unroll
        for (int i = 0; i < 4; i++) {
            int idx = tid + i * 256;
            int r = idx >> 3, ch = idx & 7;
            cp16(smb + r * 144 + ch * 16,          Ag0 + (size_t)r * KCAT + ch * 8);
            cp16(smb + TILE_B + r * 144 + ch * 16, Bg0 + (size_t)r * KCAT + ch * 8);
        }
        CP_COMMIT();
    }

    int buf = 0;
    for (int it = 0; it < GNITER; it++) {
        if (it + 1 < GNITER) {
            const __nv_bfloat16* Ag = Ag0 + (it + 1) * GBK;
            const __nv_bfloat16* Bg = Bg0 + (it + 1) * GBK;
            const uint32_t nb = smb + (buf ^ 1) * BUF_B;
#pragma unroll
            for (int i = 0; i < 4; i++) {
                int idx = tid + i * 256;
                int r = idx >> 3, ch = idx & 7;
                cp16(nb + r * 144 + ch * 16,          Ag + (size_t)r * KCAT + ch * 8);
                cp16(nb + TILE_B + r * 144 + ch * 16, Bg + (size_t)r * KCAT + ch * 8);
            }
            CP_COMMIT();
            CP_WAIT1();
        } else {
            CP_WAIT0();
        }
        __syncthreads();

        const uint32_t bb = smb + buf * BUF_B;
#pragma unroll
        for (int ks = 0; ks < 4; ks++) {
            uint32_t a[4][4], bq[2][4];
#pragma unroll
            for (int mt = 0; mt < 4; mt++)
                ldsm4(a[mt], bb + aoff + (uint32_t)(mt * 16) * 144 + ks * 32);
#pragma unroll
            for (int p = 0; p < 2; p++)
                ldsm4(bq[p], bb + boff + (uint32_t)(p * 16) * 144 + ks * 32);
#pragma unroll
            for (int mt = 0; mt < 4; mt++)
#pragma unroll
                for (int p = 0; p < 2; p++) {
                    mma16816(acc[mt][2 * p],     a[mt], &bq[p][0]);
                    mma16816(acc[mt][2 * p + 1], a[mt], &bq[p][2]);
                }
        }
        __syncthreads();
        buf ^= 1;
    }
}

// Projection GEMM: grid.z selects q/k/v; packed [hb][row][hi64|lo64] output.
__global__ void __launch_bounds__(256) gemm_proj(
    const __nv_bfloat16* __restrict__ A3, const __nv_bfloat16* __restrict__ B3,
    __nv_bfloat16* __restrict__ Cp3)
{
    extern __shared__ char smc[];
    const uint32_t smb = smem_u32(smc);
    const int tid = threadIdx.x;
    const int wid = tid >> 5, lid = tid & 31;
    const int wm = wid >> 2, wn = wid & 3;
    const int g = lid >> 2, tg = lid & 3;
    const int m0 = blockIdx.y * 128, n0 = blockIdx.x * 128;
    const int z = blockIdx.z;

    const __nv_bfloat16* Ag0 = A3 + (size_t)z * MROWS * KCAT + (size_t)m0 * KCAT;
    const __nv_bfloat16* Bg0 = B3 + (size_t)z * DMODEL * KCAT + (size_t)n0 * KCAT;
    __nv_bfloat16* Cp = Cp3 + (size_t)z * PACKN;

    float acc[4][4][4];
#pragma unroll
    for (int mt = 0; mt < 4; mt++)
#pragma unroll
        for (int nt = 0; nt < 4; nt++)
#pragma unroll
            for (int r = 0; r < 4; r++) acc[mt][nt][r] = 0.f;

    gemm_mainloop(Ag0, Bg0, smb, smc, tid, acc);

#pragma unroll
    for (int mt = 0; mt < 4; mt++) {
        int m = m0 + wm * 64 + mt * 16 + g;
#pragma unroll
        for (int nt = 0; nt < 4; nt++) {
            int n = n0 + wn * 32 + nt * 8 + 2 * tg;
            int h = n >> 6, e = n & 63;
#pragma unroll
            for (int half = 0; half < 2; half++) {
                int mm = m + half * 8;
                int b = mm >> 11, qq = mm & 2047;
                int hb = (h << 1) + b;
                uint32_t hi, lo;
                pack_hilo(acc[mt][nt][2 * half], acc[mt][nt][2 * half + 1], hi, lo);
                __nv_bfloat16* o = Cp + ((size_t)hb * SEQ + qq) * 128;
                *(uint32_t*)(o + e)      = hi;
                *(uint32_t*)(o + 64 + e) = lo;
            }
        }
    }
}

// Output projection GEMM: fp32 C + bias + residual.
__global__ void __launch_bounds__(256) gemm_out(
    const __nv_bfloat16* __restrict__ A, const __nv_bfloat16* __restrict__ Bt,
    float* __restrict__ Cf, const float* __restrict__ bias,
    const float* __restrict__ residual)
{
    extern __shared__ char smc[];
    const uint32_t smb = smem_u32(smc);
    const int tid = threadIdx.x;
    const int wid = tid >> 5, lid = tid & 31;
    const int wm = wid >> 2, wn = wid & 3;
    const int g = lid >> 2, tg = lid & 3;
    const int m0 = blockIdx.y * 128, n0 = blockIdx.x * 128;

    const __nv_bfloat16* Ag0 = A  + (size_t)m0 * KCAT;
    const __nv_bfloat16* Bg0 = Bt + (size_t)n0 * KCAT;

    float acc[4][4][4];
#pragma unroll
    for (int mt = 0; mt < 4; mt++)
#pragma unroll
        for (int nt = 0; nt < 4; nt++)
#pragma unroll
            for (int r = 0; r < 4; r++) acc[mt][nt][r] = 0.f;

    gemm_mainloop(Ag0, Bg0, smb, smc, tid, acc);

#pragma unroll
    for (int mt = 0; mt < 4; mt++) {
        int m = m0 + wm * 64 + mt * 16 + g;
#pragma unroll
        for (int nt = 0; nt < 4; nt++) {
            int n = n0 + wn * 32 + nt * 8 + 2 * tg;
            float2 v0 = make_float2(acc[mt][nt][0], acc[mt][nt][1]);
            float2 v1 = make_float2(acc[mt][nt][2], acc[mt][nt][3]);
            float2 bv = *(const float2*)(bias + n);
            float2 r0 = *(const float2*)(residual + (size_t)m * DMODEL + n);
            float2 r1 = *(const float2*)(residual + (size_t)(m + 8) * DMODEL + n);
            v0.x += bv.x + r0.x; v0.y += bv.y + r0.y;
            v1.x += bv.x + r1.x; v1.y += bv.y + r1.y;
            *(float2*)(Cf + (size_t)m * DMODEL + n)       = v0;
            *(float2*)(Cf + (size_t)(m + 8) * DMODEL + n) = v1;
        }
    }
}

// ======================= flash attention via mma.sync ======================
#define AQ_OFF  0
#define AK_OFF  34816
#define AV_OFF  (34816 + 2*17408)
#define ATT_SMEM (34816 + 4*17408)   // 104448

__global__ void __launch_bounds__(256) attn_mma(
    const __nv_bfloat16* __restrict__ Qc, const __nv_bfloat16* __restrict__ Kc,
    const __nv_bfloat16* __restrict__ Vc, const unsigned char* __restrict__ mask,
    __nv_bfloat16* __restrict__ acat)
{
    extern __shared__ char smc[];
    const uint32_t smb = smem_u32(smc);
    const int tid = threadIdx.x;
    const int wid = tid >> 5, lid = tid & 31;
    const int g = lid >> 2, tg = lid & 3;
    const int qb = blockIdx.x, hb = blockIdx.y;
    const int h = hb >> 1, b = hb & 1;
    const int q0 = qb * 128;
    const int qrow = wid * 16;

    // ldmatrix lane-relative byte offsets (row stride 272B)
    const int lrow = lid & 7, quad = lid >> 3;
    const uint32_t aoff = (uint32_t)(((quad & 1) * 8 + lrow) * 272 + (quad >> 1) * 16)
                        + (uint32_t)qrow * 272;
    const uint32_t boff = (uint32_t)(((quad >> 1) * 8 + lrow) * 272 + (quad & 1) * 16);
    // trans-ldmatrix offset for V ([k][e] layout): rows = keys, cols = e
    const uint32_t voff = (uint32_t)(((quad & 1) * 8 + lrow) * 272 + (quad >> 1) * 16);

    // ---- load Q tile (persistent) + first K/V tile
    {
        const __nv_bfloat16* Qg = Qc + ((size_t)hb * SEQ + q0) * 128;
#pragma unroll
        for (int i = 0; i < 8; i++) {
            int idx = tid + i * 256;
            int r = idx >> 4, ch = idx & 15;
            cp16(smb + AQ_OFF + r * 272 + ch * 16, Qg + (size_t)r * 128 + ch * 8);
        }
        const __nv_bfloat16* Kg = Kc + ((size_t)hb * SEQ) * 128;
        const __nv_bfloat16* Vg = Vc + ((size_t)hb * SEQ) * 128;
#pragma unroll
        for (int i = 0; i < 4; i++) {
            int idx = tid + i * 256;
            int r = idx >> 4, ch = idx & 15;
            cp16(smb + AK_OFF + r * 272 + ch * 16, Kg + (size_t)r * 128 + ch * 8);
            cp16(smb + AV_OFF + r * 272 + ch * 16, Vg + (size_t)r * 128 + ch * 8);
        }
        CP_COMMIT();
    }

    float o_acc[8][4];
#pragma unroll
    for (int nt = 0; nt < 8; nt++)
#pragma unroll
        for (int r = 0; r < 4; r++) o_acc[nt][r] = 0.f;
    float m0 = -1e30f, m1 = -1e30f, l0 = 0.f, l1 = 0.f;

    int buf = 0;

    for (int kt = 0; kt < SEQ / 64; kt++) {
        if (kt + 1 < SEQ / 64) {
            const __nv_bfloat16* Kg = Kc + ((size_t)hb * SEQ + (kt + 1) * 64) * 128;
            const __nv_bfloat16* Vg = Vc + ((size_t)hb * SEQ + (kt + 1) * 64) * 128;
            const uint32_t kb_ = smb + AK_OFF + (buf ^ 1) * 17408;
            const uint32_t vb_ = smb + AV_OFF + (buf ^ 1) * 17408;
#pragma unroll
            for (int i = 0; i < 4; i++) {
                int idx = tid + i * 256;
                int r = idx >> 4, ch = idx & 15;
                cp16(kb_ + r * 272 + ch * 16, Kg + (size_t)r * 128 + ch * 8);
                cp16(vb_ + r * 272 + ch * 16, Vg + (size_t)r * 128 + ch * 8);
            }
            CP_COMMIT();
            CP_WAIT1();
        } else {
            CP_WAIT0();
        }
        __syncthreads();

        const uint32_t Qb = smb + AQ_OFF;
        const uint32_t Kb = smb + AK_OFF + buf * 17408;
        const uint32_t Vb = smb + AV_OFF + buf * 17408;

        // ---- S = Q K^T: Qhi.Khi + Qlo.Khi (kb 0..3), Qhi.Klo (kb 4..7)
        float s[8][4];
#pragma unroll
        for (int nt = 0; nt < 8; nt++)
#pragma unroll
            for (int r = 0; r < 4; r++) s[nt][r] = 0.f;

#pragma unroll
        for (int kb = 0; kb < 4; kb++) {
            uint32_t bq[4][4];
#pragma unroll
            for (int p = 0; p < 4; p++)
                ldsm4(bq[p], Kb + boff + (uint32_t)(p * 16) * 272 + kb * 32);
            uint32_t a[4];
            ldsm4(a, Qb + aoff + kb * 32);          // Qhi
#pragma unroll
            for (int p = 0; p < 4; p++) {
                mma16816(s[2 * p],     a, &bq[p][0]);
                mma16816(s[2 * p + 1], a, &bq[p][2]);
            }
            ldsm4(a, Qb + aoff + (kb + 4) * 32);    // Qlo
#pragma unroll
            for (int p = 0; p < 4; p++) {
                mma16816(s[2 * p],     a, &bq[p][0]);
                mma16816(s[2 * p + 1], a, &bq[p][2]);
            }
        }
#pragma unroll
        for (int kb = 4; kb < 8; kb++) {
            uint32_t bq[4][4];
#pragma unroll
            for (int p = 0; p < 4; p++)
                ldsm4(bq[p], Kb + boff + (uint32_t)(p * 16) * 272 + kb * 32);
            uint32_t a[4];
            ldsm4(a, Qb + aoff + (kb - 4) * 32);    // Qhi
#pragma unroll
            for (int p = 0; p < 4; p++) {
                mma16816(s[2 * p],     a, &bq[p][0]);
                mma16816(s[2 * p + 1], a, &bq[p][2]);
            }
        }

        // ---- scale + mask
        const size_t mrow0 = ((size_t)b * SEQ + q0 + qrow + g) * SEQ + kt * 64;
        const size_t mrow1 = mrow0 + 8 * SEQ;
#pragma unroll
        for (int nt = 0; nt < 8; nt++) {
            uchar2 mk0 = *(const uchar2*)(mask + mrow0 + nt * 8 + 2 * tg);
            uchar2 mk1 = *(const uchar2*)(mask + mrow1 + nt * 8 + 2 * tg);
            s[nt][0] = mk0.x ? -1e30f : s[nt][0] * 0.125f;
            s[nt][1] = mk0.y ? -1e30f : s[nt][1] * 0.125f;
            s[nt][2] = mk1.x ? -1e30f : s[nt][2] * 0.125f;
            s[nt][3] = mk1.y ? -1e30f : s[nt][3] * 0.125f;
        }

        // ---- online softmax
        float mt0 = -1e30f, mt1 = -1e30f;
#pragma unroll
        for (int nt = 0; nt < 8; nt++) {
            mt0 = fmaxf(mt0, fmaxf(s[nt][0], s[nt][1]));
            mt1 = fmaxf(mt1, fmaxf(s[nt][2], s[nt][3]));
        }
        mt0 = fmaxf(mt0, __shfl_xor_sync(0xffffffffu, mt0, 1));
        mt0 = fmaxf(mt0, __shfl_xor_sync(0xffffffffu, mt0, 2));
        mt1 = fmaxf(mt1, __shfl_xor_sync(0xffffffffu, mt1, 1));
        mt1 = fmaxf(mt1, __shfl_xor_sync(0xffffffffu, mt1, 2));
        const float mn0 = fmaxf(m0, mt0), mn1 = fmaxf(m1, mt1);
        const float f0 = __expf(m0 - mn0), f1 = __expf(m1 - mn1);

        float ls0 = 0.f, ls1 = 0.f;
#pragma unroll
        for (int nt = 0; nt < 8; nt++) {
            s[nt][0] = __expf(s[nt][0] - mn0);
            s[nt][1] = __expf(s[nt][1] - mn0);
            s[nt][2] = __expf(s[nt][2] - mn1);
            s[nt][3] = __expf(s[nt][3] - mn1);
            ls0 += s[nt][0] + s[nt][1];
            ls1 += s[nt][2] + s[nt][3];
        }
        ls0 += __shfl_xor_sync(0xffffffffu, ls0, 1);
        ls0 += __shfl_xor_sync(0xffffffffu, ls0, 2);
        ls1 += __shfl_xor_sync(0xffffffffu, ls1, 1);
        ls1 += __shfl_xor_sync(0xffffffffu, ls1, 2);
        l0 = l0 * f0 + ls0; l1 = l1 * f1 + ls1;
        m0 = mn0; m1 = mn1;

#pragma unroll
        for (int nt = 0; nt < 8; nt++) {
            o_acc[nt][0] *= f0; o_acc[nt][1] *= f0;
            o_acc[nt][2] *= f1; o_acc[nt][3] *= f1;
        }

        // ---- P hi/lo fragments (A-frag layout; k-chunks of 16 keys)
        uint32_t phi[4][4], plo[4][4];
#pragma unroll
        for (int ks = 0; ks < 4; ks++) {
            pack_hilo(s[2*ks][0],   s[2*ks][1],   phi[ks][0], plo[ks][0]);
            pack_hilo(s[2*ks][2],   s[2*ks][3],   phi[ks][1], plo[ks][1]);
            pack_hilo(s[2*ks+1][0], s[2*ks+1][1], phi[ks][2], plo[ks][2]);
            pack_hilo(s[2*ks+1][2], s[2*ks+1][3], phi[ks][3], plo[ks][3]);
        }

        // ---- O += P V via trans-ldmatrix of [k][e] tiles
        // per key-chunk kb: Vhi (e 0..63) with phi+plo, Vlo with phi
#pragma unroll
        for (int kb = 0; kb < 4; kb++) {
            const uint32_t krow = Vb + voff + (uint32_t)(kb * 16) * 272;
            uint32_t bt[4][4];
#pragma unroll
            for (int nt = 0; nt < 4; nt++)
                ldsm4t(bt[nt], krow + nt * 32);            // Vhi e-block nt
#pragma unroll
            for (int nt = 0; nt < 4; nt++) {
                mma16816(o_acc[2 * nt],     phi[kb], &bt[nt][0]);
                mma16816(o_acc[2 * nt + 1], phi[kb], &bt[nt][2]);
                mma16816(o_acc[2 * nt],     plo[kb], &bt[nt][0]);
                mma16816(o_acc[2 * nt + 1], plo[kb], &bt[nt][2]);
            }
#pragma unroll
            for (int nt = 0; nt < 4; nt++)
                ldsm4t(bt[nt], krow + 128 + nt * 32);      // Vlo e-block nt
#pragma unroll
            for (int nt = 0; nt < 4; nt++) {
                mma16816(o_acc[2 * nt],     phi[kb], &bt[nt][0]);
                mma16816(o_acc[2 * nt + 1], phi[kb], &bt[nt][2]);
            }
        }
        __syncthreads();
        buf ^= 1;
    }

    // ---- epilogue: normalize, split hi/lo, write into acat [hi|lo|hi]
    const float inv0 = 1.f / l0, inv1 = 1.f / l1;
    const int row0 = b * SEQ + q0 + qrow + g;
    const int row1 = row0 + 8;
    __nv_bfloat16* p0 = acat + (size_t)row0 * KCAT;
    __nv_bfloat16* p1 = acat + (size_t)row1 * KCAT;
#pragma unroll
    for (int nt = 0; nt < 8; nt++) {
        const int d = h * 64 + nt * 8 + 2 * tg;
        uint32_t h0, lo0, h1, lo1;
        pack_hilo(o_acc[nt][0] * inv0, o_acc[nt][1] * inv0, h0, lo0);
        pack_hilo(o_acc[nt][2] * inv1, o_acc[nt][3] * inv1, h1, lo1);
        *(uint32_t*)(p0 + d)        = h0;
        *(uint32_t*)(p0 + 1024 + d) = lo0;
        *(uint32_t*)(p0 + 2048 + d) = h0;
        *(uint32_t*)(p1 + d)        = h1;
        *(uint32_t*)(p1 + 1024 + d) = lo1;
        *(uint32_t*)(p1 + 2048 + d) = h1;
    }
}

// ======================= LayerNorm (torch semantics) =======================
__global__ void __launch_bounds__(256) ln_kernel(
    const float* __restrict__ y, const float* __restrict__ gamma,
    const float* __restrict__ beta, float* __restrict__ out)
{
    __shared__ float sh_s[8], sh_ss[8];
    const int row = blockIdx.x;
    const float* x = y + (size_t)row * DMODEL;

    float s = 0.f, ss = 0.f;
    for (int i = threadIdx.x; i < DMODEL; i += 256) {
        float v = x[i]; s += v; ss += v * v;
    }
#pragma unroll
    for (int o = 16; o > 0; o >>= 1) {
        s  += __shfl_xor_sync(0xffffffffu, s,  o);
        ss += __shfl_xor_sync(0xffffffffu, ss, o);
    }
    int warp = threadIdx.x >> 5, lane = threadIdx.x & 31;
    if (lane == 0) { sh_s[warp] = s; sh_ss[warp] = ss; }
    __syncthreads();
    if (threadIdx.x < 32) {
        s  = (lane < 8) ? sh_s[lane]  : 0.f;
        ss = (lane < 8) ? sh_ss[lane] : 0.f;
#pragma unroll
        for (int o = 4; o > 0; o >>= 1) {
            s  += __shfl_xor_sync(0xffffffffu, s,  o);
            ss += __shfl_xor_sync(0xffffffffu, ss, o);
        }
        if (lane == 0) { sh_s[0] = s; sh_ss[0] = ss; }
    }
    __syncthreads();
    float mean = sh_s[0] * (1.f / DMODEL);
    float var  = (sh_ss[0] - (float)DMODEL * mean * mean) * (1.f / (DMODEL - 1));
    var = fmaxf(var, 0.f);
    float inv = 1.f / (sqrtf(var) + 1e-3f);
    for (int i = threadIdx.x; i < DMODEL; i += 256)
        out[(size_t)row * DMODEL + i] = (x[i] - mean) * inv * gamma[i] + beta[i];
}

// ===========================================================================
extern "C" void kernel_launch(void* const* d_in, const int* in_sizes, int n_in,
                              void* d_out, int out_size)
{
    const float* v     = (const float*)d_in[0];
    const float* k     = (const float*)d_in[1];
    const float* q     = (const float*)d_in[2];
    const void*  mask  = (const void*)d_in[3];
    const float* w_q   = (const float*)d_in[4];
    const float* w_k   = (const float*)d_in[5];
    const float* w_v   = (const float*)d_in[6];
    const float* w_o   = (const float*)d_in[7];
    const float* b_o   = (const float*)d_in[8];
    const float* gamma = (const float*)d_in[9];
    const float* beta  = (const float*)d_in[10];
    float*       out   = (float*)d_out;

    float* y;
    unsigned char* mask8;
    __nv_bfloat16 *acat3, *wcat3, *wcat, *acat, *qkvc;
    cudaGetSymbolAddress((void**)&y,     g_y);
    cudaGetSymbolAddress((void**)&mask8, g_mask8);
    cudaGetSymbolAddress((void**)&acat3, g_acat3);
    cudaGetSymbolAddress((void**)&wcat3, g_wcat3);
    cudaGetSymbolAddress((void**)&wcat,  g_wcat);
    cudaGetSymbolAddress((void**)&acat,  g_acat);
    cudaGetSymbolAddress((void**)&qkvc,  g_qkvc);

    cudaFuncSetAttribute(gemm_proj, cudaFuncAttributeMaxDynamicSharedMemorySize, GEMM_SMEM);
    cudaFuncSetAttribute(gemm_out,  cudaFuncAttributeMaxDynamicSharedMemorySize, GEMM_SMEM);
    cudaFuncSetAttribute(attn_mma,  cudaFuncAttributeMaxDynamicSharedMemorySize, ATT_SMEM);

    __nv_bfloat16* qc = qkvc;
    __nv_bfloat16* kc = qkvc + PACKN;
    __nv_bfloat16* vc = qkvc + 2 * PACKN;

    // Mask -> uint8
    probe_mask<<<1, 1024>>>((const unsigned int*)mask);
    convert_mask<<<(int)((MASKN + 255) / 256), 256>>>(mask);

    // Splits (merged)
    split_act3<<<(int)((3 * ACTN + 255) / 256), 256>>>(q, k, v, acat3);
    split_w3<<<(int)((3 * (size_t)NHEAD * DMODEL * DHEAD + 255) / 256), 256>>>(w_q, w_k, w_v, wcat3);
    split_w_flat<<<(int)(((size_t)DMODEL * DMODEL + 255) / 256), 256>>>(w_o, wcat);

    // All three projections in one launch -> packed qc/kc/vc
    dim3 pgrid(DMODEL / 128, MROWS / 128, 3);    // (8, 32, 3)
    gemm_proj<<<pgrid, 256, GEMM_SMEM>>>(acat3, wcat3, qkvc);

    // Flash attention (writes acat directly)
    dim3 agrid(SEQ / 128, NHEAD * BATCH);
    attn_mma<<<agrid, 256, ATT_SMEM>>>(qc, kc, vc, mask8, acat);

    // Output projection + bias + residual(k)
    dim3 ggrid(DMODEL / 128, MROWS / 128);
    gemm_out<<<ggrid, 256, GEMM_SMEM>>>(acat, wcat, y, b_o, k);

    // LayerNorm
    ln_kernel<<<MROWS, 256>>>(y, gamma, beta, out);
}

// round 9
// speedup vs baseline: 2.9920x; 1.1139x over previous
#include <cuda_runtime.h>
#include <cuda_bf16.h>
#include <math.h>
#include <cstdint>

#define NHEAD  16
#define DMODEL 1024
#define DHEAD  64
#define BATCH  2
#define SEQ    2048
#define MROWS  (BATCH*SEQ)   // 4096
#define MASKN  ((size_t)BATCH*SEQ*SEQ)
#define KCAT   3072          // [hi | lo | hi] concat along K (projection GEMMs)
#define ACTN   ((size_t)MROWS*DMODEL)
#define PACKN  ((size_t)32*SEQ*128)

// Scratch (device globals; no allocation in kernel_launch)
__device__ float g_y  [MROWS*DMODEL];
__device__ unsigned char g_mask8[MASKN];
__device__ int g_fmt;
__device__ __nv_bfloat16 g_acat3[(size_t)3*MROWS*KCAT];  // 75.5MB
__device__ __nv_bfloat16 g_wcat3[(size_t)3*DMODEL*KCAT]; // 18.9MB
__device__ __nv_bfloat16 g_wcat [(size_t)DMODEL*KCAT];   // 6.3MB (w_o)
__device__ __nv_bfloat16 g_acat [(size_t)MROWS*KCAT];    // 25.2MB (attn out)
__device__ __nv_bfloat16 g_qkvc[(size_t)3*PACKN];        // qc|kc|vc, 48MB

// ======================= mma.sync + cp.async helpers =======================
__device__ __forceinline__ void mma16816(float* c, const uint32_t* a, const uint32_t* b) {
    asm volatile("mma.sync.aligned.m16n8k16.row.col.f32.bf16.bf16.f32 "
        "{%0,%1,%2,%3}, {%4,%5,%6,%7}, {%8,%9}, {%0,%1,%2,%3};"
        : "+f"(c[0]), "+f"(c[1]), "+f"(c[2]), "+f"(c[3])
        : "r"(a[0]), "r"(a[1]), "r"(a[2]), "r"(a[3]), "r"(b[0]), "r"(b[1]));
}
__device__ __forceinline__ void ldsm4(uint32_t* r, uint32_t addr) {
    asm volatile("ldmatrix.sync.aligned.m8n8.x4.shared.b16 {%0,%1,%2,%3}, [%4];"
        : "=r"(r[0]), "=r"(r[1]), "=r"(r[2]), "=r"(r[3]) : "r"(addr));
}
__device__ __forceinline__ void ldsm4t(uint32_t* r, uint32_t addr) {
    asm volatile("ldmatrix.sync.aligned.m8n8.x4.trans.shared.b16 {%0,%1,%2,%3}, [%4];"
        : "=r"(r[0]), "=r"(r[1]), "=r"(r[2]), "=r"(r[3]) : "r"(addr));
}
__device__ __forceinline__ uint32_t smem_u32(const void* p) {
    uint32_t a;
    asm("{ .reg .u64 t; cvta.to.shared.u64 t, %1; cvt.u32.u64 %0, t; }" : "=r"(a) : "l"(p));
    return a;
}
__device__ __forceinline__ void cp16(uint32_t dst, const void* src) {
    asm volatile("cp.async.cg.shared.global [%0], [%1], 16;" :: "r"(dst), "l"(src));
}
#define CP_COMMIT() asm volatile("cp.async.commit_group;" ::: "memory")
#define CP_WAIT1()  asm volatile("cp.async.wait_group 1;" ::: "memory")
#define CP_WAIT0()  asm volatile("cp.async.wait_group 0;" ::: "memory")

__device__ __forceinline__ void pack_hilo(float x, float y, uint32_t& hi, uint32_t& lo) {
    __nv_bfloat16 hx = __float2bfloat16(x), hy = __float2bfloat16(y);
    __nv_bfloat16 lx = __float2bfloat16(x - __bfloat162float(hx));
    __nv_bfloat16 ly = __float2bfloat16(y - __bfloat162float(hy));
    __nv_bfloat162 hp = __halves2bfloat162(hx, hy);
    __nv_bfloat162 lp = __halves2bfloat162(lx, ly);
    hi = *(uint32_t*)&hp; lo = *(uint32_t*)&lp;
}

// ======================= mask dtype probe + convert ========================
__global__ void probe_mask(const unsigned int* __restrict__ m) {
    __shared__ int s_i32, s_f32;
    if (threadIdx.x == 0) { s_i32 = 1; s_f32 = 1; }
    __syncthreads();
    int bad_i = 0, bad_f = 0;
    for (int i = threadIdx.x; i < (1 << 20); i += blockDim.x) {
        unsigned int w = m[i];
        if (w != 0u && w != 1u) bad_i = 1;
        if (w != 0u && w != 0x3F800000u) bad_f = 1;
    }
    if (bad_i) atomicAnd(&s_i32, 0);
    if (bad_f) atomicAnd(&s_f32, 0);
    __syncthreads();
    if (threadIdx.x == 0) g_fmt = s_i32 ? 1 : (s_f32 ? 2 : 0);
}
__global__ void convert_mask(const void* __restrict__ src) {
    size_t i = (size_t)blockIdx.x * blockDim.x + threadIdx.x;
    if (i >= MASKN) return;
    int fmt = g_fmt;
    unsigned char v;
    if (fmt == 1)      v = (unsigned char)(((const int*)src)[i] != 0);
    else if (fmt == 2) v = (unsigned char)(((const float*)src)[i] != 0.f);
    else               v = ((const unsigned char*)src)[i];
    g_mask8[i] = v;
}

// ======================= bf16 hi/lo split conversions ======================
// q,k,v -> acat3[z][r][hi|lo|hi]  (writes d-contiguous: already coalesced)
__global__ void split_act3(const float* __restrict__ q, const float* __restrict__ k,
                           const float* __restrict__ v, __nv_bfloat16* __restrict__ out) {
    size_t i = (size_t)blockIdx.x * blockDim.x + threadIdx.x;
    if (i >= 3 * ACTN) return;
    int z = (int)(i / ACTN);
    size_t j = i % ACTN;
    size_t r = j / DMODEL, d = j % DMODEL;
    const float* src = (z == 0) ? q : (z == 1) ? k : v;
    float val = src[j];
    __nv_bfloat16 hi = __float2bfloat16(val);
    __nv_bfloat16 lo = __float2bfloat16(val - __bfloat162float(hi));
    __nv_bfloat16* o = out + (size_t)z * MROWS * KCAT + r * KCAT;
    o[d] = hi; o[1024 + d] = lo; o[2048 + d] = hi;
}

// w_q,w_k,w_v [h,d,e] -> wcat3[z][n=h*64+e][hi|hi|lo], SMEM-tiled transpose.
// grid: (16 d-tiles, NHEAD, 3), 256 threads. Loads coalesced along e,
// writes coalesced along d (64 bf16 = 128B rows).
__global__ void __launch_bounds__(256) split_w3t(
    const float* __restrict__ wq, const float* __restrict__ wk,
    const float* __restrict__ wv, __nv_bfloat16* __restrict__ out)
{
    __shared__ float t[64][65];
    const int dt = blockIdx.x, h = blockIdx.y, z = blockIdx.z;
    const float* src = (z == 0) ? wq : (z == 1) ? wk : wv;
    const int tid = threadIdx.x;
#pragma unroll
    for (int i = 0; i < 16; i++) {
        int idx = tid + i * 256;
        int dr = idx >> 6, e = idx & 63;
        t[dr][e] = src[((size_t)h * DMODEL + dt * 64 + dr) * DHEAD + e];
    }
    __syncthreads();
#pragma unroll
    for (int i = 0; i < 16; i++) {
        int idx = tid + i * 256;
        int e = idx >> 6, dr = idx & 63;
        float val = t[dr][e];
        __nv_bfloat16 hi = __float2bfloat16(val);
        __nv_bfloat16 lo = __float2bfloat16(val - __bfloat162float(hi));
        int n = h * DHEAD + e, d = dt * 64 + dr;
        __nv_bfloat16* o = out + (size_t)z * DMODEL * KCAT + (size_t)n * KCAT;
        o[d] = hi; o[1024 + d] = hi; o[2048 + d] = lo;
    }
}

// w_o [d,n] -> wcat[n][hi|hi|lo], SMEM-tiled transpose.
// grid: (16 n-tiles, 16 d-tiles), 256 threads.
__global__ void __launch_bounds__(256) split_w_flat_t(
    const float* __restrict__ w, __nv_bfloat16* __restrict__ out)
{
    __shared__ float t[64][65];
    const int nt = blockIdx.x, dt = blockIdx.y;
    const int tid = threadIdx.x;
#pragma unroll
    for (int i = 0; i < 16; i++) {
        int idx = tid + i * 256;
        int dr = idx >> 6, nr = idx & 63;
        t[dr][nr] = w[(size_t)(dt * 64 + dr) * DMODEL + nt * 64 + nr];
    }
    __syncthreads();
#pragma unroll
    for (int i = 0; i < 16; i++) {
        int idx = tid + i * 256;
        int nr = idx >> 6, dr = idx & 63;
        float val = t[dr][nr];
        __nv_bfloat16 hi = __float2bfloat16(val);
        __nv_bfloat16 lo = __float2bfloat16(val - __bfloat162float(hi));
        int n = nt * 64 + nr, d = dt * 64 + dr;
        __nv_bfloat16* o = out + (size_t)n * KCAT;
        o[d] = hi; o[1024 + d] = hi; o[2048 + d] = lo;
    }
}

// ======================= mma.sync GEMM machinery ===========================
#define GBK     64
#define GNITER  (KCAT / GBK)                 // 48
#define TILE_B  (128 * 72 * 2)               // 18432 bytes per A or B tile
#define BUF_B   (2 * TILE_B)
#define GEMM_SMEM (2 * BUF_B)                // 73728

// Shared mainloop: accumulates C(128x128) for A[m0..], Bt[n0..] over KCAT.
__device__ __forceinline__ void gemm_mainloop(
    const __nv_bfloat16* Ag0, const __nv_bfloat16* Bg0,
    uint32_t smb, const char* smc, int tid, float acc[4][4][4])
{
    const int wid = tid >> 5, lid = tid & 31;
    const int wm = wid >> 2, wn = wid & 3;
    const int lrow = lid & 7, quad = lid >> 3;
    const uint32_t aoff = (uint32_t)(((quad & 1) * 8 + lrow) * 144 + (quad >> 1) * 16)
                        + (uint32_t)(wm * 64) * 144;
    const uint32_t boff = (uint32_t)(((quad >> 1) * 8 + lrow) * 144 + (quad & 1) * 16)
                        + (uint32_t)(wn * 32) * 144 + TILE_B;

    {
#pragma unroll
        for (int i = 0; i < 4; i++) {
            int idx = tid + i * 256;
            int r = idx >> 3, ch = idx & 7;
            cp16(smb + r * 144 + ch * 16,          Ag0 + (size_t)r * KCAT + ch * 8);
            cp16(smb + TILE_B + r * 144 + ch * 16, Bg0 + (size_t)r * KCAT + ch * 8);
        }
        CP_COMMIT();
    }

    int buf = 0;
    for (int it = 0; it < GNITER; it++) {
        if (it + 1 < GNITER) {
            const __nv_bfloat16* Ag = Ag0 + (it + 1) * GBK;
            const __nv_bfloat16* Bg = Bg0 + (it + 1) * GBK;
            const uint32_t nb = smb + (buf ^ 1) * BUF_B;
#pragma unroll
            for (int i = 0; i < 4; i++) {
                int idx = tid + i * 256;
                int r = idx >> 3, ch = idx & 7;
                cp16(nb + r * 144 + ch * 16,          Ag + (size_t)r * KCAT + ch * 8);
                cp16(nb + TILE_B + r * 144 + ch * 16, Bg + (size_t)r * KCAT + ch * 8);
            }
            CP_COMMIT();
            CP_WAIT1();
        } else {
            CP_WAIT0();
        }
        __syncthreads();

        const uint32_t bb = smb + buf * BUF_B;
#pragma unroll
        for (int ks = 0; ks < 4; ks++) {
            uint32_t a[4][4], bq[2][4];
#pragma unroll
            for (int mt = 0; mt < 4; mt++)
                ldsm4(a[mt], bb + aoff + (uint32_t)(mt * 16) * 144 + ks * 32);
#pragma unroll
            for (int p = 0; p < 2; p++)
                ldsm4(bq[p], bb + boff + (uint32_t)(p * 16) * 144 + ks * 32);
#pragma unroll
            for (int mt = 0; mt < 4; mt++)
#pragma unroll
                for (int p = 0; p < 2; p++) {
                    mma16816(acc[mt][2 * p],     a[mt], &bq[p][0]);
                    mma16816(acc[mt][2 * p + 1], a[mt], &bq[p][2]);
                }
        }
        __syncthreads();
        buf ^= 1;
    }
}

// Projection GEMM: grid.z selects q/k/v; packed [hb][row][hi64|lo64] output.
__global__ void __launch_bounds__(256) gemm_proj(
    const __nv_bfloat16* __restrict__ A3, const __nv_bfloat16* __restrict__ B3,
    __nv_bfloat16* __restrict__ Cp3)
{
    extern __shared__ char smc[];
    const uint32_t smb = smem_u32(smc);
    const int tid = threadIdx.x;
    const int wid = tid >> 5, lid = tid & 31;
    const int wm = wid >> 2, wn = wid & 3;
    const int g = lid >> 2, tg = lid & 3;
    const int m0 = blockIdx.y * 128, n0 = blockIdx.x * 128;
    const int z = blockIdx.z;

    const __nv_bfloat16* Ag0 = A3 + (size_t)z * MROWS * KCAT + (size_t)m0 * KCAT;
    const __nv_bfloat16* Bg0 = B3 + (size_t)z * DMODEL * KCAT + (size_t)n0 * KCAT;
    __nv_bfloat16* Cp = Cp3 + (size_t)z * PACKN;

    float acc[4][4][4];
#pragma unroll
    for (int mt = 0; mt < 4; mt++)
#pragma unroll
        for (int nt = 0; nt < 4; nt++)
#pragma unroll
            for (int r = 0; r < 4; r++) acc[mt][nt][r] = 0.f;

    gemm_mainloop(Ag0, Bg0, smb, smc, tid, acc);

#pragma unroll
    for (int mt = 0; mt < 4; mt++) {
        int m = m0 + wm * 64 + mt * 16 + g;
#pragma unroll
        for (int nt = 0; nt < 4; nt++) {
            int n = n0 + wn * 32 + nt * 8 + 2 * tg;
            int h = n >> 6, e = n & 63;
#pragma unroll
            for (int half = 0; half < 2; half++) {
                int mm = m + half * 8;
                int b = mm >> 11, qq = mm & 2047;
                int hb = (h << 1) + b;
                uint32_t hi, lo;
                pack_hilo(acc[mt][nt][2 * half], acc[mt][nt][2 * half + 1], hi, lo);
                __nv_bfloat16* o = Cp + ((size_t)hb * SEQ + qq) * 128;
                *(uint32_t*)(o + e)      = hi;
                *(uint32_t*)(o + 64 + e) = lo;
            }
        }
    }
}

// Output projection GEMM: fp32 C + bias + residual.
__global__ void __launch_bounds__(256) gemm_out(
    const __nv_bfloat16* __restrict__ A, const __nv_bfloat16* __restrict__ Bt,
    float* __restrict__ Cf, const float* __restrict__ bias,
    const float* __restrict__ residual)
{
    extern __shared__ char smc[];
    const uint32_t smb = smem_u32(smc);
    const int tid = threadIdx.x;
    const int wid = tid >> 5, lid = tid & 31;
    const int wm = wid >> 2, wn = wid & 3;
    const int g = lid >> 2, tg = lid & 3;
    const int m0 = blockIdx.y * 128, n0 = blockIdx.x * 128;

    const __nv_bfloat16* Ag0 = A  + (size_t)m0 * KCAT;
    const __nv_bfloat16* Bg0 = Bt + (size_t)n0 * KCAT;

    float acc[4][4][4];
#pragma unroll
    for (int mt = 0; mt < 4; mt++)
#pragma unroll
        for (int nt = 0; nt < 4; nt++)
#pragma unroll
            for (int r = 0; r < 4; r++) acc[mt][nt][r] = 0.f;

    gemm_mainloop(Ag0, Bg0, smb, smc, tid, acc);

#pragma unroll
    for (int mt = 0; mt < 4; mt++) {
        int m = m0 + wm * 64 + mt * 16 + g;
#pragma unroll
        for (int nt = 0; nt < 4; nt++) {
            int n = n0 + wn * 32 + nt * 8 + 2 * tg;
            float2 v0 = make_float2(acc[mt][nt][0], acc[mt][nt][1]);
            float2 v1 = make_float2(acc[mt][nt][2], acc[mt][nt][3]);
            float2 bv = *(const float2*)(bias + n);
            float2 r0 = *(const float2*)(residual + (size_t)m * DMODEL + n);
            float2 r1 = *(const float2*)(residual + (size_t)(m + 8) * DMODEL + n);
            v0.x += bv.x + r0.x; v0.y += bv.y + r0.y;
            v1.x += bv.x + r1.x; v1.y += bv.y + r1.y;
            *(float2*)(Cf + (size_t)m * DMODEL + n)       = v0;
            *(float2*)(Cf + (size_t)(m + 8) * DMODEL + n) = v1;
        }
    }
}

// ======================= flash attention via mma.sync ======================
#define AQ_OFF  0
#define AK_OFF  34816
#define AV_OFF  (34816 + 2*17408)
#define ATT_SMEM (34816 + 4*17408)   // 104448

__global__ void __launch_bounds__(256) attn_mma(
    const __nv_bfloat16* __restrict__ Qc, const __nv_bfloat16* __restrict__ Kc,
    const __nv_bfloat16* __restrict__ Vc, const unsigned char* __restrict__ mask,
    __nv_bfloat16* __restrict__ acat)
{
    extern __shared__ char smc[];
    const uint32_t smb = smem_u32(smc);
    const int tid = threadIdx.x;
    const int wid = tid >> 5, lid = tid & 31;
    const int g = lid >> 2, tg = lid & 3;
    const int qb = blockIdx.x, hb = blockIdx.y;
    const int h = hb >> 1, b = hb & 1;
    const int q0 = qb * 128;
    const int qrow = wid * 16;

    const int lrow = lid & 7, quad = lid >> 3;
    const uint32_t aoff = (uint32_t)(((quad & 1) * 8 + lrow) * 272 + (quad >> 1) * 16)
                        + (uint32_t)qrow * 272;
    const uint32_t boff = (uint32_t)(((quad >> 1) * 8 + lrow) * 272 + (quad & 1) * 16);
    const uint32_t voff = (uint32_t)(((quad & 1) * 8 + lrow) * 272 + (quad >> 1) * 16);

    // ---- load Q tile (persistent) + first K/V tile
    {
        const __nv_bfloat16* Qg = Qc + ((size_t)hb * SEQ + q0) * 128;
#pragma unroll
        for (int i = 0; i < 8; i++) {
            int idx = tid + i * 256;
            int r = idx >> 4, ch = idx & 15;
            cp16(smb + AQ_OFF + r * 272 + ch * 16, Qg + (size_t)r * 128 + ch * 8);
        }
        const __nv_bfloat16* Kg = Kc + ((size_t)hb * SEQ) * 128;
        const __nv_bfloat16* Vg = Vc + ((size_t)hb * SEQ) * 128;
#pragma unroll
        for (int i = 0; i < 4; i++) {
            int idx = tid + i * 256;
            int r = idx >> 4, ch = idx & 15;
            cp16(smb + AK_OFF + r * 272 + ch * 16, Kg + (size_t)r * 128 + ch * 8);
            cp16(smb + AV_OFF + r * 272 + ch * 16, Vg + (size_t)r * 128 + ch * 8);
        }
        CP_COMMIT();
    }

    float o_acc[8][4];
#pragma unroll
    for (int nt = 0; nt < 8; nt++)
#pragma unroll
        for (int r = 0; r < 4; r++) o_acc[nt][r] = 0.f;
    float m0 = -1e30f, m1 = -1e30f, l0 = 0.f, l1 = 0.f;

    int buf = 0;

    for (int kt = 0; kt < SEQ / 64; kt++) {
        if (kt + 1 < SEQ / 64) {
            const __nv_bfloat16* Kg = Kc + ((size_t)hb * SEQ + (kt + 1) * 64) * 128;
            const __nv_bfloat16* Vg = Vc + ((size_t)hb * SEQ + (kt + 1) * 64) * 128;
            const uint32_t kb_ = smb + AK_OFF + (buf ^ 1) * 17408;
            const uint32_t vb_ = smb + AV_OFF + (buf ^ 1) * 17408;
#pragma unroll
            for (int i = 0; i < 4; i++) {
                int idx = tid + i * 256;
                int r = idx >> 4, ch = idx & 15;
                cp16(kb_ + r * 272 + ch * 16, Kg + (size_t)r * 128 + ch * 8);
                cp16(vb_ + r * 272 + ch * 16, Vg + (size_t)r * 128 + ch * 8);
            }
            CP_COMMIT();
            CP_WAIT1();
        } else {
            CP_WAIT0();
        }
        __syncthreads();

        const uint32_t Qb = smb + AQ_OFF;
        const uint32_t Kb = smb + AK_OFF + buf * 17408;
        const uint32_t Vb = smb + AV_OFF + buf * 17408;

        // ---- S = Q K^T: Qhi.Khi + Qlo.Khi (kb 0..3), Qhi.Klo (kb 4..7)
        float s[8][4];
#pragma unroll
        for (int nt = 0; nt < 8; nt++)
#pragma unroll
            for (int r = 0; r < 4; r++) s[nt][r] = 0.f;

#pragma unroll
        for (int kb = 0; kb < 4; kb++) {
            uint32_t bq[4][4];
#pragma unroll
            for (int p = 0; p < 4; p++)
                ldsm4(bq[p], Kb + boff + (uint32_t)(p * 16) * 272 + kb * 32);
            uint32_t a[4];
            ldsm4(a, Qb + aoff + kb * 32);          // Qhi
#pragma unroll
            for (int p = 0; p < 4; p++) {
                mma16816(s[2 * p],     a, &bq[p][0]);
                mma16816(s[2 * p + 1], a, &bq[p][2]);
            }
            ldsm4(a, Qb + aoff + (kb + 4) * 32);    // Qlo
#pragma unroll
            for (int p = 0; p < 4; p++) {
                mma16816(s[2 * p],     a, &bq[p][0]);
                mma16816(s[2 * p + 1], a, &bq[p][2]);
            }
        }
#pragma unroll
        for (int kb = 4; kb < 8; kb++) {
            uint32_t bq[4][4];
#pragma unroll
            for (int p = 0; p < 4; p++)
                ldsm4(bq[p], Kb + boff + (uint32_t)(p * 16) * 272 + kb * 32);
            uint32_t a[4];
            ldsm4(a, Qb + aoff + (kb - 4) * 32);    // Qhi
#pragma unroll
            for (int p = 0; p < 4; p++) {
                mma16816(s[2 * p],     a, &bq[p][0]);
                mma16816(s[2 * p + 1], a, &bq[p][2]);
            }
        }

        // ---- scale + mask
        const size_t mrow0 = ((size_t)b * SEQ + q0 + qrow + g) * SEQ + kt * 64;
        const size_t mrow1 = mrow0 + 8 * SEQ;
#pragma unroll
        for (int nt = 0; nt < 8; nt++) {
            uchar2 mk0 = *(const uchar2*)(mask + mrow0 + nt * 8 + 2 * tg);
            uchar2 mk1 = *(const uchar2*)(mask + mrow1 + nt * 8 + 2 * tg);
            s[nt][0] = mk0.x ? -1e30f : s[nt][0] * 0.125f;
            s[nt][1] = mk0.y ? -1e30f : s[nt][1] * 0.125f;
            s[nt][2] = mk1.x ? -1e30f : s[nt][2] * 0.125f;
            s[nt][3] = mk1.y ? -1e30f : s[nt][3] * 0.125f;
        }

        // ---- online softmax
        float mt0 = -1e30f, mt1 = -1e30f;
#pragma unroll
        for (int nt = 0; nt < 8; nt++) {
            mt0 = fmaxf(mt0, fmaxf(s[nt][0], s[nt][1]));
            mt1 = fmaxf(mt1, fmaxf(s[nt][2], s[nt][3]));
        }
        mt0 = fmaxf(mt0, __shfl_xor_sync(0xffffffffu, mt0, 1));
        mt0 = fmaxf(mt0, __shfl_xor_sync(0xffffffffu, mt0, 2));
        mt1 = fmaxf(mt1, __shfl_xor_sync(0xffffffffu, mt1, 1));
        mt1 = fmaxf(mt1, __shfl_xor_sync(0xffffffffu, mt1, 2));
        const float mn0 = fmaxf(m0, mt0), mn1 = fmaxf(m1, mt1);
        const float f0 = __expf(m0 - mn0), f1 = __expf(m1 - mn1);

        float ls0 = 0.f, ls1 = 0.f;
#pragma unroll
        for (int nt = 0; nt < 8; nt++) {
            s[nt][0] = __expf(s[nt][0] - mn0);
            s[nt][1] = __expf(s[nt][1] - mn0);
            s[nt][2] = __expf(s[nt][2] - mn1);
            s[nt][3] = __expf(s[nt][3] - mn1);
            ls0 += s[nt][0] + s[nt][1];
            ls1 += s[nt][2] + s[nt][3];
        }
        ls0 += __shfl_xor_sync(0xffffffffu, ls0, 1);
        ls0 += __shfl_xor_sync(0xffffffffu, ls0, 2);
        ls1 += __shfl_xor_sync(0xffffffffu, ls1, 1);
        ls1 += __shfl_xor_sync(0xffffffffu, ls1, 2);
        l0 = l0 * f0 + ls0; l1 = l1 * f1 + ls1;
        m0 = mn0; m1 = mn1;

#pragma unroll
        for (int nt = 0; nt < 8; nt++) {
            o_acc[nt][0] *= f0; o_acc[nt][1] *= f0;
            o_acc[nt][2] *= f1; o_acc[nt][3] *= f1;
        }

        // ---- P hi/lo fragments (A-frag layout; k-chunks of 16 keys)
        uint32_t phi[4][4], plo[4][4];
#pragma unroll
        for (int ks = 0; ks < 4; ks++) {
            pack_hilo(s[2*ks][0],   s[2*ks][1],   phi[ks][0], plo[ks][0]);
            pack_hilo(s[2*ks][2],   s[2*ks][3],   phi[ks][1], plo[ks][1]);
            pack_hilo(s[2*ks+1][0], s[2*ks+1][1], phi[ks][2], plo[ks][2]);
            pack_hilo(s[2*ks+1][2], s[2*ks+1][3], phi[ks][3], plo[ks][3]);
        }

        // ---- O += P V via trans-ldmatrix of [k][e] tiles
#pragma unroll
        for (int kb = 0; kb < 4; kb++) {
            const uint32_t krow = Vb + voff + (uint32_t)(kb * 16) * 272;
            uint32_t bt[4][4];
#pragma unroll
            for (int nt = 0; nt < 4; nt++)
                ldsm4t(bt[nt], krow + nt * 32);            // Vhi e-block nt
#pragma unroll
            for (int nt = 0; nt < 4; nt++) {
                mma16816(o_acc[2 * nt],     phi[kb], &bt[nt][0]);
                mma16816(o_acc[2 * nt + 1], phi[kb], &bt[nt][2]);
                mma16816(o_acc[2 * nt],     plo[kb], &bt[nt][0]);
                mma16816(o_acc[2 * nt + 1], plo[kb], &bt[nt][2]);
            }
#pragma unroll
            for (int nt = 0; nt < 4; nt++)
                ldsm4t(bt[nt], krow + 128 + nt * 32);      // Vlo e-block nt
#pragma unroll
            for (int nt = 0; nt < 4; nt++) {
                mma16816(o_acc[2 * nt],     phi[kb], &bt[nt][0]);
                mma16816(o_acc[2 * nt + 1], phi[kb], &bt[nt][2]);
            }
        }
        __syncthreads();
        buf ^= 1;
    }

    // ---- epilogue: normalize, split hi/lo, write into acat [hi|lo|hi]
    const float inv0 = 1.f / l0, inv1 = 1.f / l1;
    const int row0 = b * SEQ + q0 + qrow + g;
    const int row1 = row0 + 8;
    __nv_bfloat16* p0 = acat + (size_t)row0 * KCAT;
    __nv_bfloat16* p1 = acat + (size_t)row1 * KCAT;
#pragma unroll
    for (int nt = 0; nt < 8; nt++) {
        const int d = h * 64 + nt * 8 + 2 * tg;
        uint32_t h0, lo0, h1, lo1;
        pack_hilo(o_acc[nt][0] * inv0, o_acc[nt][1] * inv0, h0, lo0);
        pack_hilo(o_acc[nt][2] * inv1, o_acc[nt][3] * inv1, h1, lo1);
        *(uint32_t*)(p0 + d)        = h0;
        *(uint32_t*)(p0 + 1024 + d) = lo0;
        *(uint32_t*)(p0 + 2048 + d) = h0;
        *(uint32_t*)(p1 + d)        = h1;
        *(uint32_t*)(p1 + 1024 + d) = lo1;
        *(uint32_t*)(p1 + 2048 + d) = h1;
    }
}

// ======================= LayerNorm (torch semantics) =======================
__global__ void __launch_bounds__(256) ln_kernel(
    const float* __restrict__ y, const float* __restrict__ gamma,
    const float* __restrict__ beta, float* __restrict__ out)
{
    __shared__ float sh_s[8], sh_ss[8];
    const int row = blockIdx.x;
    const float* x = y + (size_t)row * DMODEL;

    float s = 0.f, ss = 0.f;
    for (int i = threadIdx.x; i < DMODEL; i += 256) {
        float v = x[i]; s += v; ss += v * v;
    }
#pragma unroll
    for (int o = 16; o > 0; o >>= 1) {
        s  += __shfl_xor_sync(0xffffffffu, s,  o);
        ss += __shfl_xor_sync(0xffffffffu, ss, o);
    }
    int warp = threadIdx.x >> 5, lane = threadIdx.x & 31;
    if (lane == 0) { sh_s[warp] = s; sh_ss[warp] = ss; }
    __syncthreads();
    if (threadIdx.x < 32) {
        s  = (lane < 8) ? sh_s[lane]  : 0.f;
        ss = (lane < 8) ? sh_ss[lane] : 0.f;
#pragma unroll
        for (int o = 4; o > 0; o >>= 1) {
            s  += __shfl_xor_sync(0xffffffffu, s,  o);
            ss += __shfl_xor_sync(0xffffffffu, ss, o);
        }
        if (lane == 0) { sh_s[0] = s; sh_ss[0] = ss; }
    }
    __syncthreads();
    float mean = sh_s[0] * (1.f / DMODEL);
    float var  = (sh_ss[0] - (float)DMODEL * mean * mean) * (1.f / (DMODEL - 1));
    var = fmaxf(var, 0.f);
    float inv = 1.f / (sqrtf(var) + 1e-3f);
    for (int i = threadIdx.x; i < DMODEL; i += 256)
        out[(size_t)row * DMODEL + i] = (x[i] - mean) * inv * gamma[i] + beta[i];
}

// ===========================================================================
extern "C" void kernel_launch(void* const* d_in, const int* in_sizes, int n_in,
                              void* d_out, int out_size)
{
    const float* v     = (const float*)d_in[0];
    const float* k     = (const float*)d_in[1];
    const float* q     = (const float*)d_in[2];
    const void*  mask  = (const void*)d_in[3];
    const float* w_q   = (const float*)d_in[4];
    const float* w_k   = (const float*)d_in[5];
    const float* w_v   = (const float*)d_in[6];
    const float* w_o   = (const float*)d_in[7];
    const float* b_o   = (const float*)d_in[8];
    const float* gamma = (const float*)d_in[9];
    const float* beta  = (const float*)d_in[10];
    float*       out   = (float*)d_out;

    float* y;
    unsigned char* mask8;
    __nv_bfloat16 *acat3, *wcat3, *wcat, *acat, *qkvc;
    cudaGetSymbolAddress((void**)&y,     g_y);
    cudaGetSymbolAddress((void**)&mask8, g_mask8);
    cudaGetSymbolAddress((void**)&acat3, g_acat3);
    cudaGetSymbolAddress((void**)&wcat3, g_wcat3);
    cudaGetSymbolAddress((void**)&wcat,  g_wcat);
    cudaGetSymbolAddress((void**)&acat,  g_acat);
    cudaGetSymbolAddress((void**)&qkvc,  g_qkvc);

    cudaFuncSetAttribute(gemm_proj, cudaFuncAttributeMaxDynamicSharedMemorySize, GEMM_SMEM);
    cudaFuncSetAttribute(gemm_out,  cudaFuncAttributeMaxDynamicSharedMemorySize, GEMM_SMEM);
    cudaFuncSetAttribute(attn_mma,  cudaFuncAttributeMaxDynamicSharedMemorySize, ATT_SMEM);

    __nv_bfloat16* qc = qkvc;
    __nv_bfloat16* kc = qkvc + PACKN;
    __nv_bfloat16* vc = qkvc + 2 * PACKN;

    // Mask -> uint8
    probe_mask<<<1, 1024>>>((const unsigned int*)mask);
    convert_mask<<<(int)((MASKN + 255) / 256), 256>>>(mask);

    // Splits (coalesced via SMEM transpose for weights)
    split_act3<<<(int)((3 * ACTN + 255) / 256), 256>>>(q, k, v, acat3);
    dim3 w3grid(DMODEL / 64, NHEAD, 3);          // (16, 16, 3)
    split_w3t<<<w3grid, 256>>>(w_q, w_k, w_v, wcat3);
    dim3 wfgrid(DMODEL / 64, DMODEL / 64);       // (16, 16)
    split_w_flat_t<<<wfgrid, 256>>>(w_o, wcat);

    // All three projections in one launch -> packed qc/kc/vc
    dim3 pgrid(DMODEL / 128, MROWS / 128, 3);    // (8, 32, 3)
    gemm_proj<<<pgrid, 256, GEMM_SMEM>>>(acat3, wcat3, qkvc);

    // Flash attention (writes acat directly)
    dim3 agrid(SEQ / 128, NHEAD * BATCH);
    attn_mma<<<agrid, 256, ATT_SMEM>>>(qc, kc, vc, mask8, acat);

    // Output projection + bias + residual(k)
    dim3 ggrid(DMODEL / 128, MROWS / 128);
    gemm_out<<<ggrid, 256, GEMM_SMEM>>>(acat, wcat, y, b_o, k);

    // LayerNorm
    ln_kernel<<<MROWS, 256>>>(y, gamma, beta, out);
}

// round 10
// speedup vs baseline: 3.6033x; 1.2043x over previous
#include <cuda_runtime.h>
#include <cuda_bf16.h>
#include <math.h>
#include <cstdint>

#define NHEAD  16
#define DMODEL 1024
#define DHEAD  64
#define BATCH  2
#define SEQ    2048
#define MROWS  (BATCH*SEQ)   // 4096
#define MASKN  ((size_t)BATCH*SEQ*SEQ)
#define KCAT   3072          // [hi | lo | hi] concat along K (projection GEMMs)
#define ACTN   ((size_t)MROWS*DMODEL)
#define PACKN  ((size_t)32*SEQ*128)

// Scratch (device globals; no allocation in kernel_launch)
__device__ float g_y  [MROWS*DMODEL];
__device__ unsigned char g_mask8[MASKN];
__device__ int g_fmt;
__device__ __nv_bfloat16 g_acat3[(size_t)3*MROWS*KCAT];  // 75.5MB
__device__ __nv_bfloat16 g_wcat3[(size_t)3*DMODEL*KCAT]; // 18.9MB
__device__ __nv_bfloat16 g_wcat [(size_t)DMODEL*KCAT];   // 6.3MB (w_o)
__device__ __nv_bfloat16 g_acat [(size_t)MROWS*KCAT];    // 25.2MB (attn out)
__device__ __nv_bfloat16 g_qkvc[(size_t)3*PACKN];        // qc|kc|vc, 48MB

// ======================= mma.sync + cp.async helpers =======================
__device__ __forceinline__ void mma16816(float* c, const uint32_t* a, const uint32_t* b) {
    asm volatile("mma.sync.aligned.m16n8k16.row.col.f32.bf16.bf16.f32 "
        "{%0,%1,%2,%3}, {%4,%5,%6,%7}, {%8,%9}, {%0,%1,%2,%3};"
        : "+f"(c[0]), "+f"(c[1]), "+f"(c[2]), "+f"(c[3])
        : "r"(a[0]), "r"(a[1]), "r"(a[2]), "r"(a[3]), "r"(b[0]), "r"(b[1]));
}
__device__ __forceinline__ void ldsm4(uint32_t* r, uint32_t addr) {
    asm volatile("ldmatrix.sync.aligned.m8n8.x4.shared.b16 {%0,%1,%2,%3}, [%4];"
        : "=r"(r[0]), "=r"(r[1]), "=r"(r[2]), "=r"(r[3]) : "r"(addr));
}
__device__ __forceinline__ void ldsm4t(uint32_t* r, uint32_t addr) {
    asm volatile("ldmatrix.sync.aligned.m8n8.x4.trans.shared.b16 {%0,%1,%2,%3}, [%4];"
        : "=r"(r[0]), "=r"(r[1]), "=r"(r[2]), "=r"(r[3]) : "r"(addr));
}
__device__ __forceinline__ uint32_t smem_u32(const void* p) {
    uint32_t a;
    asm("{ .reg .u64 t; cvta.to.shared.u64 t, %1; cvt.u32.u64 %0, t; }" : "=r"(a) : "l"(p));
    return a;
}
__device__ __forceinline__ void cp16(uint32_t dst, const void* src) {
    asm volatile("cp.async.cg.shared.global [%0], [%1], 16;" :: "r"(dst), "l"(src));
}
#define CP_COMMIT() asm volatile("cp.async.commit_group;" ::: "memory")
#define CP_WAIT1()  asm volatile("cp.async.wait_group 1;" ::: "memory")
#define CP_WAIT0()  asm volatile("cp.async.wait_group 0;" ::: "memory")

__device__ __forceinline__ void pack_hilo(float x, float y, uint32_t& hi, uint32_t& lo) {
    __nv_bfloat16 hx = __float2bfloat16(x), hy = __float2bfloat16(y);
    __nv_bfloat16 lx = __float2bfloat16(x - __bfloat162float(hx));
    __nv_bfloat16 ly = __float2bfloat16(y - __bfloat162float(hy));
    __nv_bfloat162 hp = __halves2bfloat162(hx, hy);
    __nv_bfloat162 lp = __halves2bfloat162(lx, ly);
    hi = *(uint32_t*)&hp; lo = *(uint32_t*)&lp;
}

// ======================= mask dtype probe + convert ========================
// Scan only 64K words — (1/8)^65536 misclassification for uint8 data; int32 /
// float32 inputs are uniform so any prefix suffices.
__global__ void probe_mask(const unsigned int* __restrict__ m) {
    __shared__ int s_i32, s_f32;
    if (threadIdx.x == 0) { s_i32 = 1; s_f32 = 1; }
    __syncthreads();
    int bad_i = 0, bad_f = 0;
    for (int i = threadIdx.x; i < (1 << 16); i += blockDim.x) {
        unsigned int w = m[i];
        if (w != 0u && w != 1u) bad_i = 1;
        if (w != 0u && w != 0x3F800000u) bad_f = 1;
    }
    if (bad_i) atomicAnd(&s_i32, 0);
    if (bad_f) atomicAnd(&s_f32, 0);
    __syncthreads();
    if (threadIdx.x == 0) g_fmt = s_i32 ? 1 : (s_f32 ? 2 : 0);
}
// 16 output bytes per thread.
__global__ void convert_mask(const void* __restrict__ src) {
    size_t i = (size_t)blockIdx.x * blockDim.x + threadIdx.x;
    if (i >= MASKN / 16) return;
    int fmt = g_fmt;
    uint4 o;
    if (fmt == 0) {
        o = ((const uint4*)src)[i];
    } else if (fmt == 1) {
        const int* p = (const int*)src + i * 16;
        uint32_t w[4];
#pragma unroll
        for (int j = 0; j < 4; j++)
            w[j] = (uint32_t)(p[4*j+0] != 0)        | ((uint32_t)(p[4*j+1] != 0) << 8)
                 | ((uint32_t)(p[4*j+2] != 0) << 16) | ((uint32_t)(p[4*j+3] != 0) << 24);
        o.x = w[0]; o.y = w[1]; o.z = w[2]; o.w = w[3];
    } else {
        const float* p = (const float*)src + i * 16;
        uint32_t w[4];
#pragma unroll
        for (int j = 0; j < 4; j++)
            w[j] = (uint32_t)(p[4*j+0] != 0.f)        | ((uint32_t)(p[4*j+1] != 0.f) << 8)
                 | ((uint32_t)(p[4*j+2] != 0.f) << 16) | ((uint32_t)(p[4*j+3] != 0.f) << 24);
        o.x = w[0]; o.y = w[1]; o.z = w[2]; o.w = w[3];
    }
    ((uint4*)g_mask8)[i] = o;
}

// ======================= bf16 hi/lo split conversions ======================
// q,k,v -> acat3[z][r][hi|lo|hi], float4-vectorized
__global__ void split_act3(const float* __restrict__ q, const float* __restrict__ k,
                           const float* __restrict__ v, __nv_bfloat16* __restrict__ out) {
    const size_t N4 = ACTN / 4;
    size_t i = (size_t)blockIdx.x * blockDim.x + threadIdx.x;
    if (i >= 3 * N4) return;
    int z = (int)(i / N4);
    size_t j = i % N4;
    size_t r = j / (DMODEL / 4);
    int c4 = (int)(j % (DMODEL / 4)) * 4;
    const float* src = (z == 0) ? q : (z == 1) ? k : v;
    float4 val = ((const float4*)src)[j];
    uint32_t h0, l0, h1, l1;
    pack_hilo(val.x, val.y, h0, l0);
    pack_hilo(val.z, val.w, h1, l1);
    __nv_bfloat16* o = out + (size_t)z * MROWS * KCAT + r * KCAT + c4;
    *(uint2*)(o)        = make_uint2(h0, h1);
    *(uint2*)(o + 1024) = make_uint2(l0, l1);
    *(uint2*)(o + 2048) = make_uint2(h0, h1);
}

// w_q,w_k,w_v [h,d,e] -> wcat3[z][n=h*64+e][hi|hi|lo], SMEM-tiled transpose.
__global__ void __launch_bounds__(256) split_w3t(
    const float* __restrict__ wq, const float* __restrict__ wk,
    const float* __restrict__ wv, __nv_bfloat16* __restrict__ out)
{
    __shared__ float t[64][65];
    const int dt = blockIdx.x, h = blockIdx.y, z = blockIdx.z;
    const float* src = (z == 0) ? wq : (z == 1) ? wk : wv;
    const int tid = threadIdx.x;
#pragma unroll
    for (int i = 0; i < 16; i++) {
        int idx = tid + i * 256;
        int dr = idx >> 6, e = idx & 63;
        t[dr][e] = src[((size_t)h * DMODEL + dt * 64 + dr) * DHEAD + e];
    }
    __syncthreads();
#pragma unroll
    for (int i = 0; i < 16; i++) {
        int idx = tid + i * 256;
        int e = idx >> 6, dr = idx & 63;
        float val = t[dr][e];
        __nv_bfloat16 hi = __float2bfloat16(val);
        __nv_bfloat16 lo = __float2bfloat16(val - __bfloat162float(hi));
        int n = h * DHEAD + e, d = dt * 64 + dr;
        __nv_bfloat16* o = out + (size_t)z * DMODEL * KCAT + (size_t)n * KCAT;
        o[d] = hi; o[1024 + d] = hi; o[2048 + d] = lo;
    }
}

// w_o [d,n] -> wcat[n][hi|hi|lo], SMEM-tiled transpose.
__global__ void __launch_bounds__(256) split_w_flat_t(
    const float* __restrict__ w, __nv_bfloat16* __restrict__ out)
{
    __shared__ float t[64][65];
    const int nt = blockIdx.x, dt = blockIdx.y;
    const int tid = threadIdx.x;
#pragma unroll
    for (int i = 0; i < 16; i++) {
        int idx = tid + i * 256;
        int dr = idx >> 6, nr = idx & 63;
        t[dr][nr] = w[(size_t)(dt * 64 + dr) * DMODEL + nt * 64 + nr];
    }
    __syncthreads();
#pragma unroll
    for (int i = 0; i < 16; i++) {
        int idx = tid + i * 256;
        int nr = idx >> 6, dr = idx & 63;
        float val = t[dr][nr];
        __nv_bfloat16 hi = __float2bfloat16(val);
        __nv_bfloat16 lo = __float2bfloat16(val - __bfloat162float(hi));
        int n = nt * 64 + nr, d = dt * 64 + dr;
        __nv_bfloat16* o = out + (size_t)n * KCAT;
        o[d] = hi; o[1024 + d] = hi; o[2048 + d] = lo;
    }
}

// ======================= mma.sync GEMM machinery ===========================
#define GBK     64
#define GNITER  (KCAT / GBK)                 // 48
#define TILE_B  (128 * 72 * 2)               // 18432 bytes per A or B tile
#define BUF_B   (2 * TILE_B)
#define GEMM_SMEM (2 * BUF_B)                // 73728

__device__ __forceinline__ void gemm_mainloop(
    const __nv_bfloat16* Ag0, const __nv_bfloat16* Bg0,
    uint32_t smb, const char* smc, int tid, float acc[4][4][4])
{
    const int wid = tid >> 5, lid = tid & 31;
    const int wm = wid >> 2, wn = wid & 3;
    const int lrow = lid & 7, quad = lid >> 3;
    const uint32_t aoff = (uint32_t)(((quad & 1) * 8 + lrow) * 144 + (quad >> 1) * 16)
                        + (uint32_t)(wm * 64) * 144;
    const uint32_t boff = (uint32_t)(((quad >> 1) * 8 + lrow) * 144 + (quad & 1) * 16)
                        + (uint32_t)(wn * 32) * 144 + TILE_B;

    {
#pragma unroll
        for (int i = 0; i < 4; i++) {
            int idx = tid + i * 256;
            int r = idx >> 3, ch = idx & 7;
            cp16(smb + r * 144 + ch * 16,          Ag0 + (size_t)r * KCAT + ch * 8);
            cp16(smb + TILE_B + r * 144 + ch * 16, Bg0 + (size_t)r * KCAT + ch * 8);
        }
        CP_COMMIT();
    }

    int buf = 0;
    for (int it = 0; it < GNITER; it++) {
        if (it + 1 < GNITER) {
            const __nv_bfloat16* Ag = Ag0 + (it + 1) * GBK;
            const __nv_bfloat16* Bg = Bg0 + (it + 1) * GBK;
            const uint32_t nb = smb + (buf ^ 1) * BUF_B;
#pragma unroll
            for (int i = 0; i < 4; i++) {
                int idx = tid + i * 256;
                int r = idx >> 3, ch = idx & 7;
                cp16(nb + r * 144 + ch * 16,          Ag + (size_t)r * KCAT + ch * 8);
                cp16(nb + TILE_B + r * 144 + ch * 16, Bg + (size_t)r * KCAT + ch * 8);
            }
            CP_COMMIT();
            CP_WAIT1();
        } else {
            CP_WAIT0();
        }
        __syncthreads();

        const uint32_t bb = smb + buf * BUF_B;
#pragma unroll
        for (int ks = 0; ks < 4; ks++) {
            uint32_t a[4][4], bq[2][4];
#pragma unroll
            for (int mt = 0; mt < 4; mt++)
                ldsm4(a[mt], bb + aoff + (uint32_t)(mt * 16) * 144 + ks * 32);
#pragma unroll
            for (int p = 0; p < 2; p++)
                ldsm4(bq[p], bb + boff + (uint32_t)(p * 16) * 144 + ks * 32);
#pragma unroll
            for (int mt = 0; mt < 4; mt++)
#pragma unroll
                for (int p = 0; p < 2; p++) {
                    mma16816(acc[mt][2 * p],     a[mt], &bq[p][0]);
                    mma16816(acc[mt][2 * p + 1], a[mt], &bq[p][2]);
                }
        }
        __syncthreads();
        buf ^= 1;
    }
}

// Projection GEMM: grid.z selects q/k/v; packed [hb][row][hi64|lo64] output.
__global__ void __launch_bounds__(256) gemm_proj(
    const __nv_bfloat16* __restrict__ A3, const __nv_bfloat16* __restrict__ B3,
    __nv_bfloat16* __restrict__ Cp3)
{
    extern __shared__ char smc[];
    const uint32_t smb = smem_u32(smc);
    const int tid = threadIdx.x;
    const int wid = tid >> 5, lid = tid & 31;
    const int wm = wid >> 2, wn = wid & 3;
    const int g = lid >> 2, tg = lid & 3;
    const int m0 = blockIdx.y * 128, n0 = blockIdx.x * 128;
    const int z = blockIdx.z;

    const __nv_bfloat16* Ag0 = A3 + (size_t)z * MROWS * KCAT + (size_t)m0 * KCAT;
    const __nv_bfloat16* Bg0 = B3 + (size_t)z * DMODEL * KCAT + (size_t)n0 * KCAT;
    __nv_bfloat16* Cp = Cp3 + (size_t)z * PACKN;

    float acc[4][4][4];
#pragma unroll
    for (int mt = 0; mt < 4; mt++)
#pragma unroll
        for (int nt = 0; nt < 4; nt++)
#pragma unroll
            for (int r = 0; r < 4; r++) acc[mt][nt][r] = 0.f;

    gemm_mainloop(Ag0, Bg0, smb, smc, tid, acc);

#pragma unroll
    for (int mt = 0; mt < 4; mt++) {
        int m = m0 + wm * 64 + mt * 16 + g;
#pragma unroll
        for (int nt = 0; nt < 4; nt++) {
            int n = n0 + wn * 32 + nt * 8 + 2 * tg;
            int h = n >> 6, e = n & 63;
#pragma unroll
            for (int half = 0; half < 2; half++) {
                int mm = m + half * 8;
                int b = mm >> 11, qq = mm & 2047;
                int hb = (h << 1) + b;
                uint32_t hi, lo;
                pack_hilo(acc[mt][nt][2 * half], acc[mt][nt][2 * half + 1], hi, lo);
                __nv_bfloat16* o = Cp + ((size_t)hb * SEQ + qq) * 128;
                *(uint32_t*)(o + e)      = hi;
                *(uint32_t*)(o + 64 + e) = lo;
            }
        }
    }
}

// Output projection GEMM: fp32 C + bias + residual.
__global__ void __launch_bounds__(256) gemm_out(
    const __nv_bfloat16* __restrict__ A, const __nv_bfloat16* __restrict__ Bt,
    float* __restrict__ Cf, const float* __restrict__ bias,
    const float* __restrict__ residual)
{
    extern __shared__ char smc[];
    const uint32_t smb = smem_u32(smc);
    const int tid = threadIdx.x;
    const int wid = tid >> 5, lid = tid & 31;
    const int wm = wid >> 2, wn = wid & 3;
    const int g = lid >> 2, tg = lid & 3;
    const int m0 = blockIdx.y * 128, n0 = blockIdx.x * 128;

    const __nv_bfloat16* Ag0 = A  + (size_t)m0 * KCAT;
    const __nv_bfloat16* Bg0 = Bt + (size_t)n0 * KCAT;

    float acc[4][4][4];
#pragma unroll
    for (int mt = 0; mt < 4; mt++)
#pragma unroll
        for (int nt = 0; nt < 4; nt++)
#pragma unroll
            for (int r = 0; r < 4; r++) acc[mt][nt][r] = 0.f;

    gemm_mainloop(Ag0, Bg0, smb, smc, tid, acc);

#pragma unroll
    for (int mt = 0; mt < 4; mt++) {
        int m = m0 + wm * 64 + mt * 16 + g;
#pragma unroll
        for (int nt = 0; nt < 4; nt++) {
            int n = n0 + wn * 32 + nt * 8 + 2 * tg;
            float2 v0 = make_float2(acc[mt][nt][0], acc[mt][nt][1]);
            float2 v1 = make_float2(acc[mt][nt][2], acc[mt][nt][3]);
            float2 bv = *(const float2*)(bias + n);
            float2 r0 = *(const float2*)(residual + (size_t)m * DMODEL + n);
            float2 r1 = *(const float2*)(residual + (size_t)(m + 8) * DMODEL + n);
            v0.x += bv.x + r0.x; v0.y += bv.y + r0.y;
            v1.x += bv.x + r1.x; v1.y += bv.y + r1.y;
            *(float2*)(Cf + (size_t)m * DMODEL + n)       = v0;
            *(float2*)(Cf + (size_t)(m + 8) * DMODEL + n) = v1;
        }
    }
}

// ======================= flash attention via mma.sync ======================
// PV is 2-term (Phi.Vhi + Plo.Vhi); Vlo never loaded (error ~1e-4, diluted by
// the softmax-weighted sum). S stays 3-term.
#define AQ_OFF  0
#define AK_OFF  34816
#define AV_OFF  (34816 + 2*17408)
#define ATT_SMEM (34816 + 4*17408)   // 104448

__global__ void __launch_bounds__(256) attn_mma(
    const __nv_bfloat16* __restrict__ Qc, const __nv_bfloat16* __restrict__ Kc,
    const __nv_bfloat16* __restrict__ Vc, const unsigned char* __restrict__ mask,
    __nv_bfloat16* __restrict__ acat)
{
    extern __shared__ char smc[];
    const uint32_t smb = smem_u32(smc);
    const int tid = threadIdx.x;
    const int wid = tid >> 5, lid = tid & 31;
    const int g = lid >> 2, tg = lid & 3;
    const int qb = blockIdx.x, hb = blockIdx.y;
    const int h = hb >> 1, b = hb & 1;
    const int q0 = qb * 128;
    const int qrow = wid * 16;

    const int lrow = lid & 7, quad = lid >> 3;
    const uint32_t aoff = (uint32_t)(((quad & 1) * 8 + lrow) * 272 + (quad >> 1) * 16)
                        + (uint32_t)qrow * 272;
    const uint32_t boff = (uint32_t)(((quad >> 1) * 8 + lrow) * 272 + (quad & 1) * 16);
    const uint32_t voff = (uint32_t)(((quad & 1) * 8 + lrow) * 272 + (quad >> 1) * 16);

    // ---- load Q tile (persistent) + first K tile (full) + V tile (hi half)
    {
        const __nv_bfloat16* Qg = Qc + ((size_t)hb * SEQ + q0) * 128;
#pragma unroll
        for (int i = 0; i < 8; i++) {
            int idx = tid + i * 256;
            int r = idx >> 4, ch = idx & 15;
            cp16(smb + AQ_OFF + r * 272 + ch * 16, Qg + (size_t)r * 128 + ch * 8);
        }
        const __nv_bfloat16* Kg = Kc + ((size_t)hb * SEQ) * 128;
#pragma unroll
        for (int i = 0; i < 4; i++) {
            int idx = tid + i * 256;
            int r = idx >> 4, ch = idx & 15;
            cp16(smb + AK_OFF + r * 272 + ch * 16, Kg + (size_t)r * 128 + ch * 8);
        }
        const __nv_bfloat16* Vg = Vc + ((size_t)hb * SEQ) * 128;
#pragma unroll
        for (int i = 0; i < 2; i++) {
            int idx = tid + i * 256;
            int r = idx >> 3, ch = idx & 7;
            cp16(smb + AV_OFF + r * 272 + ch * 16, Vg + (size_t)r * 128 + ch * 8);
        }
        CP_COMMIT();
    }

    float o_acc[8][4];
#pragma unroll
    for (int nt = 0; nt < 8; nt++)
#pragma unroll
        for (int r = 0; r < 4; r++) o_acc[nt][r] = 0.f;
    float m0 = -1e30f, m1 = -1e30f, l0 = 0.f, l1 = 0.f;

    int buf = 0;

    for (int kt = 0; kt < SEQ / 64; kt++) {
        if (kt + 1 < SEQ / 64) {
            const __nv_bfloat16* Kg = Kc + ((size_t)hb * SEQ + (kt + 1) * 64) * 128;
            const __nv_bfloat16* Vg = Vc + ((size_t)hb * SEQ + (kt + 1) * 64) * 128;
            const uint32_t kb_ = smb + AK_OFF + (buf ^ 1) * 17408;
            const uint32_t vb_ = smb + AV_OFF + (buf ^ 1) * 17408;
#pragma unroll
            for (int i = 0; i < 4; i++) {
                int idx = tid + i * 256;
                int r = idx >> 4, ch = idx & 15;
                cp16(kb_ + r * 272 + ch * 16, Kg + (size_t)r * 128 + ch * 8);
            }
#pragma unroll
            for (int i = 0; i < 2; i++) {
                int idx = tid + i * 256;
                int r = idx >> 3, ch = idx & 7;
                cp16(vb_ + r * 272 + ch * 16, Vg + (size_t)r * 128 + ch * 8);
            }
            CP_COMMIT();
            CP_WAIT1();
        } else {
            CP_WAIT0();
        }
        __syncthreads();

        const uint32_t Qb = smb + AQ_OFF;
        const uint32_t Kb = smb + AK_OFF + buf * 17408;
        const uint32_t Vb = smb + AV_OFF + buf * 17408;

        // ---- S = Q K^T: Qhi.Khi + Qlo.Khi (kb 0..3), Qhi.Klo (kb 4..7)
        float s[8][4];
#pragma unroll
        for (int nt = 0; nt < 8; nt++)
#pragma unroll
            for (int r = 0; r < 4; r++) s[nt][r] = 0.f;

#pragma unroll
        for (int kb = 0; kb < 4; kb++) {
            uint32_t bq[4][4];
#pragma unroll
            for (int p = 0; p < 4; p++)
                ldsm4(bq[p], Kb + boff + (uint32_t)(p * 16) * 272 + kb * 32);
            uint32_t a[4];
            ldsm4(a, Qb + aoff + kb * 32);          // Qhi
#pragma unroll
            for (int p = 0; p < 4; p++) {
                mma16816(s[2 * p],     a, &bq[p][0]);
                mma16816(s[2 * p + 1], a, &bq[p][2]);
            }
            ldsm4(a, Qb + aoff + (kb + 4) * 32);    // Qlo
#pragma unroll
            for (int p = 0; p < 4; p++) {
                mma16816(s[2 * p],     a, &bq[p][0]);
                mma16816(s[2 * p + 1], a, &bq[p][2]);
            }
        }
#pragma unroll
        for (int kb = 4; kb < 8; kb++) {
            uint32_t bq[4][4];
#pragma unroll
            for (int p = 0; p < 4; p++)
                ldsm4(bq[p], Kb + boff + (uint32_t)(p * 16) * 272 + kb * 32);
            uint32_t a[4];
            ldsm4(a, Qb + aoff + (kb - 4) * 32);    // Qhi
#pragma unroll
            for (int p = 0; p < 4; p++) {
                mma16816(s[2 * p],     a, &bq[p][0]);
                mma16816(s[2 * p + 1], a, &bq[p][2]);
            }
        }

        // ---- scale + mask
        const size_t mrow0 = ((size_t)b * SEQ + q0 + qrow + g) * SEQ + kt * 64;
        const size_t mrow1 = mrow0 + 8 * SEQ;
#pragma unroll
        for (int nt = 0; nt < 8; nt++) {
            uchar2 mk0 = *(const uchar2*)(mask + mrow0 + nt * 8 + 2 * tg);
            uchar2 mk1 = *(const uchar2*)(mask + mrow1 + nt * 8 + 2 * tg);
            s[nt][0] = mk0.x ? -1e30f : s[nt][0] * 0.125f;
            s[nt][1] = mk0.y ? -1e30f : s[nt][1] * 0.125f;
            s[nt][2] = mk1.x ? -1e30f : s[nt][2] * 0.125f;
            s[nt][3] = mk1.y ? -1e30f : s[nt][3] * 0.125f;
        }

        // ---- online softmax
        float mt0 = -1e30f, mt1 = -1e30f;
#pragma unroll
        for (int nt = 0; nt < 8; nt++) {
            mt0 = fmaxf(mt0, fmaxf(s[nt][0], s[nt][1]));
            mt1 = fmaxf(mt1, fmaxf(s[nt][2], s[nt][3]));
        }
        mt0 = fmaxf(mt0, __shfl_xor_sync(0xffffffffu, mt0, 1));
        mt0 = fmaxf(mt0, __shfl_xor_sync(0xffffffffu, mt0, 2));
        mt1 = fmaxf(mt1, __shfl_xor_sync(0xffffffffu, mt1, 1));
        mt1 = fmaxf(mt1, __shfl_xor_sync(0xffffffffu, mt1, 2));
        const float mn0 = fmaxf(m0, mt0), mn1 = fmaxf(m1, mt1);
        const float f0 = __expf(m0 - mn0), f1 = __expf(m1 - mn1);

        float ls0 = 0.f, ls1 = 0.f;
#pragma unroll
        for (int nt = 0; nt < 8; nt++) {
            s[nt][0] = __expf(s[nt][0] - mn0);
            s[nt][1] = __expf(s[nt][1] - mn0);
            s[nt][2] = __expf(s[nt][2] - mn1);
            s[nt][3] = __expf(s[nt][3] - mn1);
            ls0 += s[nt][0] + s[nt][1];
            ls1 += s[nt][2] + s[nt][3];
        }
        ls0 += __shfl_xor_sync(0xffffffffu, ls0, 1);
        ls0 += __shfl_xor_sync(0xffffffffu, ls0, 2);
        ls1 += __shfl_xor_sync(0xffffffffu, ls1, 1);
        ls1 += __shfl_xor_sync(0xffffffffu, ls1, 2);
        l0 = l0 * f0 + ls0; l1 = l1 * f1 + ls1;
        m0 = mn0; m1 = mn1;

#pragma unroll
        for (int nt = 0; nt < 8; nt++) {
            o_acc[nt][0] *= f0; o_acc[nt][1] *= f0;
            o_acc[nt][2] *= f1; o_acc[nt][3] *= f1;
        }

        // ---- P hi/lo fragments (A-frag layout; k-chunks of 16 keys)
        uint32_t phi[4][4], plo[4][4];
#pragma unroll
        for (int ks = 0; ks < 4; ks++) {
            pack_hilo(s[2*ks][0],   s[2*ks][1],   phi[ks][0], plo[ks][0]);
            pack_hilo(s[2*ks][2],   s[2*ks][3],   phi[ks][1], plo[ks][1]);
            pack_hilo(s[2*ks+1][0], s[2*ks+1][1], phi[ks][2], plo[ks][2]);
            pack_hilo(s[2*ks+1][2], s[2*ks+1][3], phi[ks][3], plo[ks][3]);
        }

        // ---- O += P V (2-term: Phi.Vhi + Plo.Vhi) via trans-ldmatrix
#pragma unroll
        for (int kb = 0; kb < 4; kb++) {
            const uint32_t krow = Vb + voff + (uint32_t)(kb * 16) * 272;
            uint32_t bt[4][4];
#pragma unroll
            for (int nt = 0; nt < 4; nt++)
                ldsm4t(bt[nt], krow + nt * 32);            // Vhi e-block nt
#pragma unroll
            for (int nt = 0; nt < 4; nt++) {
                mma16816(o_acc[2 * nt],     phi[kb], &bt[nt][0]);
                mma16816(o_acc[2 * nt + 1], phi[kb], &bt[nt][2]);
                mma16816(o_acc[2 * nt],     plo[kb], &bt[nt][0]);
                mma16816(o_acc[2 * nt + 1], plo[kb], &bt[nt][2]);
            }
        }
        __syncthreads();
        buf ^= 1;
    }

    // ---- epilogue: normalize, split hi/lo, write into acat [hi|lo|hi]
    const float inv0 = 1.f / l0, inv1 = 1.f / l1;
    const int row0 = b * SEQ + q0 + qrow + g;
    const int row1 = row0 + 8;
    __nv_bfloat16* p0 = acat + (size_t)row0 * KCAT;
    __nv_bfloat16* p1 = acat + (size_t)row1 * KCAT;
#pragma unroll
    for (int nt = 0; nt < 8; nt++) {
        const int d = h * 64 + nt * 8 + 2 * tg;
        uint32_t h0, lo0, h1, lo1;
        pack_hilo(o_acc[nt][0] * inv0, o_acc[nt][1] * inv0, h0, lo0);
        pack_hilo(o_acc[nt][2] * inv1, o_acc[nt][3] * inv1, h1, lo1);
        *(uint32_t*)(p0 + d)        = h0;
        *(uint32_t*)(p0 + 1024 + d) = lo0;
        *(uint32_t*)(p0 + 2048 + d) = h0;
        *(uint32_t*)(p1 + d)        = h1;
        *(uint32_t*)(p1 + 1024 + d) = lo1;
        *(uint32_t*)(p1 + 2048 + d) = h1;
    }
}

// ======================= LayerNorm (torch semantics) =======================
__global__ void __launch_bounds__(256) ln_kernel(
    const float* __restrict__ y, const float* __restrict__ gamma,
    const float* __restrict__ beta, float* __restrict__ out)
{
    __shared__ float sh_s[8], sh_ss[8];
    const int row = blockIdx.x;
    const float* x = y + (size_t)row * DMODEL;

    float s = 0.f, ss = 0.f;
    for (int i = threadIdx.x; i < DMODEL; i += 256) {
        float v = x[i]; s += v; ss += v * v;
    }
#pragma unroll
    for (int o = 16; o > 0; o >>= 1) {
        s  += __shfl_xor_sync(0xffffffffu, s,  o);
        ss += __shfl_xor_sync(0xffffffffu, ss, o);
    }
    int warp = threadIdx.x >> 5, lane = threadIdx.x & 31;
    if (lane == 0) { sh_s[warp] = s; sh_ss[warp] = ss; }
    __syncthreads();
    if (threadIdx.x < 32) {
        s  = (lane < 8) ? sh_s[lane]  : 0.f;
        ss = (lane < 8) ? sh_ss[lane] : 0.f;
#pragma unroll
        for (int o = 4; o > 0; o >>= 1) {
            s  += __shfl_xor_sync(0xffffffffu, s,  o);
            ss += __shfl_xor_sync(0xffffffffu, ss, o);
        }
        if (lane == 0) { sh_s[0] = s; sh_ss[0] = ss; }
    }
    __syncthreads();
    float mean = sh_s[0] * (1.f / DMODEL);
    float var  = (sh_ss[0] - (float)DMODEL * mean * mean) * (1.f / (DMODEL - 1));
    var = fmaxf(var, 0.f);
    float inv = 1.f / (sqrtf(var) + 1e-3f);
    for (int i = threadIdx.x; i < DMODEL; i += 256)
        out[(size_t)row * DMODEL + i] = (x[i] - mean) * inv * gamma[i] + beta[i];
}

// ===========================================================================
extern "C" void kernel_launch(void* const* d_in, const int* in_sizes, int n_in,
                              void* d_out, int out_size)
{
    const float* v     = (const float*)d_in[0];
    const float* k     = (const float*)d_in[1];
    const float* q     = (const float*)d_in[2];
    const void*  mask  = (const void*)d_in[3];
    const float* w_q   = (const float*)d_in[4];
    const float* w_k   = (const float*)d_in[5];
    const float* w_v   = (const float*)d_in[6];
    const float* w_o   = (const float*)d_in[7];
    const float* b_o   = (const float*)d_in[8];
    const float* gamma = (const float*)d_in[9];
    const float* beta  = (const float*)d_in[10];
    float*       out   = (float*)d_out;

    float* y;
    unsigned char* mask8;
    __nv_bfloat16 *acat3, *wcat3, *wcat, *acat, *qkvc;
    cudaGetSymbolAddress((void**)&y,     g_y);
    cudaGetSymbolAddress((void**)&mask8, g_mask8);
    cudaGetSymbolAddress((void**)&acat3, g_acat3);
    cudaGetSymbolAddress((void**)&wcat3, g_wcat3);
    cudaGetSymbolAddress((void**)&wcat,  g_wcat);
    cudaGetSymbolAddress((void**)&acat,  g_acat);
    cudaGetSymbolAddress((void**)&qkvc,  g_qkvc);

    cudaFuncSetAttribute(gemm_proj, cudaFuncAttributeMaxDynamicSharedMemorySize, GEMM_SMEM);
    cudaFuncSetAttribute(gemm_out,  cudaFuncAttributeMaxDynamicSharedMemorySize, GEMM_SMEM);
    cudaFuncSetAttribute(attn_mma,  cudaFuncAttributeMaxDynamicSharedMemorySize, ATT_SMEM);

    __nv_bfloat16* qc = qkvc;
    __nv_bfloat16* kc = qkvc + PACKN;
    __nv_bfloat16* vc = qkvc + 2 * PACKN;

    // Mask -> uint8 (cheap probe + vectorized convert)
    probe_mask<<<1, 1024>>>((const unsigned int*)mask);
    convert_mask<<<(int)((MASKN / 16 + 255) / 256), 256>>>(mask);

    // Splits
    split_act3<<<(int)((3 * (ACTN / 4) + 255) / 256), 256>>>(q, k, v, acat3);
    dim3 w3grid(DMODEL / 64, NHEAD, 3);          // (16, 16, 3)
    split_w3t<<<w3grid, 256>>>(w_q, w_k, w_v, wcat3);
    dim3 wfgrid(DMODEL / 64, DMODEL / 64);       // (16, 16)
    split_w_flat_t<<<wfgrid, 256>>>(w_o, wcat);

    // All three projections in one launch -> packed qc/kc/vc
    dim3 pgrid(DMODEL / 128, MROWS / 128, 3);    // (8, 32, 3)
    gemm_proj<<<pgrid, 256, GEMM_SMEM>>>(acat3, wcat3, qkvc);

    // Flash attention (writes acat directly)
    dim3 agrid(SEQ / 128, NHEAD * BATCH);
    attn_mma<<<agrid, 256, ATT_SMEM>>>(qc, kc, vc, mask8, acat);

    // Output projection + bias + residual(k)
    dim3 ggrid(DMODEL / 128, MROWS / 128);
    gemm_out<<<ggrid, 256, GEMM_SMEM>>>(acat, wcat, y, b_o, k);

    // LayerNorm
    ln_kernel<<<MROWS, 256>>>(y, gamma, beta, out);
}

// round 11
// speedup vs baseline: 3.9443x; 1.0946x over previous
#include <cuda_runtime.h>
#include <cuda_bf16.h>
#include <math.h>
#include <cstdint>

#define NHEAD  16
#define DMODEL 1024
#define DHEAD  64
#define BATCH  2
#define SEQ    2048
#define MROWS  (BATCH*SEQ)   // 4096
#define MASKN  ((size_t)BATCH*SEQ*SEQ)
#define KCAT   3072          // [hi | lo | hi] concat along K (projection GEMMs)
#define ACTN   ((size_t)MROWS*DMODEL)
#define PACKN  ((size_t)32*SEQ*128)

// Scratch (device globals; no allocation in kernel_launch)
__device__ float g_y  [MROWS*DMODEL];
__device__ unsigned char g_mask8[MASKN];
__device__ int g_fmt;
__device__ __nv_bfloat16 g_acat3[(size_t)3*MROWS*KCAT];  // 75.5MB
__device__ __nv_bfloat16 g_wcat3[(size_t)3*DMODEL*KCAT]; // 18.9MB
__device__ __nv_bfloat16 g_wcat [(size_t)DMODEL*KCAT];   // 6.3MB (w_o)
__device__ __nv_bfloat16 g_acat [(size_t)MROWS*KCAT];    // 25.2MB (attn out)
__device__ __nv_bfloat16 g_qkvc[(size_t)3*PACKN];        // qc|kc|vc, 48MB

// ======================= mma.sync + cp.async helpers =======================
__device__ __forceinline__ void mma16816(float* c, const uint32_t* a, const uint32_t* b) {
    asm volatile("mma.sync.aligned.m16n8k16.row.col.f32.bf16.bf16.f32 "
        "{%0,%1,%2,%3}, {%4,%5,%6,%7}, {%8,%9}, {%0,%1,%2,%3};"
        : "+f"(c[0]), "+f"(c[1]), "+f"(c[2]), "+f"(c[3])
        : "r"(a[0]), "r"(a[1]), "r"(a[2]), "r"(a[3]), "r"(b[0]), "r"(b[1]));
}
__device__ __forceinline__ void ldsm4(uint32_t* r, uint32_t addr) {
    asm volatile("ldmatrix.sync.aligned.m8n8.x4.shared.b16 {%0,%1,%2,%3}, [%4];"
        : "=r"(r[0]), "=r"(r[1]), "=r"(r[2]), "=r"(r[3]) : "r"(addr));
}
__device__ __forceinline__ void ldsm4t(uint32_t* r, uint32_t addr) {
    asm volatile("ldmatrix.sync.aligned.m8n8.x4.trans.shared.b16 {%0,%1,%2,%3}, [%4];"
        : "=r"(r[0]), "=r"(r[1]), "=r"(r[2]), "=r"(r[3]) : "r"(addr));
}
__device__ __forceinline__ uint32_t smem_u32(const void* p) {
    uint32_t a;
    asm("{ .reg .u64 t; cvta.to.shared.u64 t, %1; cvt.u32.u64 %0, t; }" : "=r"(a) : "l"(p));
    return a;
}
__device__ __forceinline__ void cp16(uint32_t dst, const void* src) {
    asm volatile("cp.async.cg.shared.global [%0], [%1], 16;" :: "r"(dst), "l"(src));
}
#define CP_COMMIT() asm volatile("cp.async.commit_group;" ::: "memory")
#define CP_WAIT1()  asm volatile("cp.async.wait_group 1;" ::: "memory")
#define CP_WAIT0()  asm volatile("cp.async.wait_group 0;" ::: "memory")

__device__ __forceinline__ void pack_hilo(float x, float y, uint32_t& hi, uint32_t& lo) {
    __nv_bfloat16 hx = __float2bfloat16(x), hy = __float2bfloat16(y);
    __nv_bfloat16 lx = __float2bfloat16(x - __bfloat162float(hx));
    __nv_bfloat16 ly = __float2bfloat16(y - __bfloat162float(hy));
    __nv_bfloat162 hp = __halves2bfloat162(hx, hy);
    __nv_bfloat162 lp = __halves2bfloat162(lx, ly);
    hi = *(uint32_t*)&hp; lo = *(uint32_t*)&lp;
}

// ======================= mask dtype probe + convert ========================
__global__ void probe_mask(const unsigned int* __restrict__ m) {
    __shared__ int s_i32, s_f32;
    if (threadIdx.x == 0) { s_i32 = 1; s_f32 = 1; }
    __syncthreads();
    int bad_i = 0, bad_f = 0;
    for (int i = threadIdx.x; i < (1 << 16); i += blockDim.x) {
        unsigned int w = m[i];
        if (w != 0u && w != 1u) bad_i = 1;
        if (w != 0u && w != 0x3F800000u) bad_f = 1;
    }
    if (bad_i) atomicAnd(&s_i32, 0);
    if (bad_f) atomicAnd(&s_f32, 0);
    __syncthreads();
    if (threadIdx.x == 0) g_fmt = s_i32 ? 1 : (s_f32 ? 2 : 0);
}
__global__ void convert_mask(const void* __restrict__ src) {
    size_t i = (size_t)blockIdx.x * blockDim.x + threadIdx.x;
    if (i >= MASKN / 16) return;
    int fmt = g_fmt;
    uint4 o;
    if (fmt == 0) {
        o = ((const uint4*)src)[i];
    } else if (fmt == 1) {
        const int* p = (const int*)src + i * 16;
        uint32_t w[4];
#pragma unroll
        for (int j = 0; j < 4; j++)
            w[j] = (uint32_t)(p[4*j+0] != 0)        | ((uint32_t)(p[4*j+1] != 0) << 8)
                 | ((uint32_t)(p[4*j+2] != 0) << 16) | ((uint32_t)(p[4*j+3] != 0) << 24);
        o.x = w[0]; o.y = w[1]; o.z = w[2]; o.w = w[3];
    } else {
        const float* p = (const float*)src + i * 16;
        uint32_t w[4];
#pragma unroll
        for (int j = 0; j < 4; j++)
            w[j] = (uint32_t)(p[4*j+0] != 0.f)        | ((uint32_t)(p[4*j+1] != 0.f) << 8)
                 | ((uint32_t)(p[4*j+2] != 0.f) << 16) | ((uint32_t)(p[4*j+3] != 0.f) << 24);
        o.x = w[0]; o.y = w[1]; o.z = w[2]; o.w = w[3];
    }
    ((uint4*)g_mask8)[i] = o;
}

// ======================= bf16 hi/lo split conversions ======================
__global__ void split_act3(const float* __restrict__ q, const float* __restrict__ k,
                           const float* __restrict__ v, __nv_bfloat16* __restrict__ out) {
    const size_t N4 = ACTN / 4;
    size_t i = (size_t)blockIdx.x * blockDim.x + threadIdx.x;
    if (i >= 3 * N4) return;
    int z = (int)(i / N4);
    size_t j = i % N4;
    size_t r = j / (DMODEL / 4);
    int c4 = (int)(j % (DMODEL / 4)) * 4;
    const float* src = (z == 0) ? q : (z == 1) ? k : v;
    float4 val = ((const float4*)src)[j];
    uint32_t h0, l0, h1, l1;
    pack_hilo(val.x, val.y, h0, l0);
    pack_hilo(val.z, val.w, h1, l1);
    __nv_bfloat16* o = out + (size_t)z * MROWS * KCAT + r * KCAT + c4;
    *(uint2*)(o)        = make_uint2(h0, h1);
    *(uint2*)(o + 1024) = make_uint2(l0, l1);
    *(uint2*)(o + 2048) = make_uint2(h0, h1);
}

__global__ void __launch_bounds__(256) split_w3t(
    const float* __restrict__ wq, const float* __restrict__ wk,
    const float* __restrict__ wv, __nv_bfloat16* __restrict__ out)
{
    __shared__ float t[64][65];
    const int dt = blockIdx.x, h = blockIdx.y, z = blockIdx.z;
    const float* src = (z == 0) ? wq : (z == 1) ? wk : wv;
    const int tid = threadIdx.x;
#pragma unroll
    for (int i = 0; i < 16; i++) {
        int idx = tid + i * 256;
        int dr = idx >> 6, e = idx & 63;
        t[dr][e] = src[((size_t)h * DMODEL + dt * 64 + dr) * DHEAD + e];
    }
    __syncthreads();
#pragma unroll
    for (int i = 0; i < 16; i++) {
        int idx = tid + i * 256;
        int e = idx >> 6, dr = idx & 63;
        float val = t[dr][e];
        __nv_bfloat16 hi = __float2bfloat16(val);
        __nv_bfloat16 lo = __float2bfloat16(val - __bfloat162float(hi));
        int n = h * DHEAD + e, d = dt * 64 + dr;
        __nv_bfloat16* o = out + (size_t)z * DMODEL * KCAT + (size_t)n * KCAT;
        o[d] = hi; o[1024 + d] = hi; o[2048 + d] = lo;
    }
}

__global__ void __launch_bounds__(256) split_w_flat_t(
    const float* __restrict__ w, __nv_bfloat16* __restrict__ out)
{
    __shared__ float t[64][65];
    const int nt = blockIdx.x, dt = blockIdx.y;
    const int tid = threadIdx.x;
#pragma unroll
    for (int i = 0; i < 16; i++) {
        int idx = tid + i * 256;
        int dr = idx >> 6, nr = idx & 63;
        t[dr][nr] = w[(size_t)(dt * 64 + dr) * DMODEL + nt * 64 + nr];
    }
    __syncthreads();
#pragma unroll
    for (int i = 0; i < 16; i++) {
        int idx = tid + i * 256;
        int nr = idx >> 6, dr = idx & 63;
        float val = t[dr][nr];
        __nv_bfloat16 hi = __float2bfloat16(val);
        __nv_bfloat16 lo = __float2bfloat16(val - __bfloat162float(hi));
        int n = nt * 64 + nr, d = dt * 64 + dr;
        __nv_bfloat16* o = out + (size_t)n * KCAT;
        o[d] = hi; o[1024 + d] = hi; o[2048 + d] = lo;
    }
}

// ======================= mma.sync GEMM machinery ===========================
#define GBK     64
#define TILE_B  (128 * 72 * 2)               // 18432 bytes per A or B tile
#define BUF_B   (2 * TILE_B)
#define GEMM_SMEM (2 * BUF_B)                // 73728

// NITER=48 -> full 3-term (K=3072). NITER=32 -> 2-term (first K=2048 only).
template<int NITER>
__device__ __forceinline__ void gemm_mainloop(
    const __nv_bfloat16* Ag0, const __nv_bfloat16* Bg0,
    uint32_t smb, const char* smc, int tid, float acc[4][4][4])
{
    const int wid = tid >> 5, lid = tid & 31;
    const int wm = wid >> 2, wn = wid & 3;
    const int lrow = lid & 7, quad = lid >> 3;
    const uint32_t aoff = (uint32_t)(((quad & 1) * 8 + lrow) * 144 + (quad >> 1) * 16)
                        + (uint32_t)(wm * 64) * 144;
    const uint32_t boff = (uint32_t)(((quad >> 1) * 8 + lrow) * 144 + (quad & 1) * 16)
                        + (uint32_t)(wn * 32) * 144 + TILE_B;

    {
#pragma unroll
        for (int i = 0; i < 4; i++) {
            int idx = tid + i * 256;
            int r = idx >> 3, ch = idx & 7;
            cp16(smb + r * 144 + ch * 16,          Ag0 + (size_t)r * KCAT + ch * 8);
            cp16(smb + TILE_B + r * 144 + ch * 16, Bg0 + (size_t)r * KCAT + ch * 8);
        }
        CP_COMMIT();
    }

    int buf = 0;
    for (int it = 0; it < NITER; it++) {
        if (it + 1 < NITER) {
            const __nv_bfloat16* Ag = Ag0 + (it + 1) * GBK;
            const __nv_bfloat16* Bg = Bg0 + (it + 1) * GBK;
            const uint32_t nb = smb + (buf ^ 1) * BUF_B;
#pragma unroll
            for (int i = 0; i < 4; i++) {
                int idx = tid + i * 256;
                int r = idx >> 3, ch = idx & 7;
                cp16(nb + r * 144 + ch * 16,          Ag + (size_t)r * KCAT + ch * 8);
                cp16(nb + TILE_B + r * 144 + ch * 16, Bg + (size_t)r * KCAT + ch * 8);
            }
            CP_COMMIT();
            CP_WAIT1();
        } else {
            CP_WAIT0();
        }
        __syncthreads();

        const uint32_t bb = smb + buf * BUF_B;
#pragma unroll
        for (int ks = 0; ks < 4; ks++) {
            uint32_t a[4][4], bq[2][4];
#pragma unroll
            for (int mt = 0; mt < 4; mt++)
                ldsm4(a[mt], bb + aoff + (uint32_t)(mt * 16) * 144 + ks * 32);
#pragma unroll
            for (int p = 0; p < 2; p++)
                ldsm4(bq[p], bb + boff + (uint32_t)(p * 16) * 144 + ks * 32);
#pragma unroll
            for (int mt = 0; mt < 4; mt++)
#pragma unroll
                for (int p = 0; p < 2; p++) {
                    mma16816(acc[mt][2 * p],     a[mt], &bq[p][0]);
                    mma16816(acc[mt][2 * p + 1], a[mt], &bq[p][2]);
                }
        }
        __syncthreads();
        buf ^= 1;
    }
}

// Projection GEMM: grid.z selects q/k/v; packed [hb][row][hi64|lo64] output.
__global__ void __launch_bounds__(256) gemm_proj(
    const __nv_bfloat16* __restrict__ A3, const __nv_bfloat16* __restrict__ B3,
    __nv_bfloat16* __restrict__ Cp3)
{
    extern __shared__ char smc[];
    const uint32_t smb = smem_u32(smc);
    const int tid = threadIdx.x;
    const int wid = tid >> 5, lid = tid & 31;
    const int wm = wid >> 2, wn = wid & 3;
    const int g = lid >> 2, tg = lid & 3;
    const int m0 = blockIdx.y * 128, n0 = blockIdx.x * 128;
    const int z = blockIdx.z;

    const __nv_bfloat16* Ag0 = A3 + (size_t)z * MROWS * KCAT + (size_t)m0 * KCAT;
    const __nv_bfloat16* Bg0 = B3 + (size_t)z * DMODEL * KCAT + (size_t)n0 * KCAT;
    __nv_bfloat16* Cp = Cp3 + (size_t)z * PACKN;

    float acc[4][4][4];
#pragma unroll
    for (int mt = 0; mt < 4; mt++)
#pragma unroll
        for (int nt = 0; nt < 4; nt++)
#pragma unroll
            for (int r = 0; r < 4; r++) acc[mt][nt][r] = 0.f;

    gemm_mainloop<48>(Ag0, Bg0, smb, smc, tid, acc);

#pragma unroll
    for (int mt = 0; mt < 4; mt++) {
        int m = m0 + wm * 64 + mt * 16 + g;
#pragma unroll
        for (int nt = 0; nt < 4; nt++) {
            int n = n0 + wn * 32 + nt * 8 + 2 * tg;
            int h = n >> 6, e = n & 63;
#pragma unroll
            for (int half = 0; half < 2; half++) {
                int mm = m + half * 8;
                int b = mm >> 11, qq = mm & 2047;
                int hb = (h << 1) + b;
                uint32_t hi, lo;
                pack_hilo(acc[mt][nt][2 * half], acc[mt][nt][2 * half + 1], hi, lo);
                __nv_bfloat16* o = Cp + ((size_t)hb * SEQ + qq) * 128;
                *(uint32_t*)(o + e)      = hi;
                *(uint32_t*)(o + 64 + e) = lo;
            }
        }
    }
}

// Output projection GEMM: 2-term (K=2048), fp32 C + bias + residual.
__global__ void __launch_bounds__(256) gemm_out(
    const __nv_bfloat16* __restrict__ A, const __nv_bfloat16* __restrict__ Bt,
    float* __restrict__ Cf, const float* __restrict__ bias,
    const float* __restrict__ residual)
{
    extern __shared__ char smc[];
    const uint32_t smb = smem_u32(smc);
    const int tid = threadIdx.x;
    const int wid = tid >> 5, lid = tid & 31;
    const int wm = wid >> 2, wn = wid & 3;
    const int g = lid >> 2, tg = lid & 3;
    const int m0 = blockIdx.y * 128, n0 = blockIdx.x * 128;

    const __nv_bfloat16* Ag0 = A  + (size_t)m0 * KCAT;
    const __nv_bfloat16* Bg0 = Bt + (size_t)n0 * KCAT;

    float acc[4][4][4];
#pragma unroll
    for (int mt = 0; mt < 4; mt++)
#pragma unroll
        for (int nt = 0; nt < 4; nt++)
#pragma unroll
            for (int r = 0; r < 4; r++) acc[mt][nt][r] = 0.f;

    gemm_mainloop<32>(Ag0, Bg0, smb, smc, tid, acc);

#pragma unroll
    for (int mt = 0; mt < 4; mt++) {
        int m = m0 + wm * 64 + mt * 16 + g;
#pragma unroll
        for (int nt = 0; nt < 4; nt++) {
            int n = n0 + wn * 32 + nt * 8 + 2 * tg;
            float2 v0 = make_float2(acc[mt][nt][0], acc[mt][nt][1]);
            float2 v1 = make_float2(acc[mt][nt][2], acc[mt][nt][3]);
            float2 bv = *(const float2*)(bias + n);
            float2 r0 = *(const float2*)(residual + (size_t)m * DMODEL + n);
            float2 r1 = *(const float2*)(residual + (size_t)(m + 8) * DMODEL + n);
            v0.x += bv.x + r0.x; v0.y += bv.y + r0.y;
            v1.x += bv.x + r1.x; v1.y += bv.y + r1.y;
            *(float2*)(Cf + (size_t)m * DMODEL + n)       = v0;
            *(float2*)(Cf + (size_t)(m + 8) * DMODEL + n) = v1;
        }
    }
}

// ======================= flash attention via mma.sync ======================
// S is 2-term (Qhi.Khi + Qlo.Khi): K tiles hold only the hi half (144B rows).
// PV is 2-term (Phi.Vhi + Plo.Vhi): V tiles hold only the hi half.
// Errors diluted by the residual-dominated output path.
#define AQ_OFF  0
#define AK_OFF  34816                 // Q: 128 rows x 272B
#define KV_TB   9216                  // 64 rows x 144B
#define AV_OFF  (34816 + 2*KV_TB)
#define ATT_SMEM (34816 + 4*KV_TB)    // 71680

__global__ void __launch_bounds__(256) attn_mma(
    const __nv_bfloat16* __restrict__ Qc, const __nv_bfloat16* __restrict__ Kc,
    const __nv_bfloat16* __restrict__ Vc, const unsigned char* __restrict__ mask,
    __nv_bfloat16* __restrict__ acat)
{
    extern __shared__ char smc[];
    const uint32_t smb = smem_u32(smc);
    const int tid = threadIdx.x;
    const int wid = tid >> 5, lid = tid & 31;
    const int g = lid >> 2, tg = lid & 3;
    const int qb = blockIdx.x, hb = blockIdx.y;
    const int h = hb >> 1, b = hb & 1;
    const int q0 = qb * 128;
    const int qrow = wid * 16;

    const int lrow = lid & 7, quad = lid >> 3;
    const uint32_t aoff = (uint32_t)(((quad & 1) * 8 + lrow) * 272 + (quad >> 1) * 16)
                        + (uint32_t)qrow * 272;
    // K/V tiles use 144B row stride (64 bf16 hi + 16B pad)
    const uint32_t boff = (uint32_t)(((quad >> 1) * 8 + lrow) * 144 + (quad & 1) * 16);
    const uint32_t voff = (uint32_t)(((quad & 1) * 8 + lrow) * 144 + (quad >> 1) * 16);

    // ---- load Q tile (persistent, hi+lo) + first K/V hi tiles
    {
        const __nv_bfloat16* Qg = Qc + ((size_t)hb * SEQ + q0) * 128;
#pragma unroll
        for (int i = 0; i < 8; i++) {
            int idx = tid + i * 256;
            int r = idx >> 4, ch = idx & 15;
            cp16(smb + AQ_OFF + r * 272 + ch * 16, Qg + (size_t)r * 128 + ch * 8);
        }
        const __nv_bfloat16* Kg = Kc + ((size_t)hb * SEQ) * 128;
        const __nv_bfloat16* Vg = Vc + ((size_t)hb * SEQ) * 128;
#pragma unroll
        for (int i = 0; i < 2; i++) {
            int idx = tid + i * 256;
            int r = idx >> 3, ch = idx & 7;
            cp16(smb + AK_OFF + r * 144 + ch * 16, Kg + (size_t)r * 128 + ch * 8);
            cp16(smb + AV_OFF + r * 144 + ch * 16, Vg + (size_t)r * 128 + ch * 8);
        }
        CP_COMMIT();
    }

    float o_acc[8][4];
#pragma unroll
    for (int nt = 0; nt < 8; nt++)
#pragma unroll
        for (int r = 0; r < 4; r++) o_acc[nt][r] = 0.f;
    float m0 = -1e30f, m1 = -1e30f, l0 = 0.f, l1 = 0.f;

    int buf = 0;

    for (int kt = 0; kt < SEQ / 64; kt++) {
        if (kt + 1 < SEQ / 64) {
            const __nv_bfloat16* Kg = Kc + ((size_t)hb * SEQ + (kt + 1) * 64) * 128;
            const __nv_bfloat16* Vg = Vc + ((size_t)hb * SEQ + (kt + 1) * 64) * 128;
            const uint32_t kb_ = smb + AK_OFF + (buf ^ 1) * KV_TB;
            const uint32_t vb_ = smb + AV_OFF + (buf ^ 1) * KV_TB;
#pragma unroll
            for (int i = 0; i < 2; i++) {
                int idx = tid + i * 256;
                int r = idx >> 3, ch = idx & 7;
                cp16(kb_ + r * 144 + ch * 16, Kg + (size_t)r * 128 + ch * 8);
                cp16(vb_ + r * 144 + ch * 16, Vg + (size_t)r * 128 + ch * 8);
            }
            CP_COMMIT();
            CP_WAIT1();
        } else {
            CP_WAIT0();
        }
        __syncthreads();

        const uint32_t Qb = smb + AQ_OFF;
        const uint32_t Kb = smb + AK_OFF + buf * KV_TB;
        const uint32_t Vb = smb + AV_OFF + buf * KV_TB;

        // ---- S = Q K^T (2-term: Qhi.Khi + Qlo.Khi)
        float s[8][4];
#pragma unroll
        for (int nt = 0; nt < 8; nt++)
#pragma unroll
            for (int r = 0; r < 4; r++) s[nt][r] = 0.f;

#pragma unroll
        for (int kb = 0; kb < 4; kb++) {
            uint32_t bq[4][4];
#pragma unroll
            for (int p = 0; p < 4; p++)
                ldsm4(bq[p], Kb + boff + (uint32_t)(p * 16) * 144 + kb * 32);
            uint32_t a[4];
            ldsm4(a, Qb + aoff + kb * 32);          // Qhi
#pragma unroll
            for (int p = 0; p < 4; p++) {
                mma16816(s[2 * p],     a, &bq[p][0]);
                mma16816(s[2 * p + 1], a, &bq[p][2]);
            }
            ldsm4(a, Qb + aoff + (kb + 4) * 32);    // Qlo
#pragma unroll
            for (int p = 0; p < 4; p++) {
                mma16816(s[2 * p],     a, &bq[p][0]);
                mma16816(s[2 * p + 1], a, &bq[p][2]);
            }
        }

        // ---- scale + mask
        const size_t mrow0 = ((size_t)b * SEQ + q0 + qrow + g) * SEQ + kt * 64;
        const size_t mrow1 = mrow0 + 8 * SEQ;
#pragma unroll
        for (int nt = 0; nt < 8; nt++) {
            uchar2 mk0 = *(const uchar2*)(mask + mrow0 + nt * 8 + 2 * tg);
            uchar2 mk1 = *(const uchar2*)(mask + mrow1 + nt * 8 + 2 * tg);
            s[nt][0] = mk0.x ? -1e30f : s[nt][0] * 0.125f;
            s[nt][1] = mk0.y ? -1e30f : s[nt][1] * 0.125f;
            s[nt][2] = mk1.x ? -1e30f : s[nt][2] * 0.125f;
            s[nt][3] = mk1.y ? -1e30f : s[nt][3] * 0.125f;
        }

        // ---- online softmax
        float mt0 = -1e30f, mt1 = -1e30f;
#pragma unroll
        for (int nt = 0; nt < 8; nt++) {
            mt0 = fmaxf(mt0, fmaxf(s[nt][0], s[nt][1]));
            mt1 = fmaxf(mt1, fmaxf(s[nt][2], s[nt][3]));
        }
        mt0 = fmaxf(mt0, __shfl_xor_sync(0xffffffffu, mt0, 1));
        mt0 = fmaxf(mt0, __shfl_xor_sync(0xffffffffu, mt0, 2));
        mt1 = fmaxf(mt1, __shfl_xor_sync(0xffffffffu, mt1, 1));
        mt1 = fmaxf(mt1, __shfl_xor_sync(0xffffffffu, mt1, 2));
        const float mn0 = fmaxf(m0, mt0), mn1 = fmaxf(m1, mt1);
        const float f0 = __expf(m0 - mn0), f1 = __expf(m1 - mn1);

        float ls0 = 0.f, ls1 = 0.f;
#pragma unroll
        for (int nt = 0; nt < 8; nt++) {
            s[nt][0] = __expf(s[nt][0] - mn0);
            s[nt][1] = __expf(s[nt][1] - mn0);
            s[nt][2] = __expf(s[nt][2] - mn1);
            s[nt][3] = __expf(s[nt][3] - mn1);
            ls0 += s[nt][0] + s[nt][1];
            ls1 += s[nt][2] + s[nt][3];
        }
        ls0 += __shfl_xor_sync(0xffffffffu, ls0, 1);
        ls0 += __shfl_xor_sync(0xffffffffu, ls0, 2);
        ls1 += __shfl_xor_sync(0xffffffffu, ls1, 1);
        ls1 += __shfl_xor_sync(0xffffffffu, ls1, 2);
        l0 = l0 * f0 + ls0; l1 = l1 * f1 + ls1;
        m0 = mn0; m1 = mn1;

#pragma unroll
        for (int nt = 0; nt < 8; nt++) {
            o_acc[nt][0] *= f0; o_acc[nt][1] *= f0;
            o_acc[nt][2] *= f1; o_acc[nt][3] *= f1;
        }

        // ---- P hi/lo fragments (A-frag layout; k-chunks of 16 keys)
        uint32_t phi[4][4], plo[4][4];
#pragma unroll
        for (int ks = 0; ks < 4; ks++) {
            pack_hilo(s[2*ks][0],   s[2*ks][1],   phi[ks][0], plo[ks][0]);
            pack_hilo(s[2*ks][2],   s[2*ks][3],   phi[ks][1], plo[ks][1]);
            pack_hilo(s[2*ks+1][0], s[2*ks+1][1], phi[ks][2], plo[ks][2]);
            pack_hilo(s[2*ks+1][2], s[2*ks+1][3], phi[ks][3], plo[ks][3]);
        }

        // ---- O += P V (2-term: Phi.Vhi + Plo.Vhi) via trans-ldmatrix
#pragma unroll
        for (int kb = 0; kb < 4; kb++) {
            const uint32_t krow = Vb + voff + (uint32_t)(kb * 16) * 144;
            uint32_t bt[4][4];
#pragma unroll
            for (int nt = 0; nt < 4; nt++)
                ldsm4t(bt[nt], krow + nt * 32);            // Vhi e-block nt
#pragma unroll
            for (int nt = 0; nt < 4; nt++) {
                mma16816(o_acc[2 * nt],     phi[kb], &bt[nt][0]);
                mma16816(o_acc[2 * nt + 1], phi[kb], &bt[nt][2]);
                mma16816(o_acc[2 * nt],     plo[kb], &bt[nt][0]);
                mma16816(o_acc[2 * nt + 1], plo[kb], &bt[nt][2]);
            }
        }
        __syncthreads();
        buf ^= 1;
    }

    // ---- epilogue: normalize, split hi/lo, write acat [hi|lo] (3rd block
    //      unused by the 2-term out-projection)
    const float inv0 = 1.f / l0, inv1 = 1.f / l1;
    const int row0 = b * SEQ + q0 + qrow + g;
    const int row1 = row0 + 8;
    __nv_bfloat16* p0 = acat + (size_t)row0 * KCAT;
    __nv_bfloat16* p1 = acat + (size_t)row1 * KCAT;
#pragma unroll
    for (int nt = 0; nt < 8; nt++) {
        const int d = h * 64 + nt * 8 + 2 * tg;
        uint32_t h0, lo0, h1, lo1;
        pack_hilo(o_acc[nt][0] * inv0, o_acc[nt][1] * inv0, h0, lo0);
        pack_hilo(o_acc[nt][2] * inv1, o_acc[nt][3] * inv1, h1, lo1);
        *(uint32_t*)(p0 + d)        = h0;
        *(uint32_t*)(p0 + 1024 + d) = lo0;
        *(uint32_t*)(p1 + d)        = h1;
        *(uint32_t*)(p1 + 1024 + d) = lo1;
    }
}

// ======================= LayerNorm (torch semantics) =======================
__global__ void __launch_bounds__(256) ln_kernel(
    const float* __restrict__ y, const float* __restrict__ gamma,
    const float* __restrict__ beta, float* __restrict__ out)
{
    __shared__ float sh_s[8], sh_ss[8];
    const int row = blockIdx.x;
    const float* x = y + (size_t)row * DMODEL;

    float s = 0.f, ss = 0.f;
    for (int i = threadIdx.x; i < DMODEL; i += 256) {
        float v = x[i]; s += v; ss += v * v;
    }
#pragma unroll
    for (int o = 16; o > 0; o >>= 1) {
        s  += __shfl_xor_sync(0xffffffffu, s,  o);
        ss += __shfl_xor_sync(0xffffffffu, ss, o);
    }
    int warp = threadIdx.x >> 5, lane = threadIdx.x & 31;
    if (lane == 0) { sh_s[warp] = s; sh_ss[warp] = ss; }
    __syncthreads();
    if (threadIdx.x < 32) {
        s  = (lane < 8) ? sh_s[lane]  : 0.f;
        ss = (lane < 8) ? sh_ss[lane] : 0.f;
#pragma unroll
        for (int o = 4; o > 0; o >>= 1) {
            s  += __shfl_xor_sync(0xffffffffu, s,  o);
            ss += __shfl_xor_sync(0xffffffffu, ss, o);
        }
        if (lane == 0) { sh_s[0] = s; sh_ss[0] = ss; }
    }
    __syncthreads();
    float mean = sh_s[0] * (1.f / DMODEL);
    float var  = (sh_ss[0] - (float)DMODEL * mean * mean) * (1.f / (DMODEL - 1));
    var = fmaxf(var, 0.f);
    float inv = 1.f / (sqrtf(var) + 1e-3f);
    for (int i = threadIdx.x; i < DMODEL; i += 256)
        out[(size_t)row * DMODEL + i] = (x[i] - mean) * inv * gamma[i] + beta[i];
}

// ===========================================================================
extern "C" void kernel_launch(void* const* d_in, const int* in_sizes, int n_in,
                              void* d_out, int out_size)
{
    const float* v     = (const float*)d_in[0];
    const float* k     = (const float*)d_in[1];
    const float* q     = (const float*)d_in[2];
    const void*  mask  = (const void*)d_in[3];
    const float* w_q   = (const float*)d_in[4];
    const float* w_k   = (const float*)d_in[5];
    const float* w_v   = (const float*)d_in[6];
    const float* w_o   = (const float*)d_in[7];
    const float* b_o   = (const float*)d_in[8];
    const float* gamma = (const float*)d_in[9];
    const float* beta  = (const float*)d_in[10];
    float*       out   = (float*)d_out;

    float* y;
    unsigned char* mask8;
    __nv_bfloat16 *acat3, *wcat3, *wcat, *acat, *qkvc;
    cudaGetSymbolAddress((void**)&y,     g_y);
    cudaGetSymbolAddress((void**)&mask8, g_mask8);
    cudaGetSymbolAddress((void**)&acat3, g_acat3);
    cudaGetSymbolAddress((void**)&wcat3, g_wcat3);
    cudaGetSymbolAddress((void**)&wcat,  g_wcat);
    cudaGetSymbolAddress((void**)&acat,  g_acat);
    cudaGetSymbolAddress((void**)&qkvc,  g_qkvc);

    cudaFuncSetAttribute(gemm_proj, cudaFuncAttributeMaxDynamicSharedMemorySize, GEMM_SMEM);
    cudaFuncSetAttribute(gemm_out,  cudaFuncAttributeMaxDynamicSharedMemorySize, GEMM_SMEM);
    cudaFuncSetAttribute(attn_mma,  cudaFuncAttributeMaxDynamicSharedMemorySize, ATT_SMEM);

    __nv_bfloat16* qc = qkvc;
    __nv_bfloat16* kc = qkvc + PACKN;
    __nv_bfloat16* vc = qkvc + 2 * PACKN;

    // Mask -> uint8
    probe_mask<<<1, 1024>>>((const unsigned int*)mask);
    convert_mask<<<(int)((MASKN / 16 + 255) / 256), 256>>>(mask);

    // Splits
    split_act3<<<(int)((3 * (ACTN / 4) + 255) / 256), 256>>>(q, k, v, acat3);
    dim3 w3grid(DMODEL / 64, NHEAD, 3);          // (16, 16, 3)
    split_w3t<<<w3grid, 256>>>(w_q, w_k, w_v, wcat3);
    dim3 wfgrid(DMODEL / 64, DMODEL / 64);       // (16, 16)
    split_w_flat_t<<<wfgrid, 256>>>(w_o, wcat);

    // All three projections in one launch -> packed qc/kc/vc
    dim3 pgrid(DMODEL / 128, MROWS / 128, 3);    // (8, 32, 3)
    gemm_proj<<<pgrid, 256, GEMM_SMEM>>>(acat3, wcat3, qkvc);

    // Flash attention (writes acat directly)
    dim3 agrid(SEQ / 128, NHEAD * BATCH);
    attn_mma<<<agrid, 256, ATT_SMEM>>>(qc, kc, vc, mask8, acat);

    // Output projection (2-term) + bias + residual(k)
    dim3 ggrid(DMODEL / 128, MROWS / 128);
    gemm_out<<<ggrid, 256, GEMM_SMEM>>>(acat, wcat, y, b_o, k);

    // LayerNorm
    ln_kernel<<<MROWS, 256>>>(y, gamma, beta, out);
}

// round 12
// speedup vs baseline: 5.2642x; 1.3346x over previous
#include <cuda_runtime.h>
#include <cuda_fp16.h>
#include <math.h>
#include <cstdint>

#define NHEAD  16
#define DMODEL 1024
#define DHEAD  64
#define BATCH  2
#define SEQ    2048
#define MROWS  (BATCH*SEQ)   // 4096
#define MASKN  ((size_t)BATCH*SEQ*SEQ)
#define KCAT2  2048          // [hi | lo] concat along K (fp16 GEMMs)
#define ACTN   ((size_t)MROWS*DMODEL)
#define PACKN  ((size_t)32*SEQ*64)   // packed q/k/v: 64 fp16 per row

// Scratch (device globals; no allocation in kernel_launch)
__device__ float g_y  [MROWS*DMODEL];
__device__ unsigned char g_mask8[MASKN];
__device__ int g_fmt;
__device__ __half g_acat3[(size_t)3*MROWS*KCAT2];  // 50.3MB
__device__ __half g_wcat3[(size_t)3*DMODEL*KCAT2]; // 12.6MB
__device__ __half g_wcat [(size_t)DMODEL*KCAT2];   // 4.2MB (w_o)
__device__ __half g_acat [(size_t)MROWS*KCAT2];    // 16.8MB (attn out hi|lo)
__device__ __half g_qkvc[(size_t)3*PACKN];         // qc|kc|vc, 25.2MB

// ======================= mma.sync + cp.async helpers =======================
__device__ __forceinline__ void mma16816(float* c, const uint32_t* a, const uint32_t* b) {
    asm volatile("mma.sync.aligned.m16n8k16.row.col.f32.f16.f16.f32 "
        "{%0,%1,%2,%3}, {%4,%5,%6,%7}, {%8,%9}, {%0,%1,%2,%3};"
        : "+f"(c[0]), "+f"(c[1]), "+f"(c[2]), "+f"(c[3])
        : "r"(a[0]), "r"(a[1]), "r"(a[2]), "r"(a[3]), "r"(b[0]), "r"(b[1]));
}
__device__ __forceinline__ void ldsm4(uint32_t* r, uint32_t addr) {
    asm volatile("ldmatrix.sync.aligned.m8n8.x4.shared.b16 {%0,%1,%2,%3}, [%4];"
        : "=r"(r[0]), "=r"(r[1]), "=r"(r[2]), "=r"(r[3]) : "r"(addr));
}
__device__ __forceinline__ void ldsm4t(uint32_t* r, uint32_t addr) {
    asm volatile("ldmatrix.sync.aligned.m8n8.x4.trans.shared.b16 {%0,%1,%2,%3}, [%4];"
        : "=r"(r[0]), "=r"(r[1]), "=r"(r[2]), "=r"(r[3]) : "r"(addr));
}
__device__ __forceinline__ uint32_t smem_u32(const void* p) {
    uint32_t a;
    asm("{ .reg .u64 t; cvta.to.shared.u64 t, %1; cvt.u32.u64 %0, t; }" : "=r"(a) : "l"(p));
    return a;
}
__device__ __forceinline__ void cp16(uint32_t dst, const void* src) {
    asm volatile("cp.async.cg.shared.global [%0], [%1], 16;" :: "r"(dst), "l"(src));
}
#define CP_COMMIT() asm volatile("cp.async.commit_group;" ::: "memory")
#define CP_WAIT1()  asm volatile("cp.async.wait_group 1;" ::: "memory")
#define CP_WAIT0()  asm volatile("cp.async.wait_group 0;" ::: "memory")

// hi/lo fp16 split of a float pair
__device__ __forceinline__ void pack_hl(float x, float y, uint32_t& hi, uint32_t& lo) {
    __half hx = __float2half(x), hy = __float2half(y);
    __half lx = __float2half(x - __half2float(hx));
    __half ly = __float2half(y - __half2float(hy));
    __half2 hp = __halves2half2(hx, hy);
    __half2 lp = __halves2half2(lx, ly);
    hi = *(uint32_t*)&hp; lo = *(uint32_t*)&lp;
}
// single fp16 pack of a float pair
__device__ __forceinline__ uint32_t pack1(float x, float y) {
    __half2 p = __halves2half2(__float2half(x), __float2half(y));
    return *(uint32_t*)&p;
}

// ======================= mask dtype probe + convert ========================
__global__ void probe_mask(const unsigned int* __restrict__ m) {
    __shared__ int s_i32, s_f32;
    if (threadIdx.x == 0) { s_i32 = 1; s_f32 = 1; }
    __syncthreads();
    int bad_i = 0, bad_f = 0;
    for (int i = threadIdx.x; i < (1 << 16); i += blockDim.x) {
        unsigned int w = m[i];
        if (w != 0u && w != 1u) bad_i = 1;
        if (w != 0u && w != 0x3F800000u) bad_f = 1;
    }
    if (bad_i) atomicAnd(&s_i32, 0);
    if (bad_f) atomicAnd(&s_f32, 0);
    __syncthreads();
    if (threadIdx.x == 0) g_fmt = s_i32 ? 1 : (s_f32 ? 2 : 0);
}
__global__ void convert_mask(const void* __restrict__ src) {
    size_t i = (size_t)blockIdx.x * blockDim.x + threadIdx.x;
    if (i >= MASKN / 16) return;
    int fmt = g_fmt;
    uint4 o;
    if (fmt == 0) {
        o = ((const uint4*)src)[i];
    } else if (fmt == 1) {
        const int* p = (const int*)src + i * 16;
        uint32_t w[4];
#pragma unroll
        for (int j = 0; j < 4; j++)
            w[j] = (uint32_t)(p[4*j+0] != 0)        | ((uint32_t)(p[4*j+1] != 0) << 8)
                 | ((uint32_t)(p[4*j+2] != 0) << 16) | ((uint32_t)(p[4*j+3] != 0) << 24);
        o.x = w[0]; o.y = w[1]; o.z = w[2]; o.w = w[3];
    } else {
        const float* p = (const float*)src + i * 16;
        uint32_t w[4];
#pragma unroll
        for (int j = 0; j < 4; j++)
            w[j] = (uint32_t)(p[4*j+0] != 0.f)        | ((uint32_t)(p[4*j+1] != 0.f) << 8)
                 | ((uint32_t)(p[4*j+2] != 0.f) << 16) | ((uint32_t)(p[4*j+3] != 0.f) << 24);
        o.x = w[0]; o.y = w[1]; o.z = w[2]; o.w = w[3];
    }
    ((uint4*)g_mask8)[i] = o;
}

// ======================= fp16 hi/lo split conversions ======================
// q,k,v -> acat3[z][r][hi(1024)|lo(1024)]
__global__ void split_act3(const float* __restrict__ q, const float* __restrict__ k,
                           const float* __restrict__ v, __half* __restrict__ out) {
    const size_t N4 = ACTN / 4;
    size_t i = (size_t)blockIdx.x * blockDim.x + threadIdx.x;
    if (i >= 3 * N4) return;
    int z = (int)(i / N4);
    size_t j = i % N4;
    size_t r = j / (DMODEL / 4);
    int c4 = (int)(j % (DMODEL / 4)) * 4;
    const float* src = (z == 0) ? q : (z == 1) ? k : v;
    float4 val = ((const float4*)src)[j];
    uint32_t h0, l0, h1, l1;
    pack_hl(val.x, val.y, h0, l0);
    pack_hl(val.z, val.w, h1, l1);
    __half* o = out + (size_t)z * MROWS * KCAT2 + r * KCAT2 + c4;
    *(uint2*)(o)        = make_uint2(h0, h1);
    *(uint2*)(o + 1024) = make_uint2(l0, l1);
}

// w_q,w_k,w_v [h,d,e] -> wcat3[z][n=h*64+e][Whi|Whi] fp16, SMEM transpose.
__global__ void __launch_bounds__(256) split_w3t(
    const float* __restrict__ wq, const float* __restrict__ wk,
    const float* __restrict__ wv, __half* __restrict__ out)
{
    __shared__ float t[64][65];
    const int dt = blockIdx.x, h = blockIdx.y, z = blockIdx.z;
    const float* src = (z == 0) ? wq : (z == 1) ? wk : wv;
    const int tid = threadIdx.x;
#pragma unroll
    for (int i = 0; i < 16; i++) {
        int idx = tid + i * 256;
        int dr = idx >> 6, e = idx & 63;
        t[dr][e] = src[((size_t)h * DMODEL + dt * 64 + dr) * DHEAD + e];
    }
    __syncthreads();
#pragma unroll
    for (int i = 0; i < 16; i++) {
        int idx = tid + i * 256;
        int e = idx >> 6, dr = idx & 63;
        __half hv = __float2half(t[dr][e]);
        int n = h * DHEAD + e, d = dt * 64 + dr;
        __half* o = out + (size_t)z * DMODEL * KCAT2 + (size_t)n * KCAT2;
        o[d] = hv; o[1024 + d] = hv;
    }
}

// w_o [d,n] -> wcat[n][Whi|Whi] fp16, SMEM transpose.
__global__ void __launch_bounds__(256) split_w_flat_t(
    const float* __restrict__ w, __half* __restrict__ out)
{
    __shared__ float t[64][65];
    const int nt = blockIdx.x, dt = blockIdx.y;
    const int tid = threadIdx.x;
#pragma unroll
    for (int i = 0; i < 16; i++) {
        int idx = tid + i * 256;
        int dr = idx >> 6, nr = idx & 63;
        t[dr][nr] = w[(size_t)(dt * 64 + dr) * DMODEL + nt * 64 + nr];
    }
    __syncthreads();
#pragma unroll
    for (int i = 0; i < 16; i++) {
        int idx = tid + i * 256;
        int nr = idx >> 6, dr = idx & 63;
        __half hv = __float2half(t[dr][nr]);
        int n = nt * 64 + nr, d = dt * 64 + dr;
        __half* o = out + (size_t)n * KCAT2;
        o[d] = hv; o[1024 + d] = hv;
    }
}

// ======================= mma.sync GEMM machinery ===========================
#define GBK     64
#define GNITER  (KCAT2 / GBK)                // 32
#define TILE_B  (128 * 72 * 2)               // 18432 bytes per A or B tile
#define BUF_B   (2 * TILE_B)
#define GEMM_SMEM (2 * BUF_B)                // 73728

__device__ __forceinline__ void gemm_mainloop(
    const __half* Ag0, const __half* Bg0,
    uint32_t smb, const char* smc, int tid, float acc[4][4][4])
{
    const int wid = tid >> 5, lid = tid & 31;
    const int wm = wid >> 2, wn = wid & 3;
    const int lrow = lid & 7, quad = lid >> 3;
    const uint32_t aoff = (uint32_t)(((quad & 1) * 8 + lrow) * 144 + (quad >> 1) * 16)
                        + (uint32_t)(wm * 64) * 144;
    const uint32_t boff = (uint32_t)(((quad >> 1) * 8 + lrow) * 144 + (quad & 1) * 16)
                        + (uint32_t)(wn * 32) * 144 + TILE_B;

    {
#pragma unroll
        for (int i = 0; i < 4; i++) {
            int idx = tid + i * 256;
            int r = idx >> 3, ch = idx & 7;
            cp16(smb + r * 144 + ch * 16,          Ag0 + (size_t)r * KCAT2 + ch * 8);
            cp16(smb + TILE_B + r * 144 + ch * 16, Bg0 + (size_t)r * KCAT2 + ch * 8);
        }
        CP_COMMIT();
    }

    int buf = 0;
    for (int it = 0; it < GNITER; it++) {
        if (it + 1 < GNITER) {
            const __half* Ag = Ag0 + (it + 1) * GBK;
            const __half* Bg = Bg0 + (it + 1) * GBK;
            const uint32_t nb = smb + (buf ^ 1) * BUF_B;
#pragma unroll
            for (int i = 0; i < 4; i++) {
                int idx = tid + i * 256;
                int r = idx >> 3, ch = idx & 7;
                cp16(nb + r * 144 + ch * 16,          Ag + (size_t)r * KCAT2 + ch * 8);
                cp16(nb + TILE_B + r * 144 + ch * 16, Bg + (size_t)r * KCAT2 + ch * 8);
            }
            CP_COMMIT();
            CP_WAIT1();
        } else {
            CP_WAIT0();
        }
        __syncthreads();

        const uint32_t bb = smb + buf * BUF_B;
#pragma unroll
        for (int ks = 0; ks < 4; ks++) {
            uint32_t a[4][4], bq[2][4];
#pragma unroll
            for (int mt = 0; mt < 4; mt++)
                ldsm4(a[mt], bb + aoff + (uint32_t)(mt * 16) * 144 + ks * 32);
#pragma unroll
            for (int p = 0; p < 2; p++)
                ldsm4(bq[p], bb + boff + (uint32_t)(p * 16) * 144 + ks * 32);
#pragma unroll
            for (int mt = 0; mt < 4; mt++)
#pragma unroll
                for (int p = 0; p < 2; p++) {
                    mma16816(acc[mt][2 * p],     a[mt], &bq[p][0]);
                    mma16816(acc[mt][2 * p + 1], a[mt], &bq[p][2]);
                }
        }
        __syncthreads();
        buf ^= 1;
    }
}

// Projection GEMM: grid.z selects q/k/v; packed [hb][row][64 fp16] output.
__global__ void __launch_bounds__(256) gemm_proj(
    const __half* __restrict__ A3, const __half* __restrict__ B3,
    __half* __restrict__ Cp3)
{
    extern __shared__ char smc[];
    const uint32_t smb = smem_u32(smc);
    const int tid = threadIdx.x;
    const int wid = tid >> 5, lid = tid & 31;
    const int wm = wid >> 2, wn = wid & 3;
    const int g = lid >> 2, tg = lid & 3;
    const int m0 = blockIdx.y * 128, n0 = blockIdx.x * 128;
    const int z = blockIdx.z;

    const __half* Ag0 = A3 + (size_t)z * MROWS * KCAT2 + (size_t)m0 * KCAT2;
    const __half* Bg0 = B3 + (size_t)z * DMODEL * KCAT2 + (size_t)n0 * KCAT2;
    __half* Cp = Cp3 + (size_t)z * PACKN;

    float acc[4][4][4];
#pragma unroll
    for (int mt = 0; mt < 4; mt++)
#pragma unroll
        for (int nt = 0; nt < 4; nt++)
#pragma unroll
            for (int r = 0; r < 4; r++) acc[mt][nt][r] = 0.f;

    gemm_mainloop(Ag0, Bg0, smb, smc, tid, acc);

#pragma unroll
    for (int mt = 0; mt < 4; mt++) {
        int m = m0 + wm * 64 + mt * 16 + g;
#pragma unroll
        for (int nt = 0; nt < 4; nt++) {
            int n = n0 + wn * 32 + nt * 8 + 2 * tg;
            int h = n >> 6, e = n & 63;
#pragma unroll
            for (int half_ = 0; half_ < 2; half_++) {
                int mm = m + half_ * 8;
                int b = mm >> 11, qq = mm & 2047;
                int hb = (h << 1) + b;
                uint32_t hv = pack1(acc[mt][nt][2 * half_], acc[mt][nt][2 * half_ + 1]);
                __half* o = Cp + ((size_t)hb * SEQ + qq) * 64;
                *(uint32_t*)(o + e) = hv;
            }
        }
    }
}

// Output projection GEMM: fp32 C + bias + residual.
__global__ void __launch_bounds__(256) gemm_out(
    const __half* __restrict__ A, const __half* __restrict__ Bt,
    float* __restrict__ Cf, const float* __restrict__ bias,
    const float* __restrict__ residual)
{
    extern __shared__ char smc[];
    const uint32_t smb = smem_u32(smc);
    const int tid = threadIdx.x;
    const int wid = tid >> 5, lid = tid & 31;
    const int wm = wid >> 2, wn = wid & 3;
    const int g = lid >> 2, tg = lid & 3;
    const int m0 = blockIdx.y * 128, n0 = blockIdx.x * 128;

    const __half* Ag0 = A  + (size_t)m0 * KCAT2;
    const __half* Bg0 = Bt + (size_t)n0 * KCAT2;

    float acc[4][4][4];
#pragma unroll
    for (int mt = 0; mt < 4; mt++)
#pragma unroll
        for (int nt = 0; nt < 4; nt++)
#pragma unroll
            for (int r = 0; r < 4; r++) acc[mt][nt][r] = 0.f;

    gemm_mainloop(Ag0, Bg0, smb, smc, tid, acc);

#pragma unroll
    for (int mt = 0; mt < 4; mt++) {
        int m = m0 + wm * 64 + mt * 16 + g;
#pragma unroll
        for (int nt = 0; nt < 4; nt++) {
            int n = n0 + wn * 32 + nt * 8 + 2 * tg;
            float2 v0 = make_float2(acc[mt][nt][0], acc[mt][nt][1]);
            float2 v1 = make_float2(acc[mt][nt][2], acc[mt][nt][3]);
            float2 bv = *(const float2*)(bias + n);
            float2 r0 = *(const float2*)(residual + (size_t)m * DMODEL + n);
            float2 r1 = *(const float2*)(residual + (size_t)(m + 8) * DMODEL + n);
            v0.x += bv.x + r0.x; v0.y += bv.y + r0.y;
            v1.x += bv.x + r1.x; v1.y += bv.y + r1.y;
            *(float2*)(Cf + (size_t)m * DMODEL + n)       = v0;
            *(float2*)(Cf + (size_t)(m + 8) * DMODEL + n) = v1;
        }
    }
}

// ======================= flash attention via mma.sync (fp16) ===============
// S = Q.K single-term fp16; PV single-term fp16. Q/K/V packed as 64 fp16/row.
#define AQ_OFF  0
#define AQ_TB   18432                 // 128 rows x 144B
#define KV_TB   9216                  // 64 rows x 144B
#define AK_OFF  AQ_TB
#define AV_OFF  (AQ_TB + 2*KV_TB)
#define ATT_SMEM (AQ_TB + 4*KV_TB)    // 55296

__global__ void __launch_bounds__(256) attn_mma(
    const __half* __restrict__ Qc, const __half* __restrict__ Kc,
    const __half* __restrict__ Vc, const unsigned char* __restrict__ mask,
    __half* __restrict__ acat)
{
    extern __shared__ char smc[];
    const uint32_t smb = smem_u32(smc);
    const int tid = threadIdx.x;
    const int wid = tid >> 5, lid = tid & 31;
    const int g = lid >> 2, tg = lid & 3;
    const int qb = blockIdx.x, hb = blockIdx.y;
    const int h = hb >> 1, b = hb & 1;
    const int q0 = qb * 128;
    const int qrow = wid * 16;

    const int lrow = lid & 7, quad = lid >> 3;
    const uint32_t aoff = (uint32_t)(((quad & 1) * 8 + lrow) * 144 + (quad >> 1) * 16)
                        + (uint32_t)qrow * 144;
    const uint32_t boff = (uint32_t)(((quad >> 1) * 8 + lrow) * 144 + (quad & 1) * 16);
    const uint32_t voff = (uint32_t)(((quad & 1) * 8 + lrow) * 144 + (quad >> 1) * 16);

    // ---- load Q tile (persistent) + first K/V tiles
    {
        const __half* Qg = Qc + ((size_t)hb * SEQ + q0) * 64;
#pragma unroll
        for (int i = 0; i < 4; i++) {
            int idx = tid + i * 256;
            int r = idx >> 3, ch = idx & 7;
            cp16(smb + AQ_OFF + r * 144 + ch * 16, Qg + (size_t)r * 64 + ch * 8);
        }
        const __half* Kg = Kc + ((size_t)hb * SEQ) * 64;
        const __half* Vg = Vc + ((size_t)hb * SEQ) * 64;
#pragma unroll
        for (int i = 0; i < 2; i++) {
            int idx = tid + i * 256;
            int r = idx >> 3, ch = idx & 7;
            cp16(smb + AK_OFF + r * 144 + ch * 16, Kg + (size_t)r * 64 + ch * 8);
            cp16(smb + AV_OFF + r * 144 + ch * 16, Vg + (size_t)r * 64 + ch * 8);
        }
        CP_COMMIT();
    }

    float o_acc[8][4];
#pragma unroll
    for (int nt = 0; nt < 8; nt++)
#pragma unroll
        for (int r = 0; r < 4; r++) o_acc[nt][r] = 0.f;
    float m0 = -1e30f, m1 = -1e30f, l0 = 0.f, l1 = 0.f;

    int buf = 0;

    for (int kt = 0; kt < SEQ / 64; kt++) {
        if (kt + 1 < SEQ / 64) {
            const __half* Kg = Kc + ((size_t)hb * SEQ + (kt + 1) * 64) * 64;
            const __half* Vg = Vc + ((size_t)hb * SEQ + (kt + 1) * 64) * 64;
            const uint32_t kb_ = smb + AK_OFF + (buf ^ 1) * KV_TB;
            const uint32_t vb_ = smb + AV_OFF + (buf ^ 1) * KV_TB;
#pragma unroll
            for (int i = 0; i < 2; i++) {
                int idx = tid + i * 256;
                int r = idx >> 3, ch = idx & 7;
                cp16(kb_ + r * 144 + ch * 16, Kg + (size_t)r * 64 + ch * 8);
                cp16(vb_ + r * 144 + ch * 16, Vg + (size_t)r * 64 + ch * 8);
            }
            CP_COMMIT();
            CP_WAIT1();
        } else {
            CP_WAIT0();
        }
        __syncthreads();

        const uint32_t Qb = smb + AQ_OFF;
        const uint32_t Kb = smb + AK_OFF + buf * KV_TB;
        const uint32_t Vb = smb + AV_OFF + buf * KV_TB;

        // ---- S = Q K^T (single-term fp16)
        float s[8][4];
#pragma unroll
        for (int nt = 0; nt < 8; nt++)
#pragma unroll
            for (int r = 0; r < 4; r++) s[nt][r] = 0.f;

#pragma unroll
        for (int kb = 0; kb < 4; kb++) {
            uint32_t bq[4][4];
#pragma unroll
            for (int p = 0; p < 4; p++)
                ldsm4(bq[p], Kb + boff + (uint32_t)(p * 16) * 144 + kb * 32);
            uint32_t a[4];
            ldsm4(a, Qb + aoff + kb * 32);
#pragma unroll
            for (int p = 0; p < 4; p++) {
                mma16816(s[2 * p],     a, &bq[p][0]);
                mma16816(s[2 * p + 1], a, &bq[p][2]);
            }
        }

        // ---- scale + mask
        const size_t mrow0 = ((size_t)b * SEQ + q0 + qrow + g) * SEQ + kt * 64;
        const size_t mrow1 = mrow0 + 8 * SEQ;
#pragma unroll
        for (int nt = 0; nt < 8; nt++) {
            uchar2 mk0 = *(const uchar2*)(mask + mrow0 + nt * 8 + 2 * tg);
            uchar2 mk1 = *(const uchar2*)(mask + mrow1 + nt * 8 + 2 * tg);
            s[nt][0] = mk0.x ? -1e30f : s[nt][0] * 0.125f;
            s[nt][1] = mk0.y ? -1e30f : s[nt][1] * 0.125f;
            s[nt][2] = mk1.x ? -1e30f : s[nt][2] * 0.125f;
            s[nt][3] = mk1.y ? -1e30f : s[nt][3] * 0.125f;
        }

        // ---- online softmax
        float mt0 = -1e30f, mt1 = -1e30f;
#pragma unroll
        for (int nt = 0; nt < 8; nt++) {
            mt0 = fmaxf(mt0, fmaxf(s[nt][0], s[nt][1]));
            mt1 = fmaxf(mt1, fmaxf(s[nt][2], s[nt][3]));
        }
        mt0 = fmaxf(mt0, __shfl_xor_sync(0xffffffffu, mt0, 1));
        mt0 = fmaxf(mt0, __shfl_xor_sync(0xffffffffu, mt0, 2));
        mt1 = fmaxf(mt1, __shfl_xor_sync(0xffffffffu, mt1, 1));
        mt1 = fmaxf(mt1, __shfl_xor_sync(0xffffffffu, mt1, 2));
        const float mn0 = fmaxf(m0, mt0), mn1 = fmaxf(m1, mt1);
        const float f0 = __expf(m0 - mn0), f1 = __expf(m1 - mn1);

        float ls0 = 0.f, ls1 = 0.f;
#pragma unroll
        for (int nt = 0; nt < 8; nt++) {
            s[nt][0] = __expf(s[nt][0] - mn0);
            s[nt][1] = __expf(s[nt][1] - mn0);
            s[nt][2] = __expf(s[nt][2] - mn1);
            s[nt][3] = __expf(s[nt][3] - mn1);
            ls0 += s[nt][0] + s[nt][1];
            ls1 += s[nt][2] + s[nt][3];
        }
        ls0 += __shfl_xor_sync(0xffffffffu, ls0, 1);
        ls0 += __shfl_xor_sync(0xffffffffu, ls0, 2);
        ls1 += __shfl_xor_sync(0xffffffffu, ls1, 1);
        ls1 += __shfl_xor_sync(0xffffffffu, ls1, 2);
        l0 = l0 * f0 + ls0; l1 = l1 * f1 + ls1;
        m0 = mn0; m1 = mn1;

#pragma unroll
        for (int nt = 0; nt < 8; nt++) {
            o_acc[nt][0] *= f0; o_acc[nt][1] *= f0;
            o_acc[nt][2] *= f1; o_acc[nt][3] *= f1;
        }

        // ---- P fragments (single fp16, A-frag layout)
        uint32_t pf[4][4];
#pragma unroll
        for (int ks = 0; ks < 4; ks++) {
            pf[ks][0] = pack1(s[2*ks][0],   s[2*ks][1]);
            pf[ks][1] = pack1(s[2*ks][2],   s[2*ks][3]);
            pf[ks][2] = pack1(s[2*ks+1][0], s[2*ks+1][1]);
            pf[ks][3] = pack1(s[2*ks+1][2], s[2*ks+1][3]);
        }

        // ---- O += P V (single-term fp16) via trans-ldmatrix
#pragma unroll
        for (int kb = 0; kb < 4; kb++) {
            const uint32_t krow = Vb + voff + (uint32_t)(kb * 16) * 144;
            uint32_t bt[4][4];
#pragma unroll
            for (int nt = 0; nt < 4; nt++)
                ldsm4t(bt[nt], krow + nt * 32);
#pragma unroll
            for (int nt = 0; nt < 4; nt++) {
                mma16816(o_acc[2 * nt],     pf[kb], &bt[nt][0]);
                mma16816(o_acc[2 * nt + 1], pf[kb], &bt[nt][2]);
            }
        }
        __syncthreads();
        buf ^= 1;
    }

    // ---- epilogue: normalize, hi/lo split, write acat [hi|lo]
    const float inv0 = 1.f / l0, inv1 = 1.f / l1;
    const int row0 = b * SEQ + q0 + qrow + g;
    const int row1 = row0 + 8;
    __half* p0 = acat + (size_t)row0 * KCAT2;
    __half* p1 = acat + (size_t)row1 * KCAT2;
#pragma unroll
    for (int nt = 0; nt < 8; nt++) {
        const int d = h * 64 + nt * 8 + 2 * tg;
        uint32_t h0, lo0, h1, lo1;
        pack_hl(o_acc[nt][0] * inv0, o_acc[nt][1] * inv0, h0, lo0);
        pack_hl(o_acc[nt][2] * inv1, o_acc[nt][3] * inv1, h1, lo1);
        *(uint32_t*)(p0 + d)        = h0;
        *(uint32_t*)(p0 + 1024 + d) = lo0;
        *(uint32_t*)(p1 + d)        = h1;
        *(uint32_t*)(p1 + 1024 + d) = lo1;
    }
}

// ======================= LayerNorm (torch semantics) =======================
__global__ void __launch_bounds__(256) ln_kernel(
    const float* __restrict__ y, const float* __restrict__ gamma,
    const float* __restrict__ beta, float* __restrict__ out)
{
    __shared__ float sh_s[8], sh_ss[8];
    const int row = blockIdx.x;
    const float* x = y + (size_t)row * DMODEL;

    float s = 0.f, ss = 0.f;
    for (int i = threadIdx.x; i < DMODEL; i += 256) {
        float v = x[i]; s += v; ss += v * v;
    }
#pragma unroll
    for (int o = 16; o > 0; o >>= 1) {
        s  += __shfl_xor_sync(0xffffffffu, s,  o);
        ss += __shfl_xor_sync(0xffffffffu, ss, o);
    }
    int warp = threadIdx.x >> 5, lane = threadIdx.x & 31;
    if (lane == 0) { sh_s[warp] = s; sh_ss[warp] = ss; }
    __syncthreads();
    if (threadIdx.x < 32) {
        s  = (lane < 8) ? sh_s[lane]  : 0.f;
        ss = (lane < 8) ? sh_ss[lane] : 0.f;
#pragma unroll
        for (int o = 4; o > 0; o >>= 1) {
            s  += __shfl_xor_sync(0xffffffffu, s,  o);
            ss += __shfl_xor_sync(0xffffffffu, ss, o);
        }
        if (lane == 0) { sh_s[0] = s; sh_ss[0] = ss; }
    }
    __syncthreads();
    float mean = sh_s[0] * (1.f / DMODEL);
    float var  = (sh_ss[0] - (float)DMODEL * mean * mean) * (1.f / (DMODEL - 1));
    var = fmaxf(var, 0.f);
    float inv = 1.f / (sqrtf(var) + 1e-3f);
    for (int i = threadIdx.x; i < DMODEL; i += 256)
        out[(size_t)row * DMODEL + i] = (x[i] - mean) * inv * gamma[i] + beta[i];
}

// ===========================================================================
extern "C" void kernel_launch(void* const* d_in, const int* in_sizes, int n_in,
                              void* d_out, int out_size)
{
    const float* v     = (const float*)d_in[0];
    const float* k     = (const float*)d_in[1];
    const float* q     = (const float*)d_in[2];
    const void*  mask  = (const void*)d_in[3];
    const float* w_q   = (const float*)d_in[4];
    const float* w_k   = (const float*)d_in[5];
    const float* w_v   = (const float*)d_in[6];
    const float* w_o   = (const float*)d_in[7];
    const float* b_o   = (const float*)d_in[8];
    const float* gamma = (const float*)d_in[9];
    const float* beta  = (const float*)d_in[10];
    float*       out   = (float*)d_out;

    float* y;
    unsigned char* mask8;
    __half *acat3, *wcat3, *wcat, *acat, *qkvc;
    cudaGetSymbolAddress((void**)&y,     g_y);
    cudaGetSymbolAddress((void**)&mask8, g_mask8);
    cudaGetSymbolAddress((void**)&acat3, g_acat3);
    cudaGetSymbolAddress((void**)&wcat3, g_wcat3);
    cudaGetSymbolAddress((void**)&wcat,  g_wcat);
    cudaGetSymbolAddress((void**)&acat,  g_acat);
    cudaGetSymbolAddress((void**)&qkvc,  g_qkvc);

    cudaFuncSetAttribute(gemm_proj, cudaFuncAttributeMaxDynamicSharedMemorySize, GEMM_SMEM);
    cudaFuncSetAttribute(gemm_out,  cudaFuncAttributeMaxDynamicSharedMemorySize, GEMM_SMEM);
    cudaFuncSetAttribute(attn_mma,  cudaFuncAttributeMaxDynamicSharedMemorySize, ATT_SMEM);

    __half* qc = qkvc;
    __half* kc = qkvc + PACKN;
    __half* vc = qkvc + 2 * PACKN;

    // Mask -> uint8
    probe_mask<<<1, 1024>>>((const unsigned int*)mask);
    convert_mask<<<(int)((MASKN / 16 + 255) / 256), 256>>>(mask);

    // Splits
    split_act3<<<(int)((3 * (ACTN / 4) + 255) / 256), 256>>>(q, k, v, acat3);
    dim3 w3grid(DMODEL / 64, NHEAD, 3);          // (16, 16, 3)
    split_w3t<<<w3grid, 256>>>(w_q, w_k, w_v, wcat3);
    dim3 wfgrid(DMODEL / 64, DMODEL / 64);       // (16, 16)
    split_w_flat_t<<<wfgrid, 256>>>(w_o, wcat);

    // All three projections in one launch -> packed qc/kc/vc (single fp16)
    dim3 pgrid(DMODEL / 128, MROWS / 128, 3);    // (8, 32, 3)
    gemm_proj<<<pgrid, 256, GEMM_SMEM>>>(acat3, wcat3, qkvc);

    // Flash attention (single-term fp16 S and PV; writes acat hi|lo)
    dim3 agrid(SEQ / 128, NHEAD * BATCH);
    attn_mma<<<agrid, 256, ATT_SMEM>>>(qc, kc, vc, mask8, acat);

    // Output projection (2-term fp16) + bias + residual(k)
    dim3 ggrid(DMODEL / 128, MROWS / 128);
    gemm_out<<<ggrid, 256, GEMM_SMEM>>>(acat, wcat, y, b_o, k);

    // LayerNorm
    ln_kernel<<<MROWS, 256>>>(y, gamma, beta, out);
}

// round 13
// speedup vs baseline: 6.7436x; 1.2810x over previous
#include <cuda_runtime.h>
#include <cuda_fp16.h>
#include <math.h>
#include <cstdint>

#define NHEAD  16
#define DMODEL 1024
#define DHEAD  64
#define BATCH  2
#define SEQ    2048
#define MROWS  (BATCH*SEQ)   // 4096
#define MASKN  ((size_t)BATCH*SEQ*SEQ)
#define KC     1024          // single-term fp16 GEMM K
#define ACTN   ((size_t)MROWS*DMODEL)
#define PACKN  ((size_t)32*SEQ*64)   // packed q/k/v: 64 fp16 per row

// Scratch (device globals; no allocation in kernel_launch)
__device__ float g_y  [MROWS*DMODEL];
__device__ unsigned char g_mask8[MASKN];
__device__ int g_fmt;
__device__ __half g_acat3[(size_t)3*MROWS*KC];   // 25.2MB (q|k|v activations fp16)
__device__ __half g_wcat3[(size_t)3*DMODEL*KC];  // 6.3MB  (w_q|w_k|w_v transposed)
__device__ __half g_wcat [(size_t)DMODEL*KC];    // 2.1MB  (w_o transposed)
__device__ __half g_acat [(size_t)MROWS*KC];     // 8.4MB  (attn out fp16)
__device__ __half g_qkvc[(size_t)3*PACKN];       // qc|kc|vc, 25.2MB

// ======================= mma.sync + cp.async helpers =======================
__device__ __forceinline__ void mma16816(float* c, const uint32_t* a, const uint32_t* b) {
    asm volatile("mma.sync.aligned.m16n8k16.row.col.f32.f16.f16.f32 "
        "{%0,%1,%2,%3}, {%4,%5,%6,%7}, {%8,%9}, {%0,%1,%2,%3};"
        : "+f"(c[0]), "+f"(c[1]), "+f"(c[2]), "+f"(c[3])
        : "r"(a[0]), "r"(a[1]), "r"(a[2]), "r"(a[3]), "r"(b[0]), "r"(b[1]));
}
__device__ __forceinline__ void ldsm4(uint32_t* r, uint32_t addr) {
    asm volatile("ldmatrix.sync.aligned.m8n8.x4.shared.b16 {%0,%1,%2,%3}, [%4];"
        : "=r"(r[0]), "=r"(r[1]), "=r"(r[2]), "=r"(r[3]) : "r"(addr));
}
__device__ __forceinline__ void ldsm4t(uint32_t* r, uint32_t addr) {
    asm volatile("ldmatrix.sync.aligned.m8n8.x4.trans.shared.b16 {%0,%1,%2,%3}, [%4];"
        : "=r"(r[0]), "=r"(r[1]), "=r"(r[2]), "=r"(r[3]) : "r"(addr));
}
__device__ __forceinline__ uint32_t smem_u32(const void* p) {
    uint32_t a;
    asm("{ .reg .u64 t; cvta.to.shared.u64 t, %1; cvt.u32.u64 %0, t; }" : "=r"(a) : "l"(p));
    return a;
}
__device__ __forceinline__ void cp16(uint32_t dst, const void* src) {
    asm volatile("cp.async.cg.shared.global [%0], [%1], 16;" :: "r"(dst), "l"(src));
}
#define CP_COMMIT() asm volatile("cp.async.commit_group;" ::: "memory")
#define CP_WAIT1()  asm volatile("cp.async.wait_group 1;" ::: "memory")
#define CP_WAIT0()  asm volatile("cp.async.wait_group 0;" ::: "memory")

// single fp16 pack of a float pair
__device__ __forceinline__ uint32_t pack1(float x, float y) {
    __half2 p = __halves2half2(__float2half(x), __float2half(y));
    return *(uint32_t*)&p;
}

// ======================= mask dtype probe + convert ========================
__global__ void probe_mask(const unsigned int* __restrict__ m) {
    __shared__ int s_i32, s_f32;
    if (threadIdx.x == 0) { s_i32 = 1; s_f32 = 1; }
    __syncthreads();
    int bad_i = 0, bad_f = 0;
    for (int i = threadIdx.x; i < (1 << 16); i += blockDim.x) {
        unsigned int w = m[i];
        if (w != 0u && w != 1u) bad_i = 1;
        if (w != 0u && w != 0x3F800000u) bad_f = 1;
    }
    if (bad_i) atomicAnd(&s_i32, 0);
    if (bad_f) atomicAnd(&s_f32, 0);
    __syncthreads();
    if (threadIdx.x == 0) g_fmt = s_i32 ? 1 : (s_f32 ? 2 : 0);
}
__global__ void convert_mask(const void* __restrict__ src) {
    size_t i = (size_t)blockIdx.x * blockDim.x + threadIdx.x;
    if (i >= MASKN / 16) return;
    int fmt = g_fmt;
    uint4 o;
    if (fmt == 0) {
        o = ((const uint4*)src)[i];
    } else if (fmt == 1) {
        const int* p = (const int*)src + i * 16;
        uint32_t w[4];
#pragma unroll
        for (int j = 0; j < 4; j++)
            w[j] = (uint32_t)(p[4*j+0] != 0)        | ((uint32_t)(p[4*j+1] != 0) << 8)
                 | ((uint32_t)(p[4*j+2] != 0) << 16) | ((uint32_t)(p[4*j+3] != 0) << 24);
        o.x = w[0]; o.y = w[1]; o.z = w[2]; o.w = w[3];
    } else {
        const float* p = (const float*)src + i * 16;
        uint32_t w[4];
#pragma unroll
        for (int j = 0; j < 4; j++)
            w[j] = (uint32_t)(p[4*j+0] != 0.f)        | ((uint32_t)(p[4*j+1] != 0.f) << 8)
                 | ((uint32_t)(p[4*j+2] != 0.f) << 16) | ((uint32_t)(p[4*j+3] != 0.f) << 24);
        o.x = w[0]; o.y = w[1]; o.z = w[2]; o.w = w[3];
    }
    ((uint4*)g_mask8)[i] = o;
}

// ======================= fp16 conversions ==================================
// q,k,v -> acat3[z][r][1024 fp16] (plain convert, coalesced)
__global__ void split_act3(const float* __restrict__ q, const float* __restrict__ k,
                           const float* __restrict__ v, __half* __restrict__ out) {
    const size_t N4 = ACTN / 4;
    size_t i = (size_t)blockIdx.x * blockDim.x + threadIdx.x;
    if (i >= 3 * N4) return;
    int z = (int)(i / N4);
    size_t j = i % N4;
    const float* src = (z == 0) ? q : (z == 1) ? k : v;
    float4 val = ((const float4*)src)[j];
    uint2 o;
    o.x = pack1(val.x, val.y);
    o.y = pack1(val.z, val.w);
    ((uint2*)(out + (size_t)z * ACTN))[j] = o;
}

// w_q,w_k,w_v [h,d,e] -> wcat3[z][n=h*64+e][1024 fp16], SMEM transpose.
__global__ void __launch_bounds__(256) split_w3t(
    const float* __restrict__ wq, const float* __restrict__ wk,
    const float* __restrict__ wv, __half* __restrict__ out)
{
    __shared__ float t[64][65];
    const int dt = blockIdx.x, h = blockIdx.y, z = blockIdx.z;
    const float* src = (z == 0) ? wq : (z == 1) ? wk : wv;
    const int tid = threadIdx.x;
#pragma unroll
    for (int i = 0; i < 16; i++) {
        int idx = tid + i * 256;
        int dr = idx >> 6, e = idx & 63;
        t[dr][e] = src[((size_t)h * DMODEL + dt * 64 + dr) * DHEAD + e];
    }
    __syncthreads();
#pragma unroll
    for (int i = 0; i < 16; i++) {
        int idx = tid + i * 256;
        int e = idx >> 6, dr = idx & 63;
        int n = h * DHEAD + e, d = dt * 64 + dr;
        out[(size_t)z * DMODEL * KC + (size_t)n * KC + d] = __float2half(t[dr][e]);
    }
}

// w_o [d,n] -> wcat[n][1024 fp16], SMEM transpose.
__global__ void __launch_bounds__(256) split_w_flat_t(
    const float* __restrict__ w, __half* __restrict__ out)
{
    __shared__ float t[64][65];
    const int nt = blockIdx.x, dt = blockIdx.y;
    const int tid = threadIdx.x;
#pragma unroll
    for (int i = 0; i < 16; i++) {
        int idx = tid + i * 256;
        int dr = idx >> 6, nr = idx & 63;
        t[dr][nr] = w[(size_t)(dt * 64 + dr) * DMODEL + nt * 64 + nr];
    }
    __syncthreads();
#pragma unroll
    for (int i = 0; i < 16; i++) {
        int idx = tid + i * 256;
        int nr = idx >> 6, dr = idx & 63;
        int n = nt * 64 + nr, d = dt * 64 + dr;
        out[(size_t)n * KC + d] = __float2half(t[dr][nr]);
    }
}

// ======================= mma.sync GEMM machinery ===========================
#define GBK     64
#define GNITER  (KC / GBK)                   // 16
#define TILE_B  (128 * 72 * 2)               // 18432 bytes per A or B tile
#define BUF_B   (2 * TILE_B)
#define GEMM_SMEM (2 * BUF_B)                // 73728

__device__ __forceinline__ void gemm_mainloop(
    const __half* Ag0, const __half* Bg0,
    uint32_t smb, const char* smc, int tid, float acc[4][4][4])
{
    const int wid = tid >> 5, lid = tid & 31;
    const int wm = wid >> 2, wn = wid & 3;
    const int lrow = lid & 7, quad = lid >> 3;
    const uint32_t aoff = (uint32_t)(((quad & 1) * 8 + lrow) * 144 + (quad >> 1) * 16)
                        + (uint32_t)(wm * 64) * 144;
    const uint32_t boff = (uint32_t)(((quad >> 1) * 8 + lrow) * 144 + (quad & 1) * 16)
                        + (uint32_t)(wn * 32) * 144 + TILE_B;

    {
#pragma unroll
        for (int i = 0; i < 4; i++) {
            int idx = tid + i * 256;
            int r = idx >> 3, ch = idx & 7;
            cp16(smb + r * 144 + ch * 16,          Ag0 + (size_t)r * KC + ch * 8);
            cp16(smb + TILE_B + r * 144 + ch * 16, Bg0 + (size_t)r * KC + ch * 8);
        }
        CP_COMMIT();
    }

    int buf = 0;
    for (int it = 0; it < GNITER; it++) {
        if (it + 1 < GNITER) {
            const __half* Ag = Ag0 + (it + 1) * GBK;
            const __half* Bg = Bg0 + (it + 1) * GBK;
            const uint32_t nb = smb + (buf ^ 1) * BUF_B;
#pragma unroll
            for (int i = 0; i < 4; i++) {
                int idx = tid + i * 256;
                int r = idx >> 3, ch = idx & 7;
                cp16(nb + r * 144 + ch * 16,          Ag + (size_t)r * KC + ch * 8);
                cp16(nb + TILE_B + r * 144 + ch * 16, Bg + (size_t)r * KC + ch * 8);
            }
            CP_COMMIT();
            CP_WAIT1();
        } else {
            CP_WAIT0();
        }
        __syncthreads();

        const uint32_t bb = smb + buf * BUF_B;
#pragma unroll
        for (int ks = 0; ks < 4; ks++) {
            uint32_t a[4][4], bq[2][4];
#pragma unroll
            for (int mt = 0; mt < 4; mt++)
                ldsm4(a[mt], bb + aoff + (uint32_t)(mt * 16) * 144 + ks * 32);
#pragma unroll
            for (int p = 0; p < 2; p++)
                ldsm4(bq[p], bb + boff + (uint32_t)(p * 16) * 144 + ks * 32);
#pragma unroll
            for (int mt = 0; mt < 4; mt++)
#pragma unroll
                for (int p = 0; p < 2; p++) {
                    mma16816(acc[mt][2 * p],     a[mt], &bq[p][0]);
                    mma16816(acc[mt][2 * p + 1], a[mt], &bq[p][2]);
                }
        }
        __syncthreads();
        buf ^= 1;
    }
}

// Projection GEMM: grid.z selects q/k/v; packed [hb][row][64 fp16] output.
__global__ void __launch_bounds__(256) gemm_proj(
    const __half* __restrict__ A3, const __half* __restrict__ B3,
    __half* __restrict__ Cp3)
{
    extern __shared__ char smc[];
    const uint32_t smb = smem_u32(smc);
    const int tid = threadIdx.x;
    const int wid = tid >> 5, lid = tid & 31;
    const int wm = wid >> 2, wn = wid & 3;
    const int g = lid >> 2, tg = lid & 3;
    const int m0 = blockIdx.y * 128, n0 = blockIdx.x * 128;
    const int z = blockIdx.z;

    const __half* Ag0 = A3 + (size_t)z * MROWS * KC + (size_t)m0 * KC;
    const __half* Bg0 = B3 + (size_t)z * DMODEL * KC + (size_t)n0 * KC;
    __half* Cp = Cp3 + (size_t)z * PACKN;

    float acc[4][4][4];
#pragma unroll
    for (int mt = 0; mt < 4; mt++)
#pragma unroll
        for (int nt = 0; nt < 4; nt++)
#pragma unroll
            for (int r = 0; r < 4; r++) acc[mt][nt][r] = 0.f;

    gemm_mainloop(Ag0, Bg0, smb, smc, tid, acc);

#pragma unroll
    for (int mt = 0; mt < 4; mt++) {
        int m = m0 + wm * 64 + mt * 16 + g;
#pragma unroll
        for (int nt = 0; nt < 4; nt++) {
            int n = n0 + wn * 32 + nt * 8 + 2 * tg;
            int h = n >> 6, e = n & 63;
#pragma unroll
            for (int half_ = 0; half_ < 2; half_++) {
                int mm = m + half_ * 8;
                int b = mm >> 11, qq = mm & 2047;
                int hb = (h << 1) + b;
                uint32_t hv = pack1(acc[mt][nt][2 * half_], acc[mt][nt][2 * half_ + 1]);
                __half* o = Cp + ((size_t)hb * SEQ + qq) * 64;
                *(uint32_t*)(o + e) = hv;
            }
        }
    }
}

// Output projection GEMM: fp32 C + bias + residual.
__global__ void __launch_bounds__(256) gemm_out(
    const __half* __restrict__ A, const __half* __restrict__ Bt,
    float* __restrict__ Cf, const float* __restrict__ bias,
    const float* __restrict__ residual)
{
    extern __shared__ char smc[];
    const uint32_t smb = smem_u32(smc);
    const int tid = threadIdx.x;
    const int wid = tid >> 5, lid = tid & 31;
    const int wm = wid >> 2, wn = wid & 3;
    const int g = lid >> 2, tg = lid & 3;
    const int m0 = blockIdx.y * 128, n0 = blockIdx.x * 128;

    const __half* Ag0 = A  + (size_t)m0 * KC;
    const __half* Bg0 = Bt + (size_t)n0 * KC;

    float acc[4][4][4];
#pragma unroll
    for (int mt = 0; mt < 4; mt++)
#pragma unroll
        for (int nt = 0; nt < 4; nt++)
#pragma unroll
            for (int r = 0; r < 4; r++) acc[mt][nt][r] = 0.f;

    gemm_mainloop(Ag0, Bg0, smb, smc, tid, acc);

#pragma unroll
    for (int mt = 0; mt < 4; mt++) {
        int m = m0 + wm * 64 + mt * 16 + g;
#pragma unroll
        for (int nt = 0; nt < 4; nt++) {
            int n = n0 + wn * 32 + nt * 8 + 2 * tg;
            float2 v0 = make_float2(acc[mt][nt][0], acc[mt][nt][1]);
            float2 v1 = make_float2(acc[mt][nt][2], acc[mt][nt][3]);
            float2 bv = *(const float2*)(bias + n);
            float2 r0 = *(const float2*)(residual + (size_t)m * DMODEL + n);
            float2 r1 = *(const float2*)(residual + (size_t)(m + 8) * DMODEL + n);
            v0.x += bv.x + r0.x; v0.y += bv.y + r0.y;
            v1.x += bv.x + r1.x; v1.y += bv.y + r1.y;
            *(float2*)(Cf + (size_t)m * DMODEL + n)       = v0;
            *(float2*)(Cf + (size_t)(m + 8) * DMODEL + n) = v1;
        }
    }
}

// ======================= flash attention via mma.sync (fp16) ===============
#define AQ_OFF  0
#define AQ_TB   18432                 // 128 rows x 144B
#define KV_TB   9216                  // 64 rows x 144B
#define AK_OFF  AQ_TB
#define AV_OFF  (AQ_TB + 2*KV_TB)
#define ATT_SMEM (AQ_TB + 4*KV_TB)    // 55296

__global__ void __launch_bounds__(256) attn_mma(
    const __half* __restrict__ Qc, const __half* __restrict__ Kc,
    const __half* __restrict__ Vc, const unsigned char* __restrict__ mask,
    __half* __restrict__ acat)
{
    extern __shared__ char smc[];
    const uint32_t smb = smem_u32(smc);
    const int tid = threadIdx.x;
    const int wid = tid >> 5, lid = tid & 31;
    const int g = lid >> 2, tg = lid & 3;
    const int qb = blockIdx.x, hb = blockIdx.y;
    const int h = hb >> 1, b = hb & 1;
    const int q0 = qb * 128;
    const int qrow = wid * 16;

    const int lrow = lid & 7, quad = lid >> 3;
    const uint32_t aoff = (uint32_t)(((quad & 1) * 8 + lrow) * 144 + (quad >> 1) * 16)
                        + (uint32_t)qrow * 144;
    const uint32_t boff = (uint32_t)(((quad >> 1) * 8 + lrow) * 144 + (quad & 1) * 16);
    const uint32_t voff = (uint32_t)(((quad & 1) * 8 + lrow) * 144 + (quad >> 1) * 16);

    // ---- load Q tile (persistent) + first K/V tiles
    {
        const __half* Qg = Qc + ((size_t)hb * SEQ + q0) * 64;
#pragma unroll
        for (int i = 0; i < 4; i++) {
            int idx = tid + i * 256;
            int r = idx >> 3, ch = idx & 7;
            cp16(smb + AQ_OFF + r * 144 + ch * 16, Qg + (size_t)r * 64 + ch * 8);
        }
        const __half* Kg = Kc + ((size_t)hb * SEQ) * 64;
        const __half* Vg = Vc + ((size_t)hb * SEQ) * 64;
#pragma unroll
        for (int i = 0; i < 2; i++) {
            int idx = tid + i * 256;
            int r = idx >> 3, ch = idx & 7;
            cp16(smb + AK_OFF + r * 144 + ch * 16, Kg + (size_t)r * 64 + ch * 8);
            cp16(smb + AV_OFF + r * 144 + ch * 16, Vg + (size_t)r * 64 + ch * 8);
        }
        CP_COMMIT();
    }

    float o_acc[8][4];
#pragma unroll
    for (int nt = 0; nt < 8; nt++)
#pragma unroll
        for (int r = 0; r < 4; r++) o_acc[nt][r] = 0.f;
    float m0 = -1e30f, m1 = -1e30f, l0 = 0.f, l1 = 0.f;

    int buf = 0;

    for (int kt = 0; kt < SEQ / 64; kt++) {
        if (kt + 1 < SEQ / 64) {
            const __half* Kg = Kc + ((size_t)hb * SEQ + (kt + 1) * 64) * 64;
            const __half* Vg = Vc + ((size_t)hb * SEQ + (kt + 1) * 64) * 64;
            const uint32_t kb_ = smb + AK_OFF + (buf ^ 1) * KV_TB;
            const uint32_t vb_ = smb + AV_OFF + (buf ^ 1) * KV_TB;
#pragma unroll
            for (int i = 0; i < 2; i++) {
                int idx = tid + i * 256;
                int r = idx >> 3, ch = idx & 7;
                cp16(kb_ + r * 144 + ch * 16, Kg + (size_t)r * 64 + ch * 8);
                cp16(vb_ + r * 144 + ch * 16, Vg + (size_t)r * 64 + ch * 8);
            }
            CP_COMMIT();
            CP_WAIT1();
        } else {
            CP_WAIT0();
        }
        __syncthreads();

        const uint32_t Qb = smb + AQ_OFF;
        const uint32_t Kb = smb + AK_OFF + buf * KV_TB;
        const uint32_t Vb = smb + AV_OFF + buf * KV_TB;

        // ---- S = Q K^T (single-term fp16)
        float s[8][4];
#pragma unroll
        for (int nt = 0; nt < 8; nt++)
#pragma unroll
            for (int r = 0; r < 4; r++) s[nt][r] = 0.f;

#pragma unroll
        for (int kb = 0; kb < 4; kb++) {
            uint32_t bq[4][4];
#pragma unroll
            for (int p = 0; p < 4; p++)
                ldsm4(bq[p], Kb + boff + (uint32_t)(p * 16) * 144 + kb * 32);
            uint32_t a[4];
            ldsm4(a, Qb + aoff + kb * 32);
#pragma unroll
            for (int p = 0; p < 4; p++) {
                mma16816(s[2 * p],     a, &bq[p][0]);
                mma16816(s[2 * p + 1], a, &bq[p][2]);
            }
        }

        // ---- scale + mask
        const size_t mrow0 = ((size_t)b * SEQ + q0 + qrow + g) * SEQ + kt * 64;
        const size_t mrow1 = mrow0 + 8 * SEQ;
#pragma unroll
        for (int nt = 0; nt < 8; nt++) {
            uchar2 mk0 = *(const uchar2*)(mask + mrow0 + nt * 8 + 2 * tg);
            uchar2 mk1 = *(const uchar2*)(mask + mrow1 + nt * 8 + 2 * tg);
            s[nt][0] = mk0.x ? -1e30f : s[nt][0] * 0.125f;
            s[nt][1] = mk0.y ? -1e30f : s[nt][1] * 0.125f;
            s[nt][2] = mk1.x ? -1e30f : s[nt][2] * 0.125f;
            s[nt][3] = mk1.y ? -1e30f : s[nt][3] * 0.125f;
        }

        // ---- online softmax
        float mt0 = -1e30f, mt1 = -1e30f;
#pragma unroll
        for (int nt = 0; nt < 8; nt++) {
            mt0 = fmaxf(mt0, fmaxf(s[nt][0], s[nt][1]));
            mt1 = fmaxf(mt1, fmaxf(s[nt][2], s[nt][3]));
        }
        mt0 = fmaxf(mt0, __shfl_xor_sync(0xffffffffu, mt0, 1));
        mt0 = fmaxf(mt0, __shfl_xor_sync(0xffffffffu, mt0, 2));
        mt1 = fmaxf(mt1, __shfl_xor_sync(0xffffffffu, mt1, 1));
        mt1 = fmaxf(mt1, __shfl_xor_sync(0xffffffffu, mt1, 2));
        const float mn0 = fmaxf(m0, mt0), mn1 = fmaxf(m1, mt1);
        const float f0 = __expf(m0 - mn0), f1 = __expf(m1 - mn1);

        float ls0 = 0.f, ls1 = 0.f;
#pragma unroll
        for (int nt = 0; nt < 8; nt++) {
            s[nt][0] = __expf(s[nt][0] - mn0);
            s[nt][1] = __expf(s[nt][1] - mn0);
            s[nt][2] = __expf(s[nt][2] - mn1);
            s[nt][3] = __expf(s[nt][3] - mn1);
            ls0 += s[nt][0] + s[nt][1];
            ls1 += s[nt][2] + s[nt][3];
        }
        ls0 += __shfl_xor_sync(0xffffffffu, ls0, 1);
        ls0 += __shfl_xor_sync(0xffffffffu, ls0, 2);
        ls1 += __shfl_xor_sync(0xffffffffu, ls1, 1);
        ls1 += __shfl_xor_sync(0xffffffffu, ls1, 2);
        l0 = l0 * f0 + ls0; l1 = l1 * f1 + ls1;
        m0 = mn0; m1 = mn1;

#pragma unroll
        for (int nt = 0; nt < 8; nt++) {
            o_acc[nt][0] *= f0; o_acc[nt][1] *= f0;
            o_acc[nt][2] *= f1; o_acc[nt][3] *= f1;
        }

        // ---- P fragments (single fp16, A-frag layout)
        uint32_t pf[4][4];
#pragma unroll
        for (int ks = 0; ks < 4; ks++) {
            pf[ks][0] = pack1(s[2*ks][0],   s[2*ks][1]);
            pf[ks][1] = pack1(s[2*ks][2],   s[2*ks][3]);
            pf[ks][2] = pack1(s[2*ks+1][0], s[2*ks+1][1]);
            pf[ks][3] = pack1(s[2*ks+1][2], s[2*ks+1][3]);
        }

        // ---- O += P V (single-term fp16) via trans-ldmatrix
#pragma unroll
        for (int kb = 0; kb < 4; kb++) {
            const uint32_t krow = Vb + voff + (uint32_t)(kb * 16) * 144;
            uint32_t bt[4][4];
#pragma unroll
            for (int nt = 0; nt < 4; nt++)
                ldsm4t(bt[nt], krow + nt * 32);
#pragma unroll
            for (int nt = 0; nt < 4; nt++) {
                mma16816(o_acc[2 * nt],     pf[kb], &bt[nt][0]);
                mma16816(o_acc[2 * nt + 1], pf[kb], &bt[nt][2]);
            }
        }
        __syncthreads();
        buf ^= 1;
    }

    // ---- epilogue: normalize, single fp16, write acat [row][1024]
    const float inv0 = 1.f / l0, inv1 = 1.f / l1;
    const int row0 = b * SEQ + q0 + qrow + g;
    const int row1 = row0 + 8;
    __half* p0 = acat + (size_t)row0 * KC;
    __half* p1 = acat + (size_t)row1 * KC;
#pragma unroll
    for (int nt = 0; nt < 8; nt++) {
        const int d = h * 64 + nt * 8 + 2 * tg;
        *(uint32_t*)(p0 + d) = pack1(o_acc[nt][0] * inv0, o_acc[nt][1] * inv0);
        *(uint32_t*)(p1 + d) = pack1(o_acc[nt][2] * inv1, o_acc[nt][3] * inv1);
    }
}

// ======================= LayerNorm (torch semantics) =======================
__global__ void __launch_bounds__(256) ln_kernel(
    const float* __restrict__ y, const float* __restrict__ gamma,
    const float* __restrict__ beta, float* __restrict__ out)
{
    __shared__ float sh_s[8], sh_ss[8];
    const int row = blockIdx.x;
    const float* x = y + (size_t)row * DMODEL;

    float s = 0.f, ss = 0.f;
    for (int i = threadIdx.x; i < DMODEL; i += 256) {
        float v = x[i]; s += v; ss += v * v;
    }
#pragma unroll
    for (int o = 16; o > 0; o >>= 1) {
        s  += __shfl_xor_sync(0xffffffffu, s,  o);
        ss += __shfl_xor_sync(0xffffffffu, ss, o);
    }
    int warp = threadIdx.x >> 5, lane = threadIdx.x & 31;
    if (lane == 0) { sh_s[warp] = s; sh_ss[warp] = ss; }
    __syncthreads();
    if (threadIdx.x < 32) {
        s  = (lane < 8) ? sh_s[lane]  : 0.f;
        ss = (lane < 8) ? sh_ss[lane] : 0.f;
#pragma unroll
        for (int o = 4; o > 0; o >>= 1) {
            s  += __shfl_xor_sync(0xffffffffu, s,  o);
            ss += __shfl_xor_sync(0xffffffffu, ss, o);
        }
        if (lane == 0) { sh_s[0] = s; sh_ss[0] = ss; }
    }
    __syncthreads();
    float mean = sh_s[0] * (1.f / DMODEL);
    float var  = (sh_ss[0] - (float)DMODEL * mean * mean) * (1.f / (DMODEL - 1));
    var = fmaxf(var, 0.f);
    float inv = 1.f / (sqrtf(var) + 1e-3f);
    for (int i = threadIdx.x; i < DMODEL; i += 256)
        out[(size_t)row * DMODEL + i] = (x[i] - mean) * inv * gamma[i] + beta[i];
}

// ===========================================================================
extern "C" void kernel_launch(void* const* d_in, const int* in_sizes, int n_in,
                              void* d_out, int out_size)
{
    const float* v     = (const float*)d_in[0];
    const float* k     = (const float*)d_in[1];
    const float* q     = (const float*)d_in[2];
    const void*  mask  = (const void*)d_in[3];
    const float* w_q   = (const float*)d_in[4];
    const float* w_k   = (const float*)d_in[5];
    const float* w_v   = (const float*)d_in[6];
    const float* w_o   = (const float*)d_in[7];
    const float* b_o   = (const float*)d_in[8];
    const float* gamma = (const float*)d_in[9];
    const float* beta  = (const float*)d_in[10];
    float*       out   = (float*)d_out;

    float* y;
    unsigned char* mask8;
    __half *acat3, *wcat3, *wcat, *acat, *qkvc;
    cudaGetSymbolAddress((void**)&y,     g_y);
    cudaGetSymbolAddress((void**)&mask8, g_mask8);
    cudaGetSymbolAddress((void**)&acat3, g_acat3);
    cudaGetSymbolAddress((void**)&wcat3, g_wcat3);
    cudaGetSymbolAddress((void**)&wcat,  g_wcat);
    cudaGetSymbolAddress((void**)&acat,  g_acat);
    cudaGetSymbolAddress((void**)&qkvc,  g_qkvc);

    cudaFuncSetAttribute(gemm_proj, cudaFuncAttributeMaxDynamicSharedMemorySize, GEMM_SMEM);
    cudaFuncSetAttribute(gemm_out,  cudaFuncAttributeMaxDynamicSharedMemorySize, GEMM_SMEM);
    cudaFuncSetAttribute(attn_mma,  cudaFuncAttributeMaxDynamicSharedMemorySize, ATT_SMEM);

    __half* qc = qkvc;
    __half* kc = qkvc + PACKN;
    __half* vc = qkvc + 2 * PACKN;

    // Mask -> uint8
    probe_mask<<<1, 1024>>>((const unsigned int*)mask);
    convert_mask<<<(int)((MASKN / 16 + 255) / 256), 256>>>(mask);

    // Conversions
    split_act3<<<(int)((3 * (ACTN / 4) + 255) / 256), 256>>>(q, k, v, acat3);
    dim3 w3grid(DMODEL / 64, NHEAD, 3);          // (16, 16, 3)
    split_w3t<<<w3grid, 256>>>(w_q, w_k, w_v, wcat3);
    dim3 wfgrid(DMODEL / 64, DMODEL / 64);       // (16, 16)
    split_w_flat_t<<<wfgrid, 256>>>(w_o, wcat);

    // All three projections (1-term fp16) -> packed qc/kc/vc
    dim3 pgrid(DMODEL / 128, MROWS / 128, 3);    // (8, 32, 3)
    gemm_proj<<<pgrid, 256, GEMM_SMEM>>>(acat3, wcat3, qkvc);

    // Flash attention (single-term fp16 S and PV)
    dim3 agrid(SEQ / 128, NHEAD * BATCH);
    attn_mma<<<agrid, 256, ATT_SMEM>>>(qc, kc, vc, mask8, acat);

    // Output projection (1-term fp16) + bias + residual(k)
    dim3 ggrid(DMODEL / 128, MROWS / 128);
    gemm_out<<<ggrid, 256, GEMM_SMEM>>>(acat, wcat, y, b_o, k);

    // LayerNorm
    ln_kernel<<<MROWS, 256>>>(y, gamma, beta, out);
}

// round 14
// speedup vs baseline: 7.0361x; 1.0434x over previous
#include <cuda_runtime.h>
#include <cuda_fp16.h>
#include <math.h>
#include <cstdint>

#define NHEAD  16
#define DMODEL 1024
#define DHEAD  64
#define BATCH  2
#define SEQ    2048
#define MROWS  (BATCH*SEQ)   // 4096
#define MASKN  ((size_t)BATCH*SEQ*SEQ)
#define KC     1024          // single-term fp16 GEMM K
#define ACTN   ((size_t)MROWS*DMODEL)
#define PACKN  ((size_t)32*SEQ*64)   // packed q/k/v: 64 fp16 per row

// Scratch (device globals; no allocation in kernel_launch)
__device__ float g_y  [MROWS*DMODEL];
__device__ unsigned char g_mask8[MASKN];
__device__ int g_fmt;
__device__ __half g_acat3[(size_t)3*MROWS*KC];   // 25.2MB (q|k|v activations fp16)
__device__ __half g_wcat3[(size_t)3*DMODEL*KC];  // 6.3MB  (w_q|w_k|w_v transposed)
__device__ __half g_wcat [(size_t)DMODEL*KC];    // 2.1MB  (w_o transposed)
__device__ __half g_acat [(size_t)MROWS*KC];     // 8.4MB  (attn out fp16)
__device__ __half g_qkvc[(size_t)3*PACKN];       // qc|kc|vc, 25.2MB

// ======================= mma.sync + cp.async helpers =======================
__device__ __forceinline__ void mma16816(float* c, const uint32_t* a, const uint32_t* b) {
    asm volatile("mma.sync.aligned.m16n8k16.row.col.f32.f16.f16.f32 "
        "{%0,%1,%2,%3}, {%4,%5,%6,%7}, {%8,%9}, {%0,%1,%2,%3};"
        : "+f"(c[0]), "+f"(c[1]), "+f"(c[2]), "+f"(c[3])
        : "r"(a[0]), "r"(a[1]), "r"(a[2]), "r"(a[3]), "r"(b[0]), "r"(b[1]));
}
__device__ __forceinline__ void ldsm4(uint32_t* r, uint32_t addr) {
    asm volatile("ldmatrix.sync.aligned.m8n8.x4.shared.b16 {%0,%1,%2,%3}, [%4];"
        : "=r"(r[0]), "=r"(r[1]), "=r"(r[2]), "=r"(r[3]) : "r"(addr));
}
__device__ __forceinline__ void ldsm4t(uint32_t* r, uint32_t addr) {
    asm volatile("ldmatrix.sync.aligned.m8n8.x4.trans.shared.b16 {%0,%1,%2,%3}, [%4];"
        : "=r"(r[0]), "=r"(r[1]), "=r"(r[2]), "=r"(r[3]) : "r"(addr));
}
__device__ __forceinline__ uint32_t smem_u32(const void* p) {
    uint32_t a;
    asm("{ .reg .u64 t; cvta.to.shared.u64 t, %1; cvt.u32.u64 %0, t; }" : "=r"(a) : "l"(p));
    return a;
}
__device__ __forceinline__ void cp16(uint32_t dst, const void* src) {
    asm volatile("cp.async.cg.shared.global [%0], [%1], 16;" :: "r"(dst), "l"(src));
}
#define CP_COMMIT() asm volatile("cp.async.commit_group;" ::: "memory")
#define CP_WAIT1()  asm volatile("cp.async.wait_group 1;" ::: "memory")
#define CP_WAIT0()  asm volatile("cp.async.wait_group 0;" ::: "memory")

// single fp16 pack of a float pair
__device__ __forceinline__ uint32_t pack1(float x, float y) {
    __half2 p = __halves2half2(__float2half(x), __float2half(y));
    return *(uint32_t*)&p;
}

// ======================= mask dtype probe + convert ========================
__global__ void probe_mask(const unsigned int* __restrict__ m) {
    __shared__ int s_i32, s_f32;
    if (threadIdx.x == 0) { s_i32 = 1; s_f32 = 1; }
    __syncthreads();
    int bad_i = 0, bad_f = 0;
    for (int i = threadIdx.x; i < (1 << 16); i += blockDim.x) {
        unsigned int w = m[i];
        if (w != 0u && w != 1u) bad_i = 1;
        if (w != 0u && w != 0x3F800000u) bad_f = 1;
    }
    if (bad_i) atomicAnd(&s_i32, 0);
    if (bad_f) atomicAnd(&s_f32, 0);
    __syncthreads();
    if (threadIdx.x == 0) g_fmt = s_i32 ? 1 : (s_f32 ? 2 : 0);
}
__global__ void convert_mask(const void* __restrict__ src) {
    size_t i = (size_t)blockIdx.x * blockDim.x + threadIdx.x;
    if (i >= MASKN / 16) return;
    int fmt = g_fmt;
    uint4 o;
    if (fmt == 0) {
        o = ((const uint4*)src)[i];
    } else if (fmt == 1) {
        const int* p = (const int*)src + i * 16;
        uint32_t w[4];
#pragma unroll
        for (int j = 0; j < 4; j++)
            w[j] = (uint32_t)(p[4*j+0] != 0)        | ((uint32_t)(p[4*j+1] != 0) << 8)
                 | ((uint32_t)(p[4*j+2] != 0) << 16) | ((uint32_t)(p[4*j+3] != 0) << 24);
        o.x = w[0]; o.y = w[1]; o.z = w[2]; o.w = w[3];
    } else {
        const float* p = (const float*)src + i * 16;
        uint32_t w[4];
#pragma unroll
        for (int j = 0; j < 4; j++)
            w[j] = (uint32_t)(p[4*j+0] != 0.f)        | ((uint32_t)(p[4*j+1] != 0.f) << 8)
                 | ((uint32_t)(p[4*j+2] != 0.f) << 16) | ((uint32_t)(p[4*j+3] != 0.f) << 24);
        o.x = w[0]; o.y = w[1]; o.z = w[2]; o.w = w[3];
    }
    ((uint4*)g_mask8)[i] = o;
}

// ======================= fp16 conversions ==================================
__global__ void split_act3(const float* __restrict__ q, const float* __restrict__ k,
                           const float* __restrict__ v, __half* __restrict__ out) {
    const size_t N4 = ACTN / 4;
    size_t i = (size_t)blockIdx.x * blockDim.x + threadIdx.x;
    if (i >= 3 * N4) return;
    int z = (int)(i / N4);
    size_t j = i % N4;
    const float* src = (z == 0) ? q : (z == 1) ? k : v;
    float4 val = ((const float4*)src)[j];
    uint2 o;
    o.x = pack1(val.x, val.y);
    o.y = pack1(val.z, val.w);
    ((uint2*)(out + (size_t)z * ACTN))[j] = o;
}

__global__ void __launch_bounds__(256) split_w3t(
    const float* __restrict__ wq, const float* __restrict__ wk,
    const float* __restrict__ wv, __half* __restrict__ out)
{
    __shared__ float t[64][65];
    const int dt = blockIdx.x, h = blockIdx.y, z = blockIdx.z;
    const float* src = (z == 0) ? wq : (z == 1) ? wk : wv;
    const int tid = threadIdx.x;
#pragma unroll
    for (int i = 0; i < 16; i++) {
        int idx = tid + i * 256;
        int dr = idx >> 6, e = idx & 63;
        t[dr][e] = src[((size_t)h * DMODEL + dt * 64 + dr) * DHEAD + e];
    }
    __syncthreads();
#pragma unroll
    for (int i = 0; i < 16; i++) {
        int idx = tid + i * 256;
        int e = idx >> 6, dr = idx & 63;
        int n = h * DHEAD + e, d = dt * 64 + dr;
        out[(size_t)z * DMODEL * KC + (size_t)n * KC + d] = __float2half(t[dr][e]);
    }
}

__global__ void __launch_bounds__(256) split_w_flat_t(
    const float* __restrict__ w, __half* __restrict__ out)
{
    __shared__ float t[64][65];
    const int nt = blockIdx.x, dt = blockIdx.y;
    const int tid = threadIdx.x;
#pragma unroll
    for (int i = 0; i < 16; i++) {
        int idx = tid + i * 256;
        int dr = idx >> 6, nr = idx & 63;
        t[dr][nr] = w[(size_t)(dt * 64 + dr) * DMODEL + nt * 64 + nr];
    }
    __syncthreads();
#pragma unroll
    for (int i = 0; i < 16; i++) {
        int idx = tid + i * 256;
        int nr = idx >> 6, dr = idx & 63;
        int n = nt * 64 + nr, d = dt * 64 + dr;
        out[(size_t)n * KC + d] = __float2half(t[dr][nr]);
    }
}

// ======================= mma.sync GEMM machinery ===========================
#define GBK     64
#define GNITER  (KC / GBK)                   // 16
#define TILE_B  (128 * 72 * 2)               // 18432 bytes per A or B tile
#define BUF_B   (2 * TILE_B)
#define GEMM_SMEM (2 * BUF_B)                // 73728

__device__ __forceinline__ void gemm_mainloop(
    const __half* Ag0, const __half* Bg0,
    uint32_t smb, const char* smc, int tid, float acc[4][4][4])
{
    const int wid = tid >> 5, lid = tid & 31;
    const int wm = wid >> 2, wn = wid & 3;
    const int lrow = lid & 7, quad = lid >> 3;
    const uint32_t aoff = (uint32_t)(((quad & 1) * 8 + lrow) * 144 + (quad >> 1) * 16)
                        + (uint32_t)(wm * 64) * 144;
    const uint32_t boff = (uint32_t)(((quad >> 1) * 8 + lrow) * 144 + (quad & 1) * 16)
                        + (uint32_t)(wn * 32) * 144 + TILE_B;

    {
#pragma unroll
        for (int i = 0; i < 4; i++) {
            int idx = tid + i * 256;
            int r = idx >> 3, ch = idx & 7;
            cp16(smb + r * 144 + ch * 16,          Ag0 + (size_t)r * KC + ch * 8);
            cp16(smb + TILE_B + r * 144 + ch * 16, Bg0 + (size_t)r * KC + ch * 8);
        }
        CP_COMMIT();
    }

    int buf = 0;
    for (int it = 0; it < GNITER; it++) {
        if (it + 1 < GNITER) {
            const __half* Ag = Ag0 + (it + 1) * GBK;
            const __half* Bg = Bg0 + (it + 1) * GBK;
            const uint32_t nb = smb + (buf ^ 1) * BUF_B;
#pragma unroll
            for (int i = 0; i < 4; i++) {
                int idx = tid + i * 256;
                int r = idx >> 3, ch = idx & 7;
                cp16(nb + r * 144 + ch * 16,          Ag + (size_t)r * KC + ch * 8);
                cp16(nb + TILE_B + r * 144 + ch * 16, Bg + (size_t)r * KC + ch * 8);
            }
            CP_COMMIT();
            CP_WAIT1();
        } else {
            CP_WAIT0();
        }
        __syncthreads();

        const uint32_t bb = smb + buf * BUF_B;
#pragma unroll
        for (int ks = 0; ks < 4; ks++) {
            uint32_t a[4][4], bq[2][4];
#pragma unroll
            for (int mt = 0; mt < 4; mt++)
                ldsm4(a[mt], bb + aoff + (uint32_t)(mt * 16) * 144 + ks * 32);
#pragma unroll
            for (int p = 0; p < 2; p++)
                ldsm4(bq[p], bb + boff + (uint32_t)(p * 16) * 144 + ks * 32);
#pragma unroll
            for (int mt = 0; mt < 4; mt++)
#pragma unroll
                for (int p = 0; p < 2; p++) {
                    mma16816(acc[mt][2 * p],     a[mt], &bq[p][0]);
                    mma16816(acc[mt][2 * p + 1], a[mt], &bq[p][2]);
                }
        }
        __syncthreads();
        buf ^= 1;
    }
}

// Projection GEMM: grid.z selects q/k/v; packed [hb][row][64 fp16] output.
__global__ void __launch_bounds__(256) gemm_proj(
    const __half* __restrict__ A3, const __half* __restrict__ B3,
    __half* __restrict__ Cp3)
{
    extern __shared__ char smc[];
    const uint32_t smb = smem_u32(smc);
    const int tid = threadIdx.x;
    const int wid = tid >> 5, lid = tid & 31;
    const int wm = wid >> 2, wn = wid & 3;
    const int g = lid >> 2, tg = lid & 3;
    const int m0 = blockIdx.y * 128, n0 = blockIdx.x * 128;
    const int z = blockIdx.z;

    const __half* Ag0 = A3 + (size_t)z * MROWS * KC + (size_t)m0 * KC;
    const __half* Bg0 = B3 + (size_t)z * DMODEL * KC + (size_t)n0 * KC;
    __half* Cp = Cp3 + (size_t)z * PACKN;

    float acc[4][4][4];
#pragma unroll
    for (int mt = 0; mt < 4; mt++)
#pragma unroll
        for (int nt = 0; nt < 4; nt++)
#pragma unroll
            for (int r = 0; r < 4; r++) acc[mt][nt][r] = 0.f;

    gemm_mainloop(Ag0, Bg0, smb, smc, tid, acc);

#pragma unroll
    for (int mt = 0; mt < 4; mt++) {
        int m = m0 + wm * 64 + mt * 16 + g;
#pragma unroll
        for (int nt = 0; nt < 4; nt++) {
            int n = n0 + wn * 32 + nt * 8 + 2 * tg;
            int h = n >> 6, e = n & 63;
#pragma unroll
            for (int half_ = 0; half_ < 2; half_++) {
                int mm = m + half_ * 8;
                int b = mm >> 11, qq = mm & 2047;
                int hb = (h << 1) + b;
                uint32_t hv = pack1(acc[mt][nt][2 * half_], acc[mt][nt][2 * half_ + 1]);
                __half* o = Cp + ((size_t)hb * SEQ + qq) * 64;
                *(uint32_t*)(o + e) = hv;
            }
        }
    }
}

// Output projection GEMM: fp32 C + bias + residual.
__global__ void __launch_bounds__(256) gemm_out(
    const __half* __restrict__ A, const __half* __restrict__ Bt,
    float* __restrict__ Cf, const float* __restrict__ bias,
    const float* __restrict__ residual)
{
    extern __shared__ char smc[];
    const uint32_t smb = smem_u32(smc);
    const int tid = threadIdx.x;
    const int wid = tid >> 5, lid = tid & 31;
    const int wm = wid >> 2, wn = wid & 3;
    const int g = lid >> 2, tg = lid & 3;
    const int m0 = blockIdx.y * 128, n0 = blockIdx.x * 128;

    const __half* Ag0 = A  + (size_t)m0 * KC;
    const __half* Bg0 = Bt + (size_t)n0 * KC;

    float acc[4][4][4];
#pragma unroll
    for (int mt = 0; mt < 4; mt++)
#pragma unroll
        for (int nt = 0; nt < 4; nt++)
#pragma unroll
            for (int r = 0; r < 4; r++) acc[mt][nt][r] = 0.f;

    gemm_mainloop(Ag0, Bg0, smb, smc, tid, acc);

#pragma unroll
    for (int mt = 0; mt < 4; mt++) {
        int m = m0 + wm * 64 + mt * 16 + g;
#pragma unroll
        for (int nt = 0; nt < 4; nt++) {
            int n = n0 + wn * 32 + nt * 8 + 2 * tg;
            float2 v0 = make_float2(acc[mt][nt][0], acc[mt][nt][1]);
            float2 v1 = make_float2(acc[mt][nt][2], acc[mt][nt][3]);
            float2 bv = *(const float2*)(bias + n);
            float2 r0 = *(const float2*)(residual + (size_t)m * DMODEL + n);
            float2 r1 = *(const float2*)(residual + (size_t)(m + 8) * DMODEL + n);
            v0.x += bv.x + r0.x; v0.y += bv.y + r0.y;
            v1.x += bv.x + r1.x; v1.y += bv.y + r1.y;
            *(float2*)(Cf + (size_t)m * DMODEL + n)       = v0;
            *(float2*)(Cf + (size_t)(m + 8) * DMODEL + n) = v1;
        }
    }
}

// ======================= flash attention via mma.sync (fp16) ===============
// 128-key pipeline stages (2 x 64-key softmax sub-passes per stage).
// SMEM: Q 128x144 + K/V stages 128x144 x2 buffers each = 92160 -> 2 CTAs/SM.
#define AQ_OFF  0
#define AQ_TB   18432                 // 128 rows x 144B
#define KV_TB2  18432                 // 128 rows x 144B per stage
#define AK_OFF  AQ_TB
#define AV_OFF  (AQ_TB + 2*KV_TB2)
#define ATT_SMEM (AQ_TB + 4*KV_TB2)   // 92160
#define NSTAGE  (SEQ / 128)           // 16

__global__ void __launch_bounds__(256, 2) attn_mma(
    const __half* __restrict__ Qc, const __half* __restrict__ Kc,
    const __half* __restrict__ Vc, const unsigned char* __restrict__ mask,
    __half* __restrict__ acat)
{
    extern __shared__ char smc[];
    const uint32_t smb = smem_u32(smc);
    const int tid = threadIdx.x;
    const int wid = tid >> 5, lid = tid & 31;
    const int g = lid >> 2, tg = lid & 3;
    const int qb = blockIdx.x, hb = blockIdx.y;
    const int h = hb >> 1, b = hb & 1;
    const int q0 = qb * 128;
    const int qrow = wid * 16;

    const int lrow = lid & 7, quad = lid >> 3;
    const uint32_t aoff = (uint32_t)(((quad & 1) * 8 + lrow) * 144 + (quad >> 1) * 16)
                        + (uint32_t)qrow * 144;
    const uint32_t boff = (uint32_t)(((quad >> 1) * 8 + lrow) * 144 + (quad & 1) * 16);
    const uint32_t voff = (uint32_t)(((quad & 1) * 8 + lrow) * 144 + (quad >> 1) * 16);

    // ---- load Q tile (persistent) + first K/V stage (128 keys)
    {
        const __half* Qg = Qc + ((size_t)hb * SEQ + q0) * 64;
#pragma unroll
        for (int i = 0; i < 4; i++) {
            int idx = tid + i * 256;
            int r = idx >> 3, ch = idx & 7;
            cp16(smb + AQ_OFF + r * 144 + ch * 16, Qg + (size_t)r * 64 + ch * 8);
        }
        const __half* Kg = Kc + ((size_t)hb * SEQ) * 64;
        const __half* Vg = Vc + ((size_t)hb * SEQ) * 64;
#pragma unroll
        for (int i = 0; i < 4; i++) {
            int idx = tid + i * 256;
            int r = idx >> 3, ch = idx & 7;
            cp16(smb + AK_OFF + r * 144 + ch * 16, Kg + (size_t)r * 64 + ch * 8);
            cp16(smb + AV_OFF + r * 144 + ch * 16, Vg + (size_t)r * 64 + ch * 8);
        }
        CP_COMMIT();
    }

    float o_acc[8][4];
#pragma unroll
    for (int nt = 0; nt < 8; nt++)
#pragma unroll
        for (int r = 0; r < 4; r++) o_acc[nt][r] = 0.f;
    float m0 = -1e30f, m1 = -1e30f, l0 = 0.f, l1 = 0.f;

    int buf = 0;

    for (int st = 0; st < NSTAGE; st++) {
        if (st + 1 < NSTAGE) {
            const __half* Kg = Kc + ((size_t)hb * SEQ + (st + 1) * 128) * 64;
            const __half* Vg = Vc + ((size_t)hb * SEQ + (st + 1) * 128) * 64;
            const uint32_t kb_ = smb + AK_OFF + (buf ^ 1) * KV_TB2;
            const uint32_t vb_ = smb + AV_OFF + (buf ^ 1) * KV_TB2;
#pragma unroll
            for (int i = 0; i < 4; i++) {
                int idx = tid + i * 256;
                int r = idx >> 3, ch = idx & 7;
                cp16(kb_ + r * 144 + ch * 16, Kg + (size_t)r * 64 + ch * 8);
                cp16(vb_ + r * 144 + ch * 16, Vg + (size_t)r * 64 + ch * 8);
            }
            CP_COMMIT();
            CP_WAIT1();
        } else {
            CP_WAIT0();
        }
        __syncthreads();

        const uint32_t Qb = smb + AQ_OFF;

#pragma unroll
        for (int sub = 0; sub < 2; sub++) {
            const uint32_t Kb = smb + AK_OFF + buf * KV_TB2 + (uint32_t)(sub * 64) * 144;
            const uint32_t Vb = smb + AV_OFF + buf * KV_TB2 + (uint32_t)(sub * 64) * 144;
            const int kt = st * 2 + sub;

            // ---- S = Q K^T (single-term fp16)
            float s[8][4];
#pragma unroll
            for (int nt = 0; nt < 8; nt++)
#pragma unroll
                for (int r = 0; r < 4; r++) s[nt][r] = 0.f;

#pragma unroll
            for (int kb = 0; kb < 4; kb++) {
                uint32_t bq[4][4];
#pragma unroll
                for (int p = 0; p < 4; p++)
                    ldsm4(bq[p], Kb + boff + (uint32_t)(p * 16) * 144 + kb * 32);
                uint32_t a[4];
                ldsm4(a, Qb + aoff + kb * 32);
#pragma unroll
                for (int p = 0; p < 4; p++) {
                    mma16816(s[2 * p],     a, &bq[p][0]);
                    mma16816(s[2 * p + 1], a, &bq[p][2]);
                }
            }

            // ---- scale + mask
            const size_t mrow0 = ((size_t)b * SEQ + q0 + qrow + g) * SEQ + kt * 64;
            const size_t mrow1 = mrow0 + 8 * SEQ;
#pragma unroll
            for (int nt = 0; nt < 8; nt++) {
                uchar2 mk0 = *(const uchar2*)(mask + mrow0 + nt * 8 + 2 * tg);
                uchar2 mk1 = *(const uchar2*)(mask + mrow1 + nt * 8 + 2 * tg);
                s[nt][0] = mk0.x ? -1e30f : s[nt][0] * 0.125f;
                s[nt][1] = mk0.y ? -1e30f : s[nt][1] * 0.125f;
                s[nt][2] = mk1.x ? -1e30f : s[nt][2] * 0.125f;
                s[nt][3] = mk1.y ? -1e30f : s[nt][3] * 0.125f;
            }

            // ---- online softmax
            float mt0 = -1e30f, mt1 = -1e30f;
#pragma unroll
            for (int nt = 0; nt < 8; nt++) {
                mt0 = fmaxf(mt0, fmaxf(s[nt][0], s[nt][1]));
                mt1 = fmaxf(mt1, fmaxf(s[nt][2], s[nt][3]));
            }
            mt0 = fmaxf(mt0, __shfl_xor_sync(0xffffffffu, mt0, 1));
            mt0 = fmaxf(mt0, __shfl_xor_sync(0xffffffffu, mt0, 2));
            mt1 = fmaxf(mt1, __shfl_xor_sync(0xffffffffu, mt1, 1));
            mt1 = fmaxf(mt1, __shfl_xor_sync(0xffffffffu, mt1, 2));
            const float mn0 = fmaxf(m0, mt0), mn1 = fmaxf(m1, mt1);
            const float f0 = __expf(m0 - mn0), f1 = __expf(m1 - mn1);

            float ls0 = 0.f, ls1 = 0.f;
#pragma unroll
            for (int nt = 0; nt < 8; nt++) {
                s[nt][0] = __expf(s[nt][0] - mn0);
                s[nt][1] = __expf(s[nt][1] - mn0);
                s[nt][2] = __expf(s[nt][2] - mn1);
                s[nt][3] = __expf(s[nt][3] - mn1);
                ls0 += s[nt][0] + s[nt][1];
                ls1 += s[nt][2] + s[nt][3];
            }
            ls0 += __shfl_xor_sync(0xffffffffu, ls0, 1);
            ls0 += __shfl_xor_sync(0xffffffffu, ls0, 2);
            ls1 += __shfl_xor_sync(0xffffffffu, ls1, 1);
            ls1 += __shfl_xor_sync(0xffffffffu, ls1, 2);
            l0 = l0 * f0 + ls0; l1 = l1 * f1 + ls1;
            m0 = mn0; m1 = mn1;

#pragma unroll
            for (int nt = 0; nt < 8; nt++) {
                o_acc[nt][0] *= f0; o_acc[nt][1] *= f0;
                o_acc[nt][2] *= f1; o_acc[nt][3] *= f1;
            }

            // ---- P fragments (single fp16, A-frag layout)
            uint32_t pf[4][4];
#pragma unroll
            for (int ks = 0; ks < 4; ks++) {
                pf[ks][0] = pack1(s[2*ks][0],   s[2*ks][1]);
                pf[ks][1] = pack1(s[2*ks][2],   s[2*ks][3]);
                pf[ks][2] = pack1(s[2*ks+1][0], s[2*ks+1][1]);
                pf[ks][3] = pack1(s[2*ks+1][2], s[2*ks+1][3]);
            }

            // ---- O += P V (single-term fp16) via trans-ldmatrix
#pragma unroll
            for (int kb = 0; kb < 4; kb++) {
                const uint32_t krow = Vb + voff + (uint32_t)(kb * 16) * 144;
                uint32_t bt[4][4];
#pragma unroll
                for (int nt = 0; nt < 4; nt++)
                    ldsm4t(bt[nt], krow + nt * 32);
#pragma unroll
                for (int nt = 0; nt < 4; nt++) {
                    mma16816(o_acc[2 * nt],     pf[kb], &bt[nt][0]);
                    mma16816(o_acc[2 * nt + 1], pf[kb], &bt[nt][2]);
                }
            }
        }
        __syncthreads();
        buf ^= 1;
    }

    // ---- epilogue: normalize, single fp16, write acat [row][1024]
    const float inv0 = 1.f / l0, inv1 = 1.f / l1;
    const int row0 = b * SEQ + q0 + qrow + g;
    const int row1 = row0 + 8;
    __half* p0 = acat + (size_t)row0 * KC;
    __half* p1 = acat + (size_t)row1 * KC;
#pragma unroll
    for (int nt = 0; nt < 8; nt++) {
        const int d = h * 64 + nt * 8 + 2 * tg;
        *(uint32_t*)(p0 + d) = pack1(o_acc[nt][0] * inv0, o_acc[nt][1] * inv0);
        *(uint32_t*)(p1 + d) = pack1(o_acc[nt][2] * inv1, o_acc[nt][3] * inv1);
    }
}

// ======================= LayerNorm (torch semantics, float4) ===============
__global__ void __launch_bounds__(256) ln_kernel(
    const float* __restrict__ y, const float* __restrict__ gamma,
    const float* __restrict__ beta, float* __restrict__ out)
{
    __shared__ float sh_s[8], sh_ss[8];
    const int row = blockIdx.x;
    const float4* x4 = (const float4*)(y + (size_t)row * DMODEL);
    const float4 xv = x4[threadIdx.x];

    float s  = xv.x + xv.y + xv.z + xv.w;
    float ss = xv.x * xv.x + xv.y * xv.y + xv.z * xv.z + xv.w * xv.w;
#pragma unroll
    for (int o = 16; o > 0; o >>= 1) {
        s  += __shfl_xor_sync(0xffffffffu, s,  o);
        ss += __shfl_xor_sync(0xffffffffu, ss, o);
    }
    int warp = threadIdx.x >> 5, lane = threadIdx.x & 31;
    if (lane == 0) { sh_s[warp] = s; sh_ss[warp] = ss; }
    __syncthreads();
    if (threadIdx.x < 32) {
        s  = (lane < 8) ? sh_s[lane]  : 0.f;
        ss = (lane < 8) ? sh_ss[lane] : 0.f;
#pragma unroll
        for (int o = 4; o > 0; o >>= 1) {
            s  += __shfl_xor_sync(0xffffffffu, s,  o);
            ss += __shfl_xor_sync(0xffffffffu, ss, o);
        }
        if (lane == 0) { sh_s[0] = s; sh_ss[0] = ss; }
    }
    __syncthreads();
    float mean = sh_s[0] * (1.f / DMODEL);
    float var  = (sh_ss[0] - (float)DMODEL * mean * mean) * (1.f / (DMODEL - 1));
    var = fmaxf(var, 0.f);
    float inv = 1.f / (sqrtf(var) + 1e-3f);

    const float4 gv = ((const float4*)gamma)[threadIdx.x];
    const float4 bv = ((const float4*)beta)[threadIdx.x];
    float4 ov;
    ov.x = (xv.x - mean) * inv * gv.x + bv.x;
    ov.y = (xv.y - mean) * inv * gv.y + bv.y;
    ov.z = (xv.z - mean) * inv * gv.z + bv.z;
    ov.w = (xv.w - mean) * inv * gv.w + bv.w;
    ((float4*)(out + (size_t)row * DMODEL))[threadIdx.x] = ov;
}

// ===========================================================================
extern "C" void kernel_launch(void* const* d_in, const int* in_sizes, int n_in,
                              void* d_out, int out_size)
{
    const float* v     = (const float*)d_in[0];
    const float* k     = (const float*)d_in[1];
    const float* q     = (const float*)d_in[2];
    const void*  mask  = (const void*)d_in[3];
    const float* w_q   = (const float*)d_in[4];
    const float* w_k   = (const float*)d_in[5];
    const float* w_v   = (const float*)d_in[6];
    const float* w_o   = (const float*)d_in[7];
    const float* b_o   = (const float*)d_in[8];
    const float* gamma = (const float*)d_in[9];
    const float* beta  = (const float*)d_in[10];
    float*       out   = (float*)d_out;

    float* y;
    unsigned char* mask8;
    __half *acat3, *wcat3, *wcat, *acat, *qkvc;
    cudaGetSymbolAddress((void**)&y,     g_y);
    cudaGetSymbolAddress((void**)&mask8, g_mask8);
    cudaGetSymbolAddress((void**)&acat3, g_acat3);
    cudaGetSymbolAddress((void**)&wcat3, g_wcat3);
    cudaGetSymbolAddress((void**)&wcat,  g_wcat);
    cudaGetSymbolAddress((void**)&acat,  g_acat);
    cudaGetSymbolAddress((void**)&qkvc,  g_qkvc);

    cudaFuncSetAttribute(gemm_proj, cudaFuncAttributeMaxDynamicSharedMemorySize, GEMM_SMEM);
    cudaFuncSetAttribute(gemm_out,  cudaFuncAttributeMaxDynamicSharedMemorySize, GEMM_SMEM);
    cudaFuncSetAttribute(attn_mma,  cudaFuncAttributeMaxDynamicSharedMemorySize, ATT_SMEM);

    __half* qc = qkvc;
    __half* kc = qkvc + PACKN;
    __half* vc = qkvc + 2 * PACKN;

    // Mask -> uint8
    probe_mask<<<1, 1024>>>((const unsigned int*)mask);
    convert_mask<<<(int)((MASKN / 16 + 255) / 256), 256>>>(mask);

    // Conversions
    split_act3<<<(int)((3 * (ACTN / 4) + 255) / 256), 256>>>(q, k, v, acat3);
    dim3 w3grid(DMODEL / 64, NHEAD, 3);          // (16, 16, 3)
    split_w3t<<<w3grid, 256>>>(w_q, w_k, w_v, wcat3);
    dim3 wfgrid(DMODEL / 64, DMODEL / 64);       // (16, 16)
    split_w_flat_t<<<wfgrid, 256>>>(w_o, wcat);

    // All three projections (1-term fp16) -> packed qc/kc/vc
    dim3 pgrid(DMODEL / 128, MROWS / 128, 3);    // (8, 32, 3)
    gemm_proj<<<pgrid, 256, GEMM_SMEM>>>(acat3, wcat3, qkvc);

    // Flash attention (single-term fp16 S and PV)
    dim3 agrid(SEQ / 128, NHEAD * BATCH);
    attn_mma<<<agrid, 256, ATT_SMEM>>>(qc, kc, vc, mask8, acat);

    // Output projection (1-term fp16) + bias + residual(k)
    dim3 ggrid(DMODEL / 128, MROWS / 128);
    gemm_out<<<ggrid, 256, GEMM_SMEM>>>(acat, wcat, y, b_o, k);

    // LayerNorm
    ln_kernel<<<MROWS, 256>>>(y, gamma, beta, out);
}

// round 15
// speedup vs baseline: 7.1260x; 1.0128x over previous
#include <cuda_runtime.h>
#include <cuda_fp16.h>
#include <math.h>
#include <cstdint>

#define NHEAD  16
#define DMODEL 1024
#define DHEAD  64
#define BATCH  2
#define SEQ    2048
#define MROWS  (BATCH*SEQ)   // 4096
#define MASKN  ((size_t)BATCH*SEQ*SEQ)
#define KC     1024          // single-term fp16 GEMM K
#define ACTN   ((size_t)MROWS*DMODEL)
#define PACKN  ((size_t)32*SEQ*64)   // packed q/k/v: 64 fp16 per row

// Scratch (device globals; no allocation in kernel_launch)
__device__ float g_y  [MROWS*DMODEL];
__device__ unsigned char g_mask8[MASKN];
__device__ int g_fmt;
__device__ __half g_acat3[(size_t)3*MROWS*KC];   // 25.2MB (q|k|v activations fp16)
__device__ __half g_wcat3[(size_t)3*DMODEL*KC];  // 6.3MB  (w_q|w_k|w_v transposed)
__device__ __half g_wcat [(size_t)DMODEL*KC];    // 2.1MB  (w_o transposed)
__device__ __half g_acat [(size_t)MROWS*KC];     // 8.4MB  (attn out fp16)
__device__ __half g_qkvc[(size_t)3*PACKN];       // qc|kc|vc, 25.2MB

// ======================= mma.sync + cp.async helpers =======================
__device__ __forceinline__ void mma16816(float* c, const uint32_t* a, const uint32_t* b) {
    asm volatile("mma.sync.aligned.m16n8k16.row.col.f32.f16.f16.f32 "
        "{%0,%1,%2,%3}, {%4,%5,%6,%7}, {%8,%9}, {%0,%1,%2,%3};"
        : "+f"(c[0]), "+f"(c[1]), "+f"(c[2]), "+f"(c[3])
        : "r"(a[0]), "r"(a[1]), "r"(a[2]), "r"(a[3]), "r"(b[0]), "r"(b[1]));
}
__device__ __forceinline__ void ldsm4(uint32_t* r, uint32_t addr) {
    asm volatile("ldmatrix.sync.aligned.m8n8.x4.shared.b16 {%0,%1,%2,%3}, [%4];"
        : "=r"(r[0]), "=r"(r[1]), "=r"(r[2]), "=r"(r[3]) : "r"(addr));
}
__device__ __forceinline__ void ldsm4t(uint32_t* r, uint32_t addr) {
    asm volatile("ldmatrix.sync.aligned.m8n8.x4.trans.shared.b16 {%0,%1,%2,%3}, [%4];"
        : "=r"(r[0]), "=r"(r[1]), "=r"(r[2]), "=r"(r[3]) : "r"(addr));
}
__device__ __forceinline__ uint32_t smem_u32(const void* p) {
    uint32_t a;
    asm("{ .reg .u64 t; cvta.to.shared.u64 t, %1; cvt.u32.u64 %0, t; }" : "=r"(a) : "l"(p));
    return a;
}
__device__ __forceinline__ void cp16(uint32_t dst, const void* src) {
    asm volatile("cp.async.cg.shared.global [%0], [%1], 16;" :: "r"(dst), "l"(src));
}
#define CP_COMMIT() asm volatile("cp.async.commit_group;" ::: "memory")
#define CP_WAIT1()  asm volatile("cp.async.wait_group 1;" ::: "memory")
#define CP_WAIT0()  asm volatile("cp.async.wait_group 0;" ::: "memory")

// single fp16 pack of a float pair
__device__ __forceinline__ uint32_t pack1(float x, float y) {
    __half2 p = __halves2half2(__float2half(x), __float2half(y));
    return *(uint32_t*)&p;
}

// ======================= mask dtype probe + convert ========================
__global__ void probe_mask(const unsigned int* __restrict__ m) {
    __shared__ int s_i32, s_f32;
    if (threadIdx.x == 0) { s_i32 = 1; s_f32 = 1; }
    __syncthreads();
    int bad_i = 0, bad_f = 0;
    for (int i = threadIdx.x; i < (1 << 16); i += blockDim.x) {
        unsigned int w = m[i];
        if (w != 0u && w != 1u) bad_i = 1;
        if (w != 0u && w != 0x3F800000u) bad_f = 1;
    }
    if (bad_i) atomicAnd(&s_i32, 0);
    if (bad_f) atomicAnd(&s_f32, 0);
    __syncthreads();
    if (threadIdx.x == 0) g_fmt = s_i32 ? 1 : (s_f32 ? 2 : 0);
}
__global__ void convert_mask(const void* __restrict__ src) {
    size_t i = (size_t)blockIdx.x * blockDim.x + threadIdx.x;
    if (i >= MASKN / 16) return;
    int fmt = g_fmt;
    uint4 o;
    if (fmt == 0) {
        o = ((const uint4*)src)[i];
    } else if (fmt == 1) {
        const int* p = (const int*)src + i * 16;
        uint32_t w[4];
#pragma unroll
        for (int j = 0; j < 4; j++)
            w[j] = (uint32_t)(p[4*j+0] != 0)        | ((uint32_t)(p[4*j+1] != 0) << 8)
                 | ((uint32_t)(p[4*j+2] != 0) << 16) | ((uint32_t)(p[4*j+3] != 0) << 24);
        o.x = w[0]; o.y = w[1]; o.z = w[2]; o.w = w[3];
    } else {
        const float* p = (const float*)src + i * 16;
        uint32_t w[4];
#pragma unroll
        for (int j = 0; j < 4; j++)
            w[j] = (uint32_t)(p[4*j+0] != 0.f)        | ((uint32_t)(p[4*j+1] != 0.f) << 8)
                 | ((uint32_t)(p[4*j+2] != 0.f) << 16) | ((uint32_t)(p[4*j+3] != 0.f) << 24);
        o.x = w[0]; o.y = w[1]; o.z = w[2]; o.w = w[3];
    }
    ((uint4*)g_mask8)[i] = o;
}

// ======================= fp16 conversions ==================================
__global__ void split_act3(const float* __restrict__ q, const float* __restrict__ k,
                           const float* __restrict__ v, __half* __restrict__ out) {
    const size_t N4 = ACTN / 4;
    size_t i = (size_t)blockIdx.x * blockDim.x + threadIdx.x;
    if (i >= 3 * N4) return;
    int z = (int)(i / N4);
    size_t j = i % N4;
    const float* src = (z == 0) ? q : (z == 1) ? k : v;
    float4 val = ((const float4*)src)[j];
    uint2 o;
    o.x = pack1(val.x, val.y);
    o.y = pack1(val.z, val.w);
    ((uint2*)(out + (size_t)z * ACTN))[j] = o;
}

// All four weights in one launch. z<3: w_q/w_k/w_v headed [h,d,e] -> wcat3.
// z==3: w_o flat [d,n] -> wcat. SMEM-tiled transpose, fully coalesced.
__global__ void __launch_bounds__(256) split_w_all(
    const float* __restrict__ wq, const float* __restrict__ wk,
    const float* __restrict__ wv, const float* __restrict__ wo,
    __half* __restrict__ out3, __half* __restrict__ outo)
{
    __shared__ float t[64][65];
    const int bx = blockIdx.x, by = blockIdx.y, z = blockIdx.z;
    const int tid = threadIdx.x;

    if (z < 3) {
        const int dt = bx, h = by;
        const float* src = (z == 0) ? wq : (z == 1) ? wk : wv;
#pragma unroll
        for (int i = 0; i < 16; i++) {
            int idx = tid + i * 256;
            int dr = idx >> 6, e = idx & 63;
            t[dr][e] = src[((size_t)h * DMODEL + dt * 64 + dr) * DHEAD + e];
        }
        __syncthreads();
#pragma unroll
        for (int i = 0; i < 16; i++) {
            int idx = tid + i * 256;
            int e = idx >> 6, dr = idx & 63;
            int n = h * DHEAD + e, d = dt * 64 + dr;
            out3[(size_t)z * DMODEL * KC + (size_t)n * KC + d] = __float2half(t[dr][e]);
        }
    } else {
        const int dt = bx, nt = by;
#pragma unroll
        for (int i = 0; i < 16; i++) {
            int idx = tid + i * 256;
            int dr = idx >> 6, nr = idx & 63;
            t[dr][nr] = wo[(size_t)(dt * 64 + dr) * DMODEL + nt * 64 + nr];
        }
        __syncthreads();
#pragma unroll
        for (int i = 0; i < 16; i++) {
            int idx = tid + i * 256;
            int nr = idx >> 6, dr = idx & 63;
            int n = nt * 64 + nr, d = dt * 64 + dr;
            outo[(size_t)n * KC + d] = __float2half(t[dr][nr]);
        }
    }
}

// ======================= mma.sync GEMM machinery ===========================
#define GBK     64
#define GNITER  (KC / GBK)                   // 16
#define TILE_B  (128 * 72 * 2)               // 18432 bytes per A or B tile
#define BUF_B   (2 * TILE_B)
#define GEMM_SMEM (2 * BUF_B)                // 73728 (x2 CTAs = 144KB, fits)

__device__ __forceinline__ void gemm_mainloop(
    const __half* Ag0, const __half* Bg0,
    uint32_t smb, const char* smc, int tid, float acc[4][4][4])
{
    const int wid = tid >> 5, lid = tid & 31;
    const int wm = wid >> 2, wn = wid & 3;
    const int lrow = lid & 7, quad = lid >> 3;
    const uint32_t aoff = (uint32_t)(((quad & 1) * 8 + lrow) * 144 + (quad >> 1) * 16)
                        + (uint32_t)(wm * 64) * 144;
    const uint32_t boff = (uint32_t)(((quad >> 1) * 8 + lrow) * 144 + (quad & 1) * 16)
                        + (uint32_t)(wn * 32) * 144 + TILE_B;

    {
#pragma unroll
        for (int i = 0; i < 4; i++) {
            int idx = tid + i * 256;
            int r = idx >> 3, ch = idx & 7;
            cp16(smb + r * 144 + ch * 16,          Ag0 + (size_t)r * KC + ch * 8);
            cp16(smb + TILE_B + r * 144 + ch * 16, Bg0 + (size_t)r * KC + ch * 8);
        }
        CP_COMMIT();
    }

    int buf = 0;
    for (int it = 0; it < GNITER; it++) {
        if (it + 1 < GNITER) {
            const __half* Ag = Ag0 + (it + 1) * GBK;
            const __half* Bg = Bg0 + (it + 1) * GBK;
            const uint32_t nb = smb + (buf ^ 1) * BUF_B;
#pragma unroll
            for (int i = 0; i < 4; i++) {
                int idx = tid + i * 256;
                int r = idx >> 3, ch = idx & 7;
                cp16(nb + r * 144 + ch * 16,          Ag + (size_t)r * KC + ch * 8);
                cp16(nb + TILE_B + r * 144 + ch * 16, Bg + (size_t)r * KC + ch * 8);
            }
            CP_COMMIT();
            CP_WAIT1();
        } else {
            CP_WAIT0();
        }
        __syncthreads();

        const uint32_t bb = smb + buf * BUF_B;
#pragma unroll
        for (int ks = 0; ks < 4; ks++) {
            uint32_t a[4][4], bq[2][4];
#pragma unroll
            for (int mt = 0; mt < 4; mt++)
                ldsm4(a[mt], bb + aoff + (uint32_t)(mt * 16) * 144 + ks * 32);
#pragma unroll
            for (int p = 0; p < 2; p++)
                ldsm4(bq[p], bb + boff + (uint32_t)(p * 16) * 144 + ks * 32);
#pragma unroll
            for (int mt = 0; mt < 4; mt++)
#pragma unroll
                for (int p = 0; p < 2; p++) {
                    mma16816(acc[mt][2 * p],     a[mt], &bq[p][0]);
                    mma16816(acc[mt][2 * p + 1], a[mt], &bq[p][2]);
                }
        }
        __syncthreads();
        buf ^= 1;
    }
}

// Projection GEMM: grid.z selects q/k/v; packed [hb][row][64 fp16] output.
__global__ void __launch_bounds__(256, 2) gemm_proj(
    const __half* __restrict__ A3, const __half* __restrict__ B3,
    __half* __restrict__ Cp3)
{
    extern __shared__ char smc[];
    const uint32_t smb = smem_u32(smc);
    const int tid = threadIdx.x;
    const int wid = tid >> 5, lid = tid & 31;
    const int wm = wid >> 2, wn = wid & 3;
    const int g = lid >> 2, tg = lid & 3;
    const int m0 = blockIdx.y * 128, n0 = blockIdx.x * 128;
    const int z = blockIdx.z;

    const __half* Ag0 = A3 + (size_t)z * MROWS * KC + (size_t)m0 * KC;
    const __half* Bg0 = B3 + (size_t)z * DMODEL * KC + (size_t)n0 * KC;
    __half* Cp = Cp3 + (size_t)z * PACKN;

    float acc[4][4][4];
#pragma unroll
    for (int mt = 0; mt < 4; mt++)
#pragma unroll
        for (int nt = 0; nt < 4; nt++)
#pragma unroll
            for (int r = 0; r < 4; r++) acc[mt][nt][r] = 0.f;

    gemm_mainloop(Ag0, Bg0, smb, smc, tid, acc);

#pragma unroll
    for (int mt = 0; mt < 4; mt++) {
        int m = m0 + wm * 64 + mt * 16 + g;
#pragma unroll
        for (int nt = 0; nt < 4; nt++) {
            int n = n0 + wn * 32 + nt * 8 + 2 * tg;
            int h = n >> 6, e = n & 63;
#pragma unroll
            for (int half_ = 0; half_ < 2; half_++) {
                int mm = m + half_ * 8;
                int b = mm >> 11, qq = mm & 2047;
                int hb = (h << 1) + b;
                uint32_t hv = pack1(acc[mt][nt][2 * half_], acc[mt][nt][2 * half_ + 1]);
                __half* o = Cp + ((size_t)hb * SEQ + qq) * 64;
                *(uint32_t*)(o + e) = hv;
            }
        }
    }
}

// Output projection GEMM: fp32 C + bias + residual.
__global__ void __launch_bounds__(256, 2) gemm_out(
    const __half* __restrict__ A, const __half* __restrict__ Bt,
    float* __restrict__ Cf, const float* __restrict__ bias,
    const float* __restrict__ residual)
{
    extern __shared__ char smc[];
    const uint32_t smb = smem_u32(smc);
    const int tid = threadIdx.x;
    const int wid = tid >> 5, lid = tid & 31;
    const int wm = wid >> 2, wn = wid & 3;
    const int g = lid >> 2, tg = lid & 3;
    const int m0 = blockIdx.y * 128, n0 = blockIdx.x * 128;

    const __half* Ag0 = A  + (size_t)m0 * KC;
    const __half* Bg0 = Bt + (size_t)n0 * KC;

    float acc[4][4][4];
#pragma unroll
    for (int mt = 0; mt < 4; mt++)
#pragma unroll
        for (int nt = 0; nt < 4; nt++)
#pragma unroll
            for (int r = 0; r < 4; r++) acc[mt][nt][r] = 0.f;

    gemm_mainloop(Ag0, Bg0, smb, smc, tid, acc);

#pragma unroll
    for (int mt = 0; mt < 4; mt++) {
        int m = m0 + wm * 64 + mt * 16 + g;
#pragma unroll
        for (int nt = 0; nt < 4; nt++) {
            int n = n0 + wn * 32 + nt * 8 + 2 * tg;
            float2 v0 = make_float2(acc[mt][nt][0], acc[mt][nt][1]);
            float2 v1 = make_float2(acc[mt][nt][2], acc[mt][nt][3]);
            float2 bv = *(const float2*)(bias + n);
            float2 r0 = *(const float2*)(residual + (size_t)m * DMODEL + n);
            float2 r1 = *(const float2*)(residual + (size_t)(m + 8) * DMODEL + n);
            v0.x += bv.x + r0.x; v0.y += bv.y + r0.y;
            v1.x += bv.x + r1.x; v1.y += bv.y + r1.y;
            *(float2*)(Cf + (size_t)m * DMODEL + n)       = v0;
            *(float2*)(Cf + (size_t)(m + 8) * DMODEL + n) = v1;
        }
    }
}

// ======================= flash attention via mma.sync (fp16) ===============
// 128-key pipeline stages (2 x 64-key softmax sub-passes per stage), 2 CTAs/SM.
#define AQ_OFF  0
#define AQ_TB   18432                 // 128 rows x 144B
#define KV_TB2  18432                 // 128 rows x 144B per stage
#define AK_OFF  AQ_TB
#define AV_OFF  (AQ_TB + 2*KV_TB2)
#define ATT_SMEM (AQ_TB + 4*KV_TB2)   // 92160
#define NSTAGE  (SEQ / 128)           // 16

__global__ void __launch_bounds__(256, 2) attn_mma(
    const __half* __restrict__ Qc, const __half* __restrict__ Kc,
    const __half* __restrict__ Vc, const unsigned char* __restrict__ mask,
    __half* __restrict__ acat)
{
    extern __shared__ char smc[];
    const uint32_t smb = smem_u32(smc);
    const int tid = threadIdx.x;
    const int wid = tid >> 5, lid = tid & 31;
    const int g = lid >> 2, tg = lid & 3;
    const int qb = blockIdx.x, hb = blockIdx.y;
    const int h = hb >> 1, b = hb & 1;
    const int q0 = qb * 128;
    const int qrow = wid * 16;

    const int lrow = lid & 7, quad = lid >> 3;
    const uint32_t aoff = (uint32_t)(((quad & 1) * 8 + lrow) * 144 + (quad >> 1) * 16)
                        + (uint32_t)qrow * 144;
    const uint32_t boff = (uint32_t)(((quad >> 1) * 8 + lrow) * 144 + (quad & 1) * 16);
    const uint32_t voff = (uint32_t)(((quad & 1) * 8 + lrow) * 144 + (quad >> 1) * 16);

    // ---- load Q tile (persistent) + first K/V stage (128 keys)
    {
        const __half* Qg = Qc + ((size_t)hb * SEQ + q0) * 64;
#pragma unroll
        for (int i = 0; i < 4; i++) {
            int idx = tid + i * 256;
            int r = idx >> 3, ch = idx & 7;
            cp16(smb + AQ_OFF + r * 144 + ch * 16, Qg + (size_t)r * 64 + ch * 8);
        }
        const __half* Kg = Kc + ((size_t)hb * SEQ) * 64;
        const __half* Vg = Vc + ((size_t)hb * SEQ) * 64;
#pragma unroll
        for (int i = 0; i < 4; i++) {
            int idx = tid + i * 256;
            int r = idx >> 3, ch = idx & 7;
            cp16(smb + AK_OFF + r * 144 + ch * 16, Kg + (size_t)r * 64 + ch * 8);
            cp16(smb + AV_OFF + r * 144 + ch * 16, Vg + (size_t)r * 64 + ch * 8);
        }
        CP_COMMIT();
    }

    float o_acc[8][4];
#pragma unroll
    for (int nt = 0; nt < 8; nt++)
#pragma unroll
        for (int r = 0; r < 4; r++) o_acc[nt][r] = 0.f;
    float m0 = -1e30f, m1 = -1e30f, l0 = 0.f, l1 = 0.f;

    int buf = 0;

    for (int st = 0; st < NSTAGE; st++) {
        if (st + 1 < NSTAGE) {
            const __half* Kg = Kc + ((size_t)hb * SEQ + (st + 1) * 128) * 64;
            const __half* Vg = Vc + ((size_t)hb * SEQ + (st + 1) * 128) * 64;
            const uint32_t kb_ = smb + AK_OFF + (buf ^ 1) * KV_TB2;
            const uint32_t vb_ = smb + AV_OFF + (buf ^ 1) * KV_TB2;
#pragma unroll
            for (int i = 0; i < 4; i++) {
                int idx = tid + i * 256;
                int r = idx >> 3, ch = idx & 7;
                cp16(kb_ + r * 144 + ch * 16, Kg + (size_t)r * 64 + ch * 8);
                cp16(vb_ + r * 144 + ch * 16, Vg + (size_t)r * 64 + ch * 8);
            }
            CP_COMMIT();
            CP_WAIT1();
        } else {
            CP_WAIT0();
        }
        __syncthreads();

        const uint32_t Qb = smb + AQ_OFF;

#pragma unroll
        for (int sub = 0; sub < 2; sub++) {
            const uint32_t Kb = smb + AK_OFF + buf * KV_TB2 + (uint32_t)(sub * 64) * 144;
            const uint32_t Vb = smb + AV_OFF + buf * KV_TB2 + (uint32_t)(sub * 64) * 144;
            const int kt = st * 2 + sub;

            // ---- S = Q K^T (single-term fp16)
            float s[8][4];
#pragma unroll
            for (int nt = 0; nt < 8; nt++)
#pragma unroll
                for (int r = 0; r < 4; r++) s[nt][r] = 0.f;

#pragma unroll
            for (int kb = 0; kb < 4; kb++) {
                uint32_t bq[4][4];
#pragma unroll
                for (int p = 0; p < 4; p++)
                    ldsm4(bq[p], Kb + boff + (uint32_t)(p * 16) * 144 + kb * 32);
                uint32_t a[4];
                ldsm4(a, Qb + aoff + kb * 32);
#pragma unroll
                for (int p = 0; p < 4; p++) {
                    mma16816(s[2 * p],     a, &bq[p][0]);
                    mma16816(s[2 * p + 1], a, &bq[p][2]);
                }
            }

            // ---- scale + mask
            const size_t mrow0 = ((size_t)b * SEQ + q0 + qrow + g) * SEQ + kt * 64;
            const size_t mrow1 = mrow0 + 8 * SEQ;
#pragma unroll
            for (int nt = 0; nt < 8; nt++) {
                uchar2 mk0 = *(const uchar2*)(mask + mrow0 + nt * 8 + 2 * tg);
                uchar2 mk1 = *(const uchar2*)(mask + mrow1 + nt * 8 + 2 * tg);
                s[nt][0] = mk0.x ? -1e30f : s[nt][0] * 0.125f;
                s[nt][1] = mk0.y ? -1e30f : s[nt][1] * 0.125f;
                s[nt][2] = mk1.x ? -1e30f : s[nt][2] * 0.125f;
                s[nt][3] = mk1.y ? -1e30f : s[nt][3] * 0.125f;
            }

            // ---- online softmax
            float mt0 = -1e30f, mt1 = -1e30f;
#pragma unroll
            for (int nt = 0; nt < 8; nt++) {
                mt0 = fmaxf(mt0, fmaxf(s[nt][0], s[nt][1]));
                mt1 = fmaxf(mt1, fmaxf(s[nt][2], s[nt][3]));
            }
            mt0 = fmaxf(mt0, __shfl_xor_sync(0xffffffffu, mt0, 1));
            mt0 = fmaxf(mt0, __shfl_xor_sync(0xffffffffu, mt0, 2));
            mt1 = fmaxf(mt1, __shfl_xor_sync(0xffffffffu, mt1, 1));
            mt1 = fmaxf(mt1, __shfl_xor_sync(0xffffffffu, mt1, 2));
            const float mn0 = fmaxf(m0, mt0), mn1 = fmaxf(m1, mt1);
            const float f0 = __expf(m0 - mn0), f1 = __expf(m1 - mn1);

            float ls0 = 0.f, ls1 = 0.f;
#pragma unroll
            for (int nt = 0; nt < 8; nt++) {
                s[nt][0] = __expf(s[nt][0] - mn0);
                s[nt][1] = __expf(s[nt][1] - mn0);
                s[nt][2] = __expf(s[nt][2] - mn1);
                s[nt][3] = __expf(s[nt][3] - mn1);
                ls0 += s[nt][0] + s[nt][1];
                ls1 += s[nt][2] + s[nt][3];
            }
            ls0 += __shfl_xor_sync(0xffffffffu, ls0, 1);
            ls0 += __shfl_xor_sync(0xffffffffu, ls0, 2);
            ls1 += __shfl_xor_sync(0xffffffffu, ls1, 1);
            ls1 += __shfl_xor_sync(0xffffffffu, ls1, 2);
            l0 = l0 * f0 + ls0; l1 = l1 * f1 + ls1;
            m0 = mn0; m1 = mn1;

#pragma unroll
            for (int nt = 0; nt < 8; nt++) {
                o_acc[nt][0] *= f0; o_acc[nt][1] *= f0;
                o_acc[nt][2] *= f1; o_acc[nt][3] *= f1;
            }

            // ---- P fragments (single fp16, A-frag layout)
            uint32_t pf[4][4];
#pragma unroll
            for (int ks = 0; ks < 4; ks++) {
                pf[ks][0] = pack1(s[2*ks][0],   s[2*ks][1]);
                pf[ks][1] = pack1(s[2*ks][2],   s[2*ks][3]);
                pf[ks][2] = pack1(s[2*ks+1][0], s[2*ks+1][1]);
                pf[ks][3] = pack1(s[2*ks+1][2], s[2*ks+1][3]);
            }

            // ---- O += P V (single-term fp16) via trans-ldmatrix
#pragma unroll
            for (int kb = 0; kb < 4; kb++) {
                const uint32_t krow = Vb + voff + (uint32_t)(kb * 16) * 144;
                uint32_t bt[4][4];
#pragma unroll
                for (int nt = 0; nt < 4; nt++)
                    ldsm4t(bt[nt], krow + nt * 32);
#pragma unroll
                for (int nt = 0; nt < 4; nt++) {
                    mma16816(o_acc[2 * nt],     pf[kb], &bt[nt][0]);
                    mma16816(o_acc[2 * nt + 1], pf[kb], &bt[nt][2]);
                }
            }
        }
        __syncthreads();
        buf ^= 1;
    }

    // ---- epilogue: normalize, single fp16, write acat [row][1024]
    const float inv0 = 1.f / l0, inv1 = 1.f / l1;
    const int row0 = b * SEQ + q0 + qrow + g;
    const int row1 = row0 + 8;
    __half* p0 = acat + (size_t)row0 * KC;
    __half* p1 = acat + (size_t)row1 * KC;
#pragma unroll
    for (int nt = 0; nt < 8; nt++) {
        const int d = h * 64 + nt * 8 + 2 * tg;
        *(uint32_t*)(p0 + d) = pack1(o_acc[nt][0] * inv0, o_acc[nt][1] * inv0);
        *(uint32_t*)(p1 + d) = pack1(o_acc[nt][2] * inv1, o_acc[nt][3] * inv1);
    }
}

// ======================= LayerNorm (torch semantics, float4) ===============
__global__ void __launch_bounds__(256) ln_kernel(
    const float* __restrict__ y, const float* __restrict__ gamma,
    const float* __restrict__ beta, float* __restrict__ out)
{
    __shared__ float sh_s[8], sh_ss[8];
    const int row = blockIdx.x;
    const float4* x4 = (const float4*)(y + (size_t)row * DMODEL);
    const float4 xv = x4[threadIdx.x];

    float s  = xv.x + xv.y + xv.z + xv.w;
    float ss = xv.x * xv.x + xv.y * xv.y + xv.z * xv.z + xv.w * xv.w;
#pragma unroll
    for (int o = 16; o > 0; o >>= 1) {
        s  += __shfl_xor_sync(0xffffffffu, s,  o);
        ss += __shfl_xor_sync(0xffffffffu, ss, o);
    }
    int warp = threadIdx.x >> 5, lane = threadIdx.x & 31;
    if (lane == 0) { sh_s[warp] = s; sh_ss[warp] = ss; }
    __syncthreads();
    if (threadIdx.x < 32) {
        s  = (lane < 8) ? sh_s[lane]  : 0.f;
        ss = (lane < 8) ? sh_ss[lane] : 0.f;
#pragma unroll
        for (int o = 4; o > 0; o >>= 1) {
            s  += __shfl_xor_sync(0xffffffffu, s,  o);
            ss += __shfl_xor_sync(0xffffffffu, ss, o);
        }
        if (lane == 0) { sh_s[0] = s; sh_ss[0] = ss; }
    }
    __syncthreads();
    float mean = sh_s[0] * (1.f / DMODEL);
    float var  = (sh_ss[0] - (float)DMODEL * mean * mean) * (1.f / (DMODEL - 1));
    var = fmaxf(var, 0.f);
    float inv = 1.f / (sqrtf(var) + 1e-3f);

    const float4 gv = ((const float4*)gamma)[threadIdx.x];
    const float4 bv = ((const float4*)beta)[threadIdx.x];
    float4 ov;
    ov.x = (xv.x - mean) * inv * gv.x + bv.x;
    ov.y = (xv.y - mean) * inv * gv.y + bv.y;
    ov.z = (xv.z - mean) * inv * gv.z + bv.z;
    ov.w = (xv.w - mean) * inv * gv.w + bv.w;
    ((float4*)(out + (size_t)row * DMODEL))[threadIdx.x] = ov;
}

// ===========================================================================
extern "C" void kernel_launch(void* const* d_in, const int* in_sizes, int n_in,
                              void* d_out, int out_size)
{
    const float* v     = (const float*)d_in[0];
    const float* k     = (const float*)d_in[1];
    const float* q     = (const float*)d_in[2];
    const void*  mask  = (const void*)d_in[3];
    const float* w_q   = (const float*)d_in[4];
    const float* w_k   = (const float*)d_in[5];
    const float* w_v   = (const float*)d_in[6];
    const float* w_o   = (const float*)d_in[7];
    const float* b_o   = (const float*)d_in[8];
    const float* gamma = (const float*)d_in[9];
    const float* beta  = (const float*)d_in[10];
    float*       out   = (float*)d_out;

    float* y;
    unsigned char* mask8;
    __half *acat3, *wcat3, *wcat, *acat, *qkvc;
    cudaGetSymbolAddress((void**)&y,     g_y);
    cudaGetSymbolAddress((void**)&mask8, g_mask8);
    cudaGetSymbolAddress((void**)&acat3, g_acat3);
    cudaGetSymbolAddress((void**)&wcat3, g_wcat3);
    cudaGetSymbolAddress((void**)&wcat,  g_wcat);
    cudaGetSymbolAddress((void**)&acat,  g_acat);
    cudaGetSymbolAddress((void**)&qkvc,  g_qkvc);

    cudaFuncSetAttribute(gemm_proj, cudaFuncAttributeMaxDynamicSharedMemorySize, GEMM_SMEM);
    cudaFuncSetAttribute(gemm_out,  cudaFuncAttributeMaxDynamicSharedMemorySize, GEMM_SMEM);
    cudaFuncSetAttribute(attn_mma,  cudaFuncAttributeMaxDynamicSharedMemorySize, ATT_SMEM);

    __half* qc = qkvc;
    __half* kc = qkvc + PACKN;
    __half* vc = qkvc + 2 * PACKN;

    // Mask -> uint8
    probe_mask<<<1, 1024>>>((const unsigned int*)mask);
    convert_mask<<<(int)((MASKN / 16 + 255) / 256), 256>>>(mask);

    // Conversions
    split_act3<<<(int)((3 * (ACTN / 4) + 255) / 256), 256>>>(q, k, v, acat3);
    dim3 wgrid(DMODEL / 64, 16, 4);              // z<3 headed, z==3 w_o flat
    split_w_all<<<wgrid, 256>>>(w_q, w_k, w_v, w_o, wcat3, wcat);

    // All three projections (1-term fp16) -> packed qc/kc/vc
    dim3 pgrid(DMODEL / 128, MROWS / 128, 3);    // (8, 32, 3)
    gemm_proj<<<pgrid, 256, GEMM_SMEM>>>(acat3, wcat3, qkvc);

    // Flash attention (single-term fp16 S and PV)
    dim3 agrid(SEQ / 128, NHEAD * BATCH);
    attn_mma<<<agrid, 256, ATT_SMEM>>>(qc, kc, vc, mask8, acat);

    // Output projection (1-term fp16) + bias + residual(k)
    dim3 ggrid(DMODEL / 128, MROWS / 128);
    gemm_out<<<ggrid, 256, GEMM_SMEM>>>(acat, wcat, y, b_o, k);

    // LayerNorm
    ln_kernel<<<MROWS, 256>>>(y, gamma, beta, out);
}

// round 16
// speedup vs baseline: 7.3679x; 1.0339x over previous
#include <cuda_runtime.h>
#include <cuda_fp16.h>
#include <math.h>
#include <cstdint>

#define NHEAD  16
#define DMODEL 1024
#define DHEAD  64
#define BATCH  2
#define SEQ    2048
#define MROWS  (BATCH*SEQ)   // 4096
#define MASKN  ((size_t)BATCH*SEQ*SEQ)
#define MASKW  (MASKN/32)    // packed words
#define KC     1024          // single-term fp16 GEMM K
#define ACTN   ((size_t)MROWS*DMODEL)
#define PACKN  ((size_t)32*SEQ*64)   // packed q/k/v: 64 fp16 per row

// Scratch (device globals; no allocation in kernel_launch)
__device__ float g_y  [MROWS*DMODEL];
__device__ uint32_t g_maskb[MASKW];              // bit-packed mask, 1MB
__device__ int g_fmt;
__device__ __half g_acat3[(size_t)3*MROWS*KC];   // 25.2MB (q|k|v activations fp16)
__device__ __half g_wcat3[(size_t)3*DMODEL*KC];  // 6.3MB  (w_q|w_k|w_v transposed)
__device__ __half g_wcat [(size_t)DMODEL*KC];    // 2.1MB  (w_o transposed)
__device__ __half g_acat [(size_t)MROWS*KC];     // 8.4MB  (attn out fp16)
__device__ __half g_qkvc[(size_t)3*PACKN];       // qc|kc|vc, 25.2MB

// ======================= mma.sync + cp.async helpers =======================
__device__ __forceinline__ void mma16816(float* c, const uint32_t* a, const uint32_t* b) {
    asm volatile("mma.sync.aligned.m16n8k16.row.col.f32.f16.f16.f32 "
        "{%0,%1,%2,%3}, {%4,%5,%6,%7}, {%8,%9}, {%0,%1,%2,%3};"
        : "+f"(c[0]), "+f"(c[1]), "+f"(c[2]), "+f"(c[3])
        : "r"(a[0]), "r"(a[1]), "r"(a[2]), "r"(a[3]), "r"(b[0]), "r"(b[1]));
}
__device__ __forceinline__ void ldsm4(uint32_t* r, uint32_t addr) {
    asm volatile("ldmatrix.sync.aligned.m8n8.x4.shared.b16 {%0,%1,%2,%3}, [%4];"
        : "=r"(r[0]), "=r"(r[1]), "=r"(r[2]), "=r"(r[3]) : "r"(addr));
}
__device__ __forceinline__ void ldsm4t(uint32_t* r, uint32_t addr) {
    asm volatile("ldmatrix.sync.aligned.m8n8.x4.trans.shared.b16 {%0,%1,%2,%3}, [%4];"
        : "=r"(r[0]), "=r"(r[1]), "=r"(r[2]), "=r"(r[3]) : "r"(addr));
}
__device__ __forceinline__ uint32_t smem_u32(const void* p) {
    uint32_t a;
    asm("{ .reg .u64 t; cvta.to.shared.u64 t, %1; cvt.u32.u64 %0, t; }" : "=r"(a) : "l"(p));
    return a;
}
__device__ __forceinline__ void cp16(uint32_t dst, const void* src) {
    asm volatile("cp.async.cg.shared.global [%0], [%1], 16;" :: "r"(dst), "l"(src));
}
#define CP_COMMIT() asm volatile("cp.async.commit_group;" ::: "memory")
#define CP_WAIT1()  asm volatile("cp.async.wait_group 1;" ::: "memory")
#define CP_WAIT0()  asm volatile("cp.async.wait_group 0;" ::: "memory")

// single fp16 pack of a float pair
__device__ __forceinline__ uint32_t pack1(float x, float y) {
    __half2 p = __halves2half2(__float2half(x), __float2half(y));
    return *(uint32_t*)&p;
}

// ======================= mask dtype probe + bit-pack =======================
__global__ void probe_mask(const unsigned int* __restrict__ m) {
    __shared__ int s_i32, s_f32;
    if (threadIdx.x == 0) { s_i32 = 1; s_f32 = 1; }
    __syncthreads();
    int bad_i = 0, bad_f = 0;
    for (int i = threadIdx.x; i < (1 << 16); i += blockDim.x) {
        unsigned int w = m[i];
        if (w != 0u && w != 1u) bad_i = 1;
        if (w != 0u && w != 0x3F800000u) bad_f = 1;
    }
    if (bad_i) atomicAnd(&s_i32, 0);
    if (bad_f) atomicAnd(&s_f32, 0);
    __syncthreads();
    if (threadIdx.x == 0) g_fmt = s_i32 ? 1 : (s_f32 ? 2 : 0);
}
// Each thread packs 32 mask values into one uint32 (bit k = value!=0).
__global__ void pack_mask(const void* __restrict__ src) {
    size_t w = (size_t)blockIdx.x * blockDim.x + threadIdx.x;
    if (w >= MASKW) return;
    int fmt = g_fmt;
    uint32_t bits = 0;
    if (fmt == 0) {
        const uint4* p = (const uint4*)src + w * 2;
        uint4 a = p[0], b = p[1];
        uint32_t vals[8] = {a.x, a.y, a.z, a.w, b.x, b.y, b.z, b.w};
#pragma unroll
        for (int j = 0; j < 8; j++) {
            uint32_t v = vals[j];
            // bytes 0..3 (values 0/1) -> bits 0..3 of nibble
            uint32_t nib = (v & 1u) | ((v >> 7) & 2u) | ((v >> 14) & 4u) | ((v >> 21) & 8u);
            bits |= nib << (j * 4);
        }
    } else if (fmt == 1) {
        const int* p = (const int*)src + w * 32;
#pragma unroll
        for (int j = 0; j < 32; j++) bits |= (uint32_t)(p[j] != 0) << j;
    } else {
        const float* p = (const float*)src + w * 32;
#pragma unroll
        for (int j = 0; j < 32; j++) bits |= (uint32_t)(p[j] != 0.f) << j;
    }
    g_maskb[w] = bits;
}

// ======================= fp16 conversions ==================================
__global__ void split_act3(const float* __restrict__ q, const float* __restrict__ k,
                           const float* __restrict__ v, __half* __restrict__ out) {
    const size_t N4 = ACTN / 4;
    size_t i = (size_t)blockIdx.x * blockDim.x + threadIdx.x;
    if (i >= 3 * N4) return;
    int z = (int)(i / N4);
    size_t j = i % N4;
    const float* src = (z == 0) ? q : (z == 1) ? k : v;
    float4 val = ((const float4*)src)[j];
    uint2 o;
    o.x = pack1(val.x, val.y);
    o.y = pack1(val.z, val.w);
    ((uint2*)(out + (size_t)z * ACTN))[j] = o;
}

// All four weights in one launch. z<3: headed [h,d,e] -> wcat3. z==3: w_o flat.
__global__ void __launch_bounds__(256) split_w_all(
    const float* __restrict__ wq, const float* __restrict__ wk,
    const float* __restrict__ wv, const float* __restrict__ wo,
    __half* __restrict__ out3, __half* __restrict__ outo)
{
    __shared__ float t[64][65];
    const int bx = blockIdx.x, by = blockIdx.y, z = blockIdx.z;
    const int tid = threadIdx.x;

    if (z < 3) {
        const int dt = bx, h = by;
        const float* src = (z == 0) ? wq : (z == 1) ? wk : wv;
#pragma unroll
        for (int i = 0; i < 16; i++) {
            int idx = tid + i * 256;
            int dr = idx >> 6, e = idx & 63;
            t[dr][e] = src[((size_t)h * DMODEL + dt * 64 + dr) * DHEAD + e];
        }
        __syncthreads();
#pragma unroll
        for (int i = 0; i < 16; i++) {
            int idx = tid + i * 256;
            int e = idx >> 6, dr = idx & 63;
            int n = h * DHEAD + e, d = dt * 64 + dr;
            out3[(size_t)z * DMODEL * KC + (size_t)n * KC + d] = __float2half(t[dr][e]);
        }
    } else {
        const int dt = bx, nt = by;
#pragma unroll
        for (int i = 0; i < 16; i++) {
            int idx = tid + i * 256;
            int dr = idx >> 6, nr = idx & 63;
            t[dr][nr] = wo[(size_t)(dt * 64 + dr) * DMODEL + nt * 64 + nr];
        }
        __syncthreads();
#pragma unroll
        for (int i = 0; i < 16; i++) {
            int idx = tid + i * 256;
            int nr = idx >> 6, dr = idx & 63;
            int n = nt * 64 + nr, d = dt * 64 + dr;
            outo[(size_t)n * KC + d] = __float2half(t[dr][nr]);
        }
    }
}

// ======================= mma.sync GEMM machinery ===========================
#define GBK     64
#define GNITER  (KC / GBK)                   // 16
#define TILE_B  (128 * 72 * 2)               // 18432 bytes per A or B tile
#define BUF_B   (2 * TILE_B)
#define GEMM_SMEM (2 * BUF_B)                // 73728

__device__ __forceinline__ void gemm_mainloop(
    const __half* Ag0, const __half* Bg0,
    uint32_t smb, const char* smc, int tid, float acc[4][4][4])
{
    const int wid = tid >> 5, lid = tid & 31;
    const int wm = wid >> 2, wn = wid & 3;
    const int lrow = lid & 7, quad = lid >> 3;
    const uint32_t aoff = (uint32_t)(((quad & 1) * 8 + lrow) * 144 + (quad >> 1) * 16)
                        + (uint32_t)(wm * 64) * 144;
    const uint32_t boff = (uint32_t)(((quad >> 1) * 8 + lrow) * 144 + (quad & 1) * 16)
                        + (uint32_t)(wn * 32) * 144 + TILE_B;

    {
#pragma unroll
        for (int i = 0; i < 4; i++) {
            int idx = tid + i * 256;
            int r = idx >> 3, ch = idx & 7;
            cp16(smb + r * 144 + ch * 16,          Ag0 + (size_t)r * KC + ch * 8);
            cp16(smb + TILE_B + r * 144 + ch * 16, Bg0 + (size_t)r * KC + ch * 8);
        }
        CP_COMMIT();
    }

    int buf = 0;
    for (int it = 0; it < GNITER; it++) {
        if (it + 1 < GNITER) {
            const __half* Ag = Ag0 + (it + 1) * GBK;
            const __half* Bg = Bg0 + (it + 1) * GBK;
            const uint32_t nb = smb + (buf ^ 1) * BUF_B;
#pragma unroll
            for (int i = 0; i < 4; i++) {
                int idx = tid + i * 256;
                int r = idx >> 3, ch = idx & 7;
                cp16(nb + r * 144 + ch * 16,          Ag + (size_t)r * KC + ch * 8);
                cp16(nb + TILE_B + r * 144 + ch * 16, Bg + (size_t)r * KC + ch * 8);
            }
            CP_COMMIT();
            CP_WAIT1();
        } else {
            CP_WAIT0();
        }
        __syncthreads();

        const uint32_t bb = smb + buf * BUF_B;
#pragma unroll
        for (int ks = 0; ks < 4; ks++) {
            uint32_t a[4][4], bq[2][4];
#pragma unroll
            for (int mt = 0; mt < 4; mt++)
                ldsm4(a[mt], bb + aoff + (uint32_t)(mt * 16) * 144 + ks * 32);
#pragma unroll
            for (int p = 0; p < 2; p++)
                ldsm4(bq[p], bb + boff + (uint32_t)(p * 16) * 144 + ks * 32);
#pragma unroll
            for (int mt = 0; mt < 4; mt++)
#pragma unroll
                for (int p = 0; p < 2; p++) {
                    mma16816(acc[mt][2 * p],     a[mt], &bq[p][0]);
                    mma16816(acc[mt][2 * p + 1], a[mt], &bq[p][2]);
                }
        }
        __syncthreads();
        buf ^= 1;
    }
}

// Projection GEMM: grid.z selects q/k/v; packed [hb][row][64 fp16] output.
__global__ void __launch_bounds__(256, 2) gemm_proj(
    const __half* __restrict__ A3, const __half* __restrict__ B3,
    __half* __restrict__ Cp3)
{
    extern __shared__ char smc[];
    const uint32_t smb = smem_u32(smc);
    const int tid = threadIdx.x;
    const int wid = tid >> 5, lid = tid & 31;
    const int wm = wid >> 2, wn = wid & 3;
    const int g = lid >> 2, tg = lid & 3;
    const int m0 = blockIdx.y * 128, n0 = blockIdx.x * 128;
    const int z = blockIdx.z;

    const __half* Ag0 = A3 + (size_t)z * MROWS * KC + (size_t)m0 * KC;
    const __half* Bg0 = B3 + (size_t)z * DMODEL * KC + (size_t)n0 * KC;
    __half* Cp = Cp3 + (size_t)z * PACKN;

    float acc[4][4][4];
#pragma unroll
    for (int mt = 0; mt < 4; mt++)
#pragma unroll
        for (int nt = 0; nt < 4; nt++)
#pragma unroll
            for (int r = 0; r < 4; r++) acc[mt][nt][r] = 0.f;

    gemm_mainloop(Ag0, Bg0, smb, smc, tid, acc);

#pragma unroll
    for (int mt = 0; mt < 4; mt++) {
        int m = m0 + wm * 64 + mt * 16 + g;
#pragma unroll
        for (int nt = 0; nt < 4; nt++) {
            int n = n0 + wn * 32 + nt * 8 + 2 * tg;
            int h = n >> 6, e = n & 63;
#pragma unroll
            for (int half_ = 0; half_ < 2; half_++) {
                int mm = m + half_ * 8;
                int b = mm >> 11, qq = mm & 2047;
                int hb = (h << 1) + b;
                uint32_t hv = pack1(acc[mt][nt][2 * half_], acc[mt][nt][2 * half_ + 1]);
                __half* o = Cp + ((size_t)hb * SEQ + qq) * 64;
                *(uint32_t*)(o + e) = hv;
            }
        }
    }
}

// Output projection GEMM: fp32 C + bias + residual.
__global__ void __launch_bounds__(256, 2) gemm_out(
    const __half* __restrict__ A, const __half* __restrict__ Bt,
    float* __restrict__ Cf, const float* __restrict__ bias,
    const float* __restrict__ residual)
{
    extern __shared__ char smc[];
    const uint32_t smb = smem_u32(smc);
    const int tid = threadIdx.x;
    const int wid = tid >> 5, lid = tid & 31;
    const int wm = wid >> 2, wn = wid & 3;
    const int g = lid >> 2, tg = lid & 3;
    const int m0 = blockIdx.y * 128, n0 = blockIdx.x * 128;

    const __half* Ag0 = A  + (size_t)m0 * KC;
    const __half* Bg0 = Bt + (size_t)n0 * KC;

    float acc[4][4][4];
#pragma unroll
    for (int mt = 0; mt < 4; mt++)
#pragma unroll
        for (int nt = 0; nt < 4; nt++)
#pragma unroll
            for (int r = 0; r < 4; r++) acc[mt][nt][r] = 0.f;

    gemm_mainloop(Ag0, Bg0, smb, smc, tid, acc);

#pragma unroll
    for (int mt = 0; mt < 4; mt++) {
        int m = m0 + wm * 64 + mt * 16 + g;
#pragma unroll
        for (int nt = 0; nt < 4; nt++) {
            int n = n0 + wn * 32 + nt * 8 + 2 * tg;
            float2 v0 = make_float2(acc[mt][nt][0], acc[mt][nt][1]);
            float2 v1 = make_float2(acc[mt][nt][2], acc[mt][nt][3]);
            float2 bv = *(const float2*)(bias + n);
            float2 r0 = *(const float2*)(residual + (size_t)m * DMODEL + n);
            float2 r1 = *(const float2*)(residual + (size_t)(m + 8) * DMODEL + n);
            v0.x += bv.x + r0.x; v0.y += bv.y + r0.y;
            v1.x += bv.x + r1.x; v1.y += bv.y + r1.y;
            *(float2*)(Cf + (size_t)m * DMODEL + n)       = v0;
            *(float2*)(Cf + (size_t)(m + 8) * DMODEL + n) = v1;
        }
    }
}

// ======================= flash attention via mma.sync (fp16) ===============
// 128-key pipeline stages, 2 CTAs/SM, bit-packed mask (uint32 = 32 keys).
#define AQ_OFF  0
#define AQ_TB   18432                 // 128 rows x 144B
#define KV_TB2  18432                 // 128 rows x 144B per stage
#define AK_OFF  AQ_TB
#define AV_OFF  (AQ_TB + 2*KV_TB2)
#define ATT_SMEM (AQ_TB + 4*KV_TB2)   // 92160
#define NSTAGE  (SEQ / 128)           // 16
#define MWPR    (SEQ / 32)            // 64 mask words per q row

__global__ void __launch_bounds__(256, 2) attn_mma(
    const __half* __restrict__ Qc, const __half* __restrict__ Kc,
    const __half* __restrict__ Vc, const uint32_t* __restrict__ maskb,
    __half* __restrict__ acat)
{
    extern __shared__ char smc[];
    const uint32_t smb = smem_u32(smc);
    const int tid = threadIdx.x;
    const int wid = tid >> 5, lid = tid & 31;
    const int g = lid >> 2, tg = lid & 3;
    const int qb = blockIdx.x, hb = blockIdx.y;
    const int h = hb >> 1, b = hb & 1;
    const int q0 = qb * 128;
    const int qrow = wid * 16;

    const int lrow = lid & 7, quad = lid >> 3;
    const uint32_t aoff = (uint32_t)(((quad & 1) * 8 + lrow) * 144 + (quad >> 1) * 16)
                        + (uint32_t)qrow * 144;
    const uint32_t boff = (uint32_t)(((quad >> 1) * 8 + lrow) * 144 + (quad & 1) * 16);
    const uint32_t voff = (uint32_t)(((quad & 1) * 8 + lrow) * 144 + (quad >> 1) * 16);

    // bit-packed mask base for this thread's two q rows
    const uint32_t* mb0 = maskb + ((size_t)b * SEQ + q0 + qrow + g) * MWPR;
    const uint32_t* mb1 = mb0 + 8 * MWPR;

    // ---- load Q tile (persistent) + first K/V stage (128 keys)
    {
        const __half* Qg = Qc + ((size_t)hb * SEQ + q0) * 64;
#pragma unroll
        for (int i = 0; i < 4; i++) {
            int idx = tid + i * 256;
            int r = idx >> 3, ch = idx & 7;
            cp16(smb + AQ_OFF + r * 144 + ch * 16, Qg + (size_t)r * 64 + ch * 8);
        }
        const __half* Kg = Kc + ((size_t)hb * SEQ) * 64;
        const __half* Vg = Vc + ((size_t)hb * SEQ) * 64;
#pragma unroll
        for (int i = 0; i < 4; i++) {
            int idx = tid + i * 256;
            int r = idx >> 3, ch = idx & 7;
            cp16(smb + AK_OFF + r * 144 + ch * 16, Kg + (size_t)r * 64 + ch * 8);
            cp16(smb + AV_OFF + r * 144 + ch * 16, Vg + (size_t)r * 64 + ch * 8);
        }
        CP_COMMIT();
    }

    float o_acc[8][4];
#pragma unroll
    for (int nt = 0; nt < 8; nt++)
#pragma unroll
        for (int r = 0; r < 4; r++) o_acc[nt][r] = 0.f;
    float m0 = -1e30f, m1 = -1e30f, l0 = 0.f, l1 = 0.f;

    int buf = 0;

    for (int st = 0; st < NSTAGE; st++) {
        if (st + 1 < NSTAGE) {
            const __half* Kg = Kc + ((size_t)hb * SEQ + (st + 1) * 128) * 64;
            const __half* Vg = Vc + ((size_t)hb * SEQ + (st + 1) * 128) * 64;
            const uint32_t kb_ = smb + AK_OFF + (buf ^ 1) * KV_TB2;
            const uint32_t vb_ = smb + AV_OFF + (buf ^ 1) * KV_TB2;
#pragma unroll
            for (int i = 0; i < 4; i++) {
                int idx = tid + i * 256;
                int r = idx >> 3, ch = idx & 7;
                cp16(kb_ + r * 144 + ch * 16, Kg + (size_t)r * 64 + ch * 8);
                cp16(vb_ + r * 144 + ch * 16, Vg + (size_t)r * 64 + ch * 8);
            }
            CP_COMMIT();
            CP_WAIT1();
        } else {
            CP_WAIT0();
        }
        __syncthreads();

        const uint32_t Qb = smb + AQ_OFF;

#pragma unroll
        for (int sub = 0; sub < 2; sub++) {
            const uint32_t Kb = smb + AK_OFF + buf * KV_TB2 + (uint32_t)(sub * 64) * 144;
            const uint32_t Vb = smb + AV_OFF + buf * KV_TB2 + (uint32_t)(sub * 64) * 144;
            const int kt = st * 2 + sub;

            // mask words for the 64 keys of this sub-pass (2 words per row)
            const uint2 mw0 = *(const uint2*)(mb0 + kt * 2);
            const uint2 mw1 = *(const uint2*)(mb1 + kt * 2);

            // ---- S = Q K^T (single-term fp16)
            float s[8][4];
#pragma unroll
            for (int nt = 0; nt < 8; nt++)
#pragma unroll
                for (int r = 0; r < 4; r++) s[nt][r] = 0.f;

#pragma unroll
            for (int kb = 0; kb < 4; kb++) {
                uint32_t bq[4][4];
#pragma unroll
                for (int p = 0; p < 4; p++)
                    ldsm4(bq[p], Kb + boff + (uint32_t)(p * 16) * 144 + kb * 32);
                uint32_t a[4];
                ldsm4(a, Qb + aoff + kb * 32);
#pragma unroll
                for (int p = 0; p < 4; p++) {
                    mma16816(s[2 * p],     a, &bq[p][0]);
                    mma16816(s[2 * p + 1], a, &bq[p][2]);
                }
            }

            // ---- scale + mask (bit tests; nt compile-time so selects fold)
#pragma unroll
            for (int nt = 0; nt < 8; nt++) {
                const uint32_t w0 = (nt < 4) ? mw0.x : mw0.y;
                const uint32_t w1 = (nt < 4) ? mw1.x : mw1.y;
                const int bi = (nt & 3) * 8 + 2 * tg;
                s[nt][0] = ((w0 >> bi) & 1u)       ? -1e30f : s[nt][0] * 0.125f;
                s[nt][1] = ((w0 >> (bi + 1)) & 1u) ? -1e30f : s[nt][1] * 0.125f;
                s[nt][2] = ((w1 >> bi) & 1u)       ? -1e30f : s[nt][2] * 0.125f;
                s[nt][3] = ((w1 >> (bi + 1)) & 1u) ? -1e30f : s[nt][3] * 0.125f;
            }

            // ---- online softmax
            float mt0 = -1e30f, mt1 = -1e30f;
#pragma unroll
            for (int nt = 0; nt < 8; nt++) {
                mt0 = fmaxf(mt0, fmaxf(s[nt][0], s[nt][1]));
                mt1 = fmaxf(mt1, fmaxf(s[nt][2], s[nt][3]));
            }
            mt0 = fmaxf(mt0, __shfl_xor_sync(0xffffffffu, mt0, 1));
            mt0 = fmaxf(mt0, __shfl_xor_sync(0xffffffffu, mt0, 2));
            mt1 = fmaxf(mt1, __shfl_xor_sync(0xffffffffu, mt1, 1));
            mt1 = fmaxf(mt1, __shfl_xor_sync(0xffffffffu, mt1, 2));
            const float mn0 = fmaxf(m0, mt0), mn1 = fmaxf(m1, mt1);
            const float f0 = __expf(m0 - mn0), f1 = __expf(m1 - mn1);

            float ls0 = 0.f, ls1 = 0.f;
#pragma unroll
            for (int nt = 0; nt < 8; nt++) {
                s[nt][0] = __expf(s[nt][0] - mn0);
                s[nt][1] = __expf(s[nt][1] - mn0);
                s[nt][2] = __expf(s[nt][2] - mn1);
                s[nt][3] = __expf(s[nt][3] - mn1);
                ls0 += s[nt][0] + s[nt][1];
                ls1 += s[nt][2] + s[nt][3];
            }
            ls0 += __shfl_xor_sync(0xffffffffu, ls0, 1);
            ls0 += __shfl_xor_sync(0xffffffffu, ls0, 2);
            ls1 += __shfl_xor_sync(0xffffffffu, ls1, 1);
            ls1 += __shfl_xor_sync(0xffffffffu, ls1, 2);
            l0 = l0 * f0 + ls0; l1 = l1 * f1 + ls1;
            m0 = mn0; m1 = mn1;

#pragma unroll
            for (int nt = 0; nt < 8; nt++) {
                o_acc[nt][0] *= f0; o_acc[nt][1] *= f0;
                o_acc[nt][2] *= f1; o_acc[nt][3] *= f1;
            }

            // ---- P fragments (single fp16, A-frag layout)
            uint32_t pf[4][4];
#pragma unroll
            for (int ks = 0; ks < 4; ks++) {
                pf[ks][0] = pack1(s[2*ks][0],   s[2*ks][1]);
                pf[ks][1] = pack1(s[2*ks][2],   s[2*ks][3]);
                pf[ks][2] = pack1(s[2*ks+1][0], s[2*ks+1][1]);
                pf[ks][3] = pack1(s[2*ks+1][2], s[2*ks+1][3]);
            }

            // ---- O += P V (single-term fp16) via trans-ldmatrix
#pragma unroll
            for (int kb = 0; kb < 4; kb++) {
                const uint32_t krow = Vb + voff + (uint32_t)(kb * 16) * 144;
                uint32_t bt[4][4];
#pragma unroll
                for (int nt = 0; nt < 4; nt++)
                    ldsm4t(bt[nt], krow + nt * 32);
#pragma unroll
                for (int nt = 0; nt < 4; nt++) {
                    mma16816(o_acc[2 * nt],     pf[kb], &bt[nt][0]);
                    mma16816(o_acc[2 * nt + 1], pf[kb], &bt[nt][2]);
                }
            }
        }
        __syncthreads();
        buf ^= 1;
    }

    // ---- epilogue: normalize, single fp16, write acat [row][1024]
    const float inv0 = 1.f / l0, inv1 = 1.f / l1;
    const int row0 = b * SEQ + q0 + qrow + g;
    const int row1 = row0 + 8;
    __half* p0 = acat + (size_t)row0 * KC;
    __half* p1 = acat + (size_t)row1 * KC;
#pragma unroll
    for (int nt = 0; nt < 8; nt++) {
        const int d = h * 64 + nt * 8 + 2 * tg;
        *(uint32_t*)(p0 + d) = pack1(o_acc[nt][0] * inv0, o_acc[nt][1] * inv0);
        *(uint32_t*)(p1 + d) = pack1(o_acc[nt][2] * inv1, o_acc[nt][3] * inv1);
    }
}

// ======================= LayerNorm (torch semantics, float4) ===============
__global__ void __launch_bounds__(256) ln_kernel(
    const float* __restrict__ y, const float* __restrict__ gamma,
    const float* __restrict__ beta, float* __restrict__ out)
{
    __shared__ float sh_s[8], sh_ss[8];
    const int row = blockIdx.x;
    const float4* x4 = (const float4*)(y + (size_t)row * DMODEL);
    const float4 xv = x4[threadIdx.x];

    float s  = xv.x + xv.y + xv.z + xv.w;
    float ss = xv.x * xv.x + xv.y * xv.y + xv.z * xv.z + xv.w * xv.w;
#pragma unroll
    for (int o = 16; o > 0; o >>= 1) {
        s  += __shfl_xor_sync(0xffffffffu, s,  o);
        ss += __shfl_xor_sync(0xffffffffu, ss, o);
    }
    int warp = threadIdx.x >> 5, lane = threadIdx.x & 31;
    if (lane == 0) { sh_s[warp] = s; sh_ss[warp] = ss; }
    __syncthreads();
    if (threadIdx.x < 32) {
        s  = (lane < 8) ? sh_s[lane]  : 0.f;
        ss = (lane < 8) ? sh_ss[lane] : 0.f;
#pragma unroll
        for (int o = 4; o > 0; o >>= 1) {
            s  += __shfl_xor_sync(0xffffffffu, s,  o);
            ss += __shfl_xor_sync(0xffffffffu, ss, o);
        }
        if (lane == 0) { sh_s[0] = s; sh_ss[0] = ss; }
    }
    __syncthreads();
    float mean = sh_s[0] * (1.f / DMODEL);
    float var  = (sh_ss[0] - (float)DMODEL * mean * mean) * (1.f / (DMODEL - 1));
    var = fmaxf(var, 0.f);
    float inv = 1.f / (sqrtf(var) + 1e-3f);

    const float4 gv = ((const float4*)gamma)[threadIdx.x];
    const float4 bv = ((const float4*)beta)[threadIdx.x];
    float4 ov;
    ov.x = (xv.x - mean) * inv * gv.x + bv.x;
    ov.y = (xv.y - mean) * inv * gv.y + bv.y;
    ov.z = (xv.z - mean) * inv * gv.z + bv.z;
    ov.w = (xv.w - mean) * inv * gv.w + bv.w;
    ((float4*)(out + (size_t)row * DMODEL))[threadIdx.x] = ov;
}

// ===========================================================================
extern "C" void kernel_launch(void* const* d_in, const int* in_sizes, int n_in,
                              void* d_out, int out_size)
{
    const float* v     = (const float*)d_in[0];
    const float* k     = (const float*)d_in[1];
    const float* q     = (const float*)d_in[2];
    const void*  mask  = (const void*)d_in[3];
    const float* w_q   = (const float*)d_in[4];
    const float* w_k   = (const float*)d_in[5];
    const float* w_v   = (const float*)d_in[6];
    const float* w_o   = (const float*)d_in[7];
    const float* b_o   = (const float*)d_in[8];
    const float* gamma = (const float*)d_in[9];
    const float* beta  = (const float*)d_in[10];
    float*       out   = (float*)d_out;

    float* y;
    uint32_t* maskb;
    __half *acat3, *wcat3, *wcat, *acat, *qkvc;
    cudaGetSymbolAddress((void**)&y,     g_y);
    cudaGetSymbolAddress((void**)&maskb, g_maskb);
    cudaGetSymbolAddress((void**)&acat3, g_acat3);
    cudaGetSymbolAddress((void**)&wcat3, g_wcat3);
    cudaGetSymbolAddress((void**)&wcat,  g_wcat);
    cudaGetSymbolAddress((void**)&acat,  g_acat);
    cudaGetSymbolAddress((void**)&qkvc,  g_qkvc);

    cudaFuncSetAttribute(gemm_proj, cudaFuncAttributeMaxDynamicSharedMemorySize, GEMM_SMEM);
    cudaFuncSetAttribute(gemm_out,  cudaFuncAttributeMaxDynamicSharedMemorySize, GEMM_SMEM);
    cudaFuncSetAttribute(attn_mma,  cudaFuncAttributeMaxDynamicSharedMemorySize, ATT_SMEM);

    __half* qc = qkvc;
    __half* kc = qkvc + PACKN;
    __half* vc = qkvc + 2 * PACKN;

    // Mask -> bit-packed
    probe_mask<<<1, 1024>>>((const unsigned int*)mask);
    pack_mask<<<(int)((MASKW + 255) / 256), 256>>>(mask);

    // Conversions
    split_act3<<<(int)((3 * (ACTN / 4) + 255) / 256), 256>>>(q, k, v, acat3);
    dim3 wgrid(DMODEL / 64, 16, 4);
    split_w_all<<<wgrid, 256>>>(w_q, w_k, w_v, w_o, wcat3, wcat);

    // All three projections (1-term fp16) -> packed qc/kc/vc
    dim3 pgrid(DMODEL / 128, MROWS / 128, 3);    // (8, 32, 3)
    gemm_proj<<<pgrid, 256, GEMM_SMEM>>>(acat3, wcat3, qkvc);

    // Flash attention (single-term fp16 S and PV, bit-packed mask)
    dim3 agrid(SEQ / 128, NHEAD * BATCH);
    attn_mma<<<agrid, 256, ATT_SMEM>>>(qc, kc, vc, maskb, acat);

    // Output projection (1-term fp16) + bias + residual(k)
    dim3 ggrid(DMODEL / 128, MROWS / 128);
    gemm_out<<<ggrid, 256, GEMM_SMEM>>>(acat, wcat, y, b_o, k);

    // LayerNorm
    ln_kernel<<<MROWS, 256>>>(y, gamma, beta, out);
}